// round 11
// baseline (speedup 1.0000x reference)
#include <cuda_runtime.h>
#include <math.h>

#define Nn 50000
#define Ee 400000
#define Hh 128
#define Gg 512
#define COUT 10

typedef unsigned long long u64;

static constexpr float EPSBN = 1e-5f;
static constexpr float BNB   = 1e-4f;

// ---------------- scratch (static device allocations) ----------------
__device__ float g_h[Nn*Hh];
__device__ float g_t[Nn*Hh];
__device__ float g_t2b[Nn*Hh];
__device__ float g_stats[512];      // zero-init; last-block finalize re-zeroes
__device__ float g_mean[512];
__device__ float g_rstd[512];
__device__ float g_disU[Nn];
__device__ float g_degP[2*Nn];      // attention degree, plane per channel
__device__ float g_epro[Nn*4];
__device__ float g_t2[Nn*2];
__device__ float g_natt[Nn*2];
__device__ float g_eperm[2*Ee];     // eatt planes (CSR-permuted)
__device__ float g_bias2[256];
__device__ float g_cat[Gg*256];
__device__ float g_hd[3*Gg*128];
__device__ int   g_ctrA, g_ctrB, g_ctrC, g_ctrD;   // zero-init counters
// CSR by destination
__device__ int g_cnt[Nn];
__device__ int g_incl[Nn];
__device__ int g_bsum[64];
__device__ int g_rowptr[Nn+1];
__device__ int g_cursor[Nn];
__device__ int g_csrc[Ee];
__device__ int g_pos[Ee];

// ---------------- small utility kernels ----------------
__global__ void init_kernel(float* disU, float* degP, int* cnt, int n) {
    int i = blockIdx.x*blockDim.x + threadIdx.x;
    if (i < n) { disU[i] = 1.f; degP[i] = 1.f; degP[Nn + i] = 1.f; cnt[i] = 0; }
}

__global__ void deg_hist(const int* __restrict__ src, const int* __restrict__ dst,
                         float* degU, int* cnt, int E) {
    int i = blockIdx.x*blockDim.x + threadIdx.x;
    if (i < E) {
        atomicAdd(&degU[src[i]], 1.0f);
        atomicAdd(&cnt[dst[i]], 1);
    }
}

__global__ void rsqrt_arr(float* p, int n) {
    int i = blockIdx.x*blockDim.x + threadIdx.x;
    if (i < n) p[i] = rsqrtf(p[i]);
}

// ---------------- CSR build ----------------
__global__ void scan_block(const int* __restrict__ cnt, int* incl, int* bsum, int n) {
    __shared__ int sm[1024];
    int i = blockIdx.x*1024 + threadIdx.x;
    sm[threadIdx.x] = (i < n) ? cnt[i] : 0;
    __syncthreads();
    for (int off = 1; off < 1024; off <<= 1) {
        int t = (threadIdx.x >= off) ? sm[threadIdx.x - off] : 0;
        __syncthreads();
        sm[threadIdx.x] += t;
        __syncthreads();
    }
    if (i < n) incl[i] = sm[threadIdx.x];
    if (threadIdx.x == 1023) bsum[blockIdx.x] = sm[1023];
}

__global__ void scan_tops(int* bsum, int nb) {
    int lane = threadIdx.x;
    int v0 = (lane < nb) ? bsum[lane] : 0;
    int v1 = (32 + lane < nb) ? bsum[32 + lane] : 0;
    #pragma unroll
    for (int o = 1; o < 32; o <<= 1) {
        int t = __shfl_up_sync(0xffffffffu, v0, o);
        if (lane >= o) v0 += t;
    }
    int tot0 = __shfl_sync(0xffffffffu, v0, 31);
    #pragma unroll
    for (int o = 1; o < 32; o <<= 1) {
        int t = __shfl_up_sync(0xffffffffu, v1, o);
        if (lane >= o) v1 += t;
    }
    v1 += tot0;
    if (lane < nb) bsum[lane] = v0;
    if (32 + lane < nb) bsum[32 + lane] = v1;
}

__global__ void make_rowptr(const int* __restrict__ cnt, const int* __restrict__ incl,
                            const int* __restrict__ bsum,
                            int* rowptr, int* cursor, float* disU, int n, int E) {
    int i = blockIdx.x*blockDim.x + threadIdx.x;
    if (i < n) {
        int b = i >> 10;
        int ex = incl[i] - cnt[i] + ((b > 0) ? bsum[b-1] : 0);
        rowptr[i] = ex;
        cursor[i] = ex;
        disU[i] = rsqrtf(disU[i]);
    }
    if (i == 0) rowptr[n] = E;
}

__global__ void fill_csr(const int* __restrict__ src, const int* __restrict__ dst,
                         int* cursor, int* csrc, int* pos, int E) {
    int e = blockIdx.x*blockDim.x + threadIdx.x;
    if (e < E) {
        int p = atomicAdd(&cursor[dst[e]], 1);
        csrc[p] = src[e];
        pos[e] = p;
    }
}

// ---------------- shared last-block finalize helper ----------------
// call with all block threads; returns true in the last block (after syncthreads)
__device__ __forceinline__ bool last_block(int* ctr, int nblocks, int* sflag) {
    __syncthreads();
    if (threadIdx.x == 0) {
        __threadfence();
        int old = atomicAdd(ctr, 1);
        *sflag = (old == nblocks - 1) ? 1 : 0;
        if (*sflag) *ctr = 0;
    }
    __syncthreads();
    return *sflag != 0;
}

// ---------------- BatchNorm stats (fused last-block finalize) ----------------
__global__ void colstats(const float* __restrict__ A, int n, float* sums,
                         float* mean, float* rstd, float inv_n, int* ctr) {
    __shared__ int sflag;
    long total  = (long)n * 128;
    long stride = (long)gridDim.x * blockDim.x;
    long i0     = (long)blockIdx.x*blockDim.x + threadIdx.x;
    int c = (int)(i0 % 128);
    float s0 = 0.f, s1 = 0.f;
    for (long i = i0; i < total; i += stride) {
        int r = (int)(i / 128);
        float v = A[(long)r*128 + c];
        s0 += v; s1 += v*v;
    }
    atomicAdd(&sums[c], s0);
    atomicAdd(&sums[128+c], s1);
    if (last_block(ctr, gridDim.x, &sflag)) {
        int t = threadIdx.x;
        if (t < 128) {
            float a0 = sums[t], a1 = sums[128+t];
            sums[t] = 0.f; sums[128+t] = 0.f;
            float m = a0*inv_n;
            float var = a1*inv_n - m*m;
            mean[t] = m;
            rstd[t] = rsqrtf(var + EPSBN);
        }
    }
}

// natt-scaled two-channel stats; last block finalizes both + computes bias2
__global__ void colstats2(const float* __restrict__ A, const float* __restrict__ natt,
                          int n, float* sums, float* mean, float* rstd, float inv_n,
                          const float* __restrict__ xcW, const float* __restrict__ xoW,
                          float* __restrict__ bias2, int* ctr) {
    __shared__ int sflag;
    __shared__ float coef[256];
    long total  = (long)n * 128;
    long stride = (long)gridDim.x * blockDim.x;
    long i0     = (long)blockIdx.x*blockDim.x + threadIdx.x;
    int c = (int)(i0 % 128);
    float s00=0.f, s01=0.f, s10=0.f, s11=0.f;
    for (long i = i0; i < total; i += stride) {
        int r = (int)(i / 128);
        float v = A[(long)r*128 + c];
        float v0 = v * natt[r*2+0];
        float v1 = v * natt[r*2+1];
        s00 += v0; s01 += v0*v0;
        s10 += v1; s11 += v1*v1;
    }
    atomicAdd(&sums[c], s00);
    atomicAdd(&sums[128+c], s01);
    atomicAdd(&sums[256+c], s10);
    atomicAdd(&sums[384+c], s11);
    if (last_block(ctr, gridDim.x, &sflag)) {
        int t = threadIdx.x;           // 0..255
        int ch = t >> 7, cc = t & 127;
        float a0 = sums[ch*256 + cc], a1 = sums[ch*256 + 128 + cc];
        sums[ch*256 + cc] = 0.f; sums[ch*256 + 128 + cc] = 0.f;
        float m = a0*inv_n;
        float var = a1*inv_n - m*m;
        float rs = rsqrtf(var + EPSBN);
        mean[t] = m;
        rstd[t] = rs;
        coef[t] = BNB - m*rs;
        __syncthreads();
        const float* W = ch ? xoW : xcW;
        float acc = 0.f;
        for (int k = 0; k < 128; k++) acc += coef[ch*128 + k] * W[k*128 + cc];
        bias2[t] = acc;
    }
}

__global__ void head_stats(const float* __restrict__ A, int lda, int n,
                           float* mean, float* rstd) {
    __shared__ float s0s[4], s1s[4];
    int c = blockIdx.x;
    int lane = threadIdx.x & 31, warp = threadIdx.x >> 5;
    float s0 = 0.f, s1 = 0.f;
    for (int r = threadIdx.x; r < n; r += blockDim.x) {
        float v = A[r*lda + c];
        s0 += v; s1 += v*v;
    }
    #pragma unroll
    for (int o = 16; o; o >>= 1) {
        s0 += __shfl_xor_sync(0xffffffffu, s0, o);
        s1 += __shfl_xor_sync(0xffffffffu, s1, o);
    }
    if (lane == 0) { s0s[warp] = s0; s1s[warp] = s1; }
    __syncthreads();
    if (threadIdx.x == 0) {
        float t0 = 0.f, t1 = 0.f;
        for (int w = 0; w < 4; w++) { t0 += s0s[w]; t1 += s1s[w]; }
        float m = t0 / n;
        float var = t1 / n - m*m;
        mean[c] = m;
        rstd[c] = rsqrtf(var + EPSBN);
    }
}

__global__ void head_stats3(const float* __restrict__ hd, int n,
                            float* mean, float* rstd) {
    __shared__ float s0s[4], s1s[4];
    int cg = blockIdx.x;
    int head = cg >> 7, c = cg & 127;
    const float* A = hd + head*Gg*128;
    int lane = threadIdx.x & 31, warp = threadIdx.x >> 5;
    float s0 = 0.f, s1 = 0.f;
    for (int r = threadIdx.x; r < n; r += blockDim.x) {
        float v = A[r*128 + c];
        s0 += v; s1 += v*v;
    }
    #pragma unroll
    for (int o = 16; o; o >>= 1) {
        s0 += __shfl_xor_sync(0xffffffffu, s0, o);
        s1 += __shfl_xor_sync(0xffffffffu, s1, o);
    }
    if (lane == 0) { s0s[warp] = s0; s1s[warp] = s1; }
    __syncthreads();
    if (threadIdx.x == 0) {
        float t0 = 0.f, t1 = 0.f;
        for (int w = 0; w < 4; w++) { t0 += s0s[w]; t1 += s1s[w]; }
        float m = t0 / n;
        float var = t1 / n - m*m;
        mean[cg] = m;
        rstd[cg] = rsqrtf(var + EPSBN);
    }
}

// ---------------- big GEMM (packed f32x2 FMA, BM=64) ----------------
static constexpr int GEMM_SMEM = (64*128 + 128*128) * 4;

__global__ __launch_bounds__(256) void gemm128(
    const float* __restrict__ A,
    const float* __restrict__ mean, const float* __restrict__ rstd,
    const float* __restrict__ W,
    float* __restrict__ out,
    float* __restrict__ sums,
    float* __restrict__ fmean, float* __restrict__ frstd, float inv_n, int* ctr,
    int n, int act)
{
    extern __shared__ float sm[];
    float* As = sm;               // [64][128]
    float* Ws = sm + 64*128;      // [128][128]
    __shared__ int sflag;
    int tid  = threadIdx.x;
    int row0 = blockIdx.x * 64;

    const float4* Wg = (const float4*)W;
    float4* Ws4 = (float4*)Ws;
    #pragma unroll 4
    for (int i = tid; i < 128*32; i += 256) Ws4[i] = Wg[i];

    #pragma unroll 2
    for (int i = tid; i < 64*32; i += 256) {
        int r = i >> 5, cq = i & 31;
        int gr = row0 + r;
        float4 v = make_float4(0.f,0.f,0.f,0.f);
        if (gr < n) {
            v = ((const float4*)A)[gr*32 + cq];
            int c = cq*4;
            v.x = (v.x - mean[c+0])*rstd[c+0] + BNB;
            v.y = (v.y - mean[c+1])*rstd[c+1] + BNB;
            v.z = (v.z - mean[c+2])*rstd[c+2] + BNB;
            v.w = (v.w - mean[c+3])*rstd[c+3] + BNB;
        }
        ((float4*)As)[i] = v;
    }
    __syncthreads();

    int tc = tid & 15, tr = tid >> 4;
    int r0 = tr*4;
    int c0 = tc*4, c1 = 64 + tc*4;

    u64 accp[4][4];
    #pragma unroll
    for (int i = 0; i < 4; i++)
        #pragma unroll
        for (int j = 0; j < 4; j++) accp[i][j] = 0ull;

    for (int k = 0; k < 128; k += 4) {
        float4 a4[4];
        #pragma unroll
        for (int i = 0; i < 4; i++)
            a4[i] = *(const float4*)&As[(r0+i)*128 + k];
        #pragma unroll
        for (int kk = 0; kk < 4; kk++) {
            ulonglong2 w01 = *(const ulonglong2*)&Ws[(k+kk)*128 + c0];
            ulonglong2 w23 = *(const ulonglong2*)&Ws[(k+kk)*128 + c1];
            u64 wp0 = w01.x, wp1 = w01.y, wp2 = w23.x, wp3 = w23.y;
            #pragma unroll
            for (int i = 0; i < 4; i++) {
                float a = ((const float*)&a4[i])[kk];
                unsigned int ai = __float_as_uint(a);
                u64 ap;
                asm("mov.b64 %0, {%1, %1};" : "=l"(ap) : "r"(ai));
                asm("fma.rn.f32x2 %0, %1, %2, %0;" : "+l"(accp[i][0]) : "l"(ap), "l"(wp0));
                asm("fma.rn.f32x2 %0, %1, %2, %0;" : "+l"(accp[i][1]) : "l"(ap), "l"(wp1));
                asm("fma.rn.f32x2 %0, %1, %2, %0;" : "+l"(accp[i][2]) : "l"(ap), "l"(wp2));
                asm("fma.rn.f32x2 %0, %1, %2, %0;" : "+l"(accp[i][3]) : "l"(ap), "l"(wp3));
            }
        }
    }

    float t0[8], t1[8];
    #pragma unroll
    for (int j = 0; j < 8; j++) { t0[j] = 0.f; t1[j] = 0.f; }

    float4* O4 = (float4*)out;
    #pragma unroll
    for (int i = 0; i < 4; i++) {
        int gr = row0 + r0 + i;
        if (gr < n) {
            float o[8];
            #pragma unroll
            for (int j = 0; j < 4; j++) {
                unsigned int lo, hi;
                asm("mov.b64 {%0, %1}, %2;" : "=r"(lo), "=r"(hi) : "l"(accp[i][j]));
                o[2*j]   = __uint_as_float(lo);
                o[2*j+1] = __uint_as_float(hi);
            }
            if (act == 1) {
                #pragma unroll
                for (int j = 0; j < 8; j++) o[j] = fmaxf(o[j], 0.f);
            }
            if (sums) {
                #pragma unroll
                for (int j = 0; j < 8; j++) { t0[j] += o[j]; t1[j] += o[j]*o[j]; }
            }
            O4[gr*32 + tc]      = make_float4(o[0], o[1], o[2], o[3]);
            O4[gr*32 + 16 + tc] = make_float4(o[4], o[5], o[6], o[7]);
        }
    }

    if (sums) {
        __syncthreads();
        float* ss = sm;
        ss[tid] = 0.f;
        __syncthreads();
        #pragma unroll
        for (int j = 0; j < 4; j++) {
            atomicAdd(&ss[c0+j],     t0[j]);   atomicAdd(&ss[128+c0+j], t1[j]);
            atomicAdd(&ss[c1+j],     t0[4+j]); atomicAdd(&ss[128+c1+j], t1[4+j]);
        }
        __syncthreads();
        atomicAdd(&sums[tid], ss[tid]);
        if (last_block(ctr, gridDim.x, &sflag)) {
            if (tid < 128) {
                float a0 = sums[tid], a1 = sums[128+tid];
                sums[tid] = 0.f; sums[128+tid] = 0.f;
                float m = a0*inv_n;
                float var = a1*inv_n - m*m;
                fmean[tid] = m;
                frstd[tid] = rsqrtf(var + EPSBN);
            }
        }
    }
}

// ---------------- merged XC/XO GEMM ----------------
__global__ __launch_bounds__(256) void gemm256(
    const float* __restrict__ h,
    const float* __restrict__ natt,
    const float* __restrict__ rstd2,
    const float* __restrict__ xcW, const float* __restrict__ xoW,
    const float* __restrict__ bias2,
    float* __restrict__ outc, float* __restrict__ outo, int n)
{
    extern __shared__ float sm[];
    float* As = sm;
    float* Ws = sm + 64*128;
    int tid  = threadIdx.x;
    int row0 = blockIdx.x * 64;

    #pragma unroll 2
    for (int i = tid; i < 64*32; i += 256) {
        int r = i >> 5, cq = i & 31;
        int gr = row0 + r;
        float4 v = (gr < n) ? ((const float4*)h)[gr*32 + cq]
                            : make_float4(0.f,0.f,0.f,0.f);
        ((float4*)As)[i] = v;
    }

    int tc = tid & 15, tr = tid >> 4;
    int r0 = tr*4;
    int c0 = tc*4, c1 = 64 + tc*4;

    #pragma unroll
    for (int half = 0; half < 2; half++) {
        const float* W  = half ? xoW : xcW;
        const float* rs = rstd2 + half*128;
        const float* bs = bias2 + half*128;
        float* out = half ? outo : outc;

        __syncthreads();
        for (int i = tid; i < 128*32; i += 256) {
            int k = i >> 5;
            float4 w = ((const float4*)W)[i];
            float sc = rs[k];
            w.x *= sc; w.y *= sc; w.z *= sc; w.w *= sc;
            ((float4*)Ws)[i] = w;
        }
        __syncthreads();

        float nv[4];
        #pragma unroll
        for (int i = 0; i < 4; i++) {
            int gr = row0 + r0 + i;
            nv[i] = (gr < n) ? natt[gr*2 + half] : 0.f;
        }

        u64 accp[4][4];
        #pragma unroll
        for (int i = 0; i < 4; i++)
            #pragma unroll
            for (int j = 0; j < 4; j++) accp[i][j] = 0ull;

        for (int k = 0; k < 128; k += 4) {
            float4 a4[4];
            #pragma unroll
            for (int i = 0; i < 4; i++)
                a4[i] = *(const float4*)&As[(r0+i)*128 + k];
            #pragma unroll
            for (int kk = 0; kk < 4; kk++) {
                ulonglong2 w01 = *(const ulonglong2*)&Ws[(k+kk)*128 + c0];
                ulonglong2 w23 = *(const ulonglong2*)&Ws[(k+kk)*128 + c1];
                u64 wp0 = w01.x, wp1 = w01.y, wp2 = w23.x, wp3 = w23.y;
                #pragma unroll
                for (int i = 0; i < 4; i++) {
                    float a = ((const float*)&a4[i])[kk] * nv[i];
                    unsigned int ai = __float_as_uint(a);
                    u64 ap;
                    asm("mov.b64 %0, {%1, %1};" : "=l"(ap) : "r"(ai));
                    asm("fma.rn.f32x2 %0, %1, %2, %0;" : "+l"(accp[i][0]) : "l"(ap), "l"(wp0));
                    asm("fma.rn.f32x2 %0, %1, %2, %0;" : "+l"(accp[i][1]) : "l"(ap), "l"(wp1));
                    asm("fma.rn.f32x2 %0, %1, %2, %0;" : "+l"(accp[i][2]) : "l"(ap), "l"(wp2));
                    asm("fma.rn.f32x2 %0, %1, %2, %0;" : "+l"(accp[i][3]) : "l"(ap), "l"(wp3));
                }
            }
        }

        float4 b0 = *(const float4*)&bs[c0];
        float4 b1 = *(const float4*)&bs[c1];
        float4* O4 = (float4*)out;
        #pragma unroll
        for (int i = 0; i < 4; i++) {
            int gr = row0 + r0 + i;
            if (gr < n) {
                float o[8];
                #pragma unroll
                for (int j = 0; j < 4; j++) {
                    unsigned int lo, hi;
                    asm("mov.b64 {%0, %1}, %2;" : "=r"(lo), "=r"(hi) : "l"(accp[i][j]));
                    o[2*j]   = __uint_as_float(lo);
                    o[2*j+1] = __uint_as_float(hi);
                }
                O4[gr*32 + tc]      = make_float4(o[0]+b0.x, o[1]+b0.y, o[2]+b0.z, o[3]+b0.w);
                O4[gr*32 + 16 + tc] = make_float4(o[4]+b1.x, o[5]+b1.y, o[6]+b1.z, o[7]+b1.w);
            }
        }
    }
}

// ---------------- CSR gather conv (MLP-4, optional last-block stats finalize) ----------------
__global__ __launch_bounds__(256) void gather128(
    const float* __restrict__ t,
    const int* __restrict__ rowptr, const int* __restrict__ csrc,
    const float* __restrict__ dis,
    const float* __restrict__ bias,
    float* __restrict__ out, float* __restrict__ sums,
    float* __restrict__ fmean, float* __restrict__ frstd, float inv_n, int* ctr,
    const float* __restrict__ eWg, const float* __restrict__ naWg,
    float* __restrict__ epro, float* __restrict__ t2,
    int n, int act)
{
    __shared__ float sEW[512];
    __shared__ float sNA[256];
    __shared__ int sflag;
    if (eWg) {
        for (int i = threadIdx.x; i < 512; i += 256) sEW[i] = eWg[i];
        for (int i = threadIdx.x; i < 256; i += 256) sNA[i] = naWg[i];
        __syncthreads();
    }
    int lane = threadIdx.x & 31;
    int w0 = (blockIdx.x*blockDim.x + threadIdx.x) >> 5;
    int nw = (gridDim.x*blockDim.x) >> 5;
    float4 bb = bias ? ((const float4*)bias)[lane] : make_float4(0.f,0.f,0.f,0.f);
    float ls0[4] = {0.f,0.f,0.f,0.f}, ls1[4] = {0.f,0.f,0.f,0.f};
    const float4* t4 = (const float4*)t;

    for (int v = w0; v < n; v += nw) {
        float dv = dis[v];
        float4 acc = t4[v*32 + lane];
        float d2 = dv*dv;
        acc.x *= d2; acc.y *= d2; acc.z *= d2; acc.w *= d2;
        int p = rowptr[v], en = rowptr[v+1];
        for (; p + 4 <= en; p += 4) {
            int s0 = __ldg(&csrc[p+0]);
            int s1 = __ldg(&csrc[p+1]);
            int s2 = __ldg(&csrc[p+2]);
            int s3 = __ldg(&csrc[p+3]);
            float w0_ = __ldg(&dis[s0]);
            float w1_ = __ldg(&dis[s1]);
            float w2_ = __ldg(&dis[s2]);
            float w3_ = __ldg(&dis[s3]);
            float4 x0 = t4[s0*32 + lane];
            float4 x1 = t4[s1*32 + lane];
            float4 x2 = t4[s2*32 + lane];
            float4 x3 = t4[s3*32 + lane];
            w0_ *= dv; w1_ *= dv; w2_ *= dv; w3_ *= dv;
            acc.x += w0_*x0.x + w1_*x1.x + w2_*x2.x + w3_*x3.x;
            acc.y += w0_*x0.y + w1_*x1.y + w2_*x2.y + w3_*x3.y;
            acc.z += w0_*x0.z + w1_*x1.z + w2_*x2.z + w3_*x3.z;
            acc.w += w0_*x0.w + w1_*x1.w + w2_*x2.w + w3_*x3.w;
        }
        for (; p < en; p++) {
            int s = __ldg(&csrc[p]);
            float w = __ldg(&dis[s]) * dv;
            float4 x = t4[s*32 + lane];
            acc.x += w*x.x; acc.y += w*x.y; acc.z += w*x.z; acc.w += w*x.w;
        }
        acc.x += bb.x; acc.y += bb.y; acc.z += bb.z; acc.w += bb.w;
        if (act == 1) {
            acc.x = fmaxf(acc.x, 0.f); acc.y = fmaxf(acc.y, 0.f);
            acc.z = fmaxf(acc.z, 0.f); acc.w = fmaxf(acc.w, 0.f);
        }
        if (sums) {
            ls0[0]+=acc.x; ls1[0]+=acc.x*acc.x;
            ls0[1]+=acc.y; ls1[1]+=acc.y*acc.y;
            ls0[2]+=acc.z; ls1[2]+=acc.z*acc.z;
            ls0[3]+=acc.w; ls1[3]+=acc.w*acc.w;
        }
        ((float4*)out)[v*32 + lane] = acc;

        if (eWg) {
            float hx[4] = {acc.x, acc.y, acc.z, acc.w};
            float p0=0,p1=0,q0=0,q1=0,u0=0,u1=0;
            #pragma unroll
            for (int i = 0; i < 4; i++) {
                int k = lane*4 + i; float xv = hx[i];
                p0 += xv*sEW[k*2+0];        p1 += xv*sEW[k*2+1];
                q0 += xv*sEW[(128+k)*2+0];  q1 += xv*sEW[(128+k)*2+1];
                u0 += xv*sNA[k*2+0];        u1 += xv*sNA[k*2+1];
            }
            #pragma unroll
            for (int o = 16; o; o >>= 1) {
                p0 += __shfl_xor_sync(0xffffffffu, p0, o);
                p1 += __shfl_xor_sync(0xffffffffu, p1, o);
                q0 += __shfl_xor_sync(0xffffffffu, q0, o);
                q1 += __shfl_xor_sync(0xffffffffu, q1, o);
                u0 += __shfl_xor_sync(0xffffffffu, u0, o);
                u1 += __shfl_xor_sync(0xffffffffu, u1, o);
            }
            if (lane == 0) {
                epro[v*4+0]=p0; epro[v*4+1]=p1; epro[v*4+2]=q0; epro[v*4+3]=q1;
                t2[v*2+0]=u0; t2[v*2+1]=u1;
            }
        }
    }

    if (sums) {
        __shared__ float ss[256];
        ss[threadIdx.x] = 0.f;
        __syncthreads();
        #pragma unroll
        for (int j = 0; j < 4; j++) {
            atomicAdd(&ss[lane*4+j],     ls0[j]);
            atomicAdd(&ss[128+lane*4+j], ls1[j]);
        }
        __syncthreads();
        atomicAdd(&sums[threadIdx.x], ss[threadIdx.x]);
        if (last_block(ctr, gridDim.x, &sflag)) {
            int tid = threadIdx.x;
            if (tid < 128) {
                float a0 = sums[tid], a1 = sums[128+tid];
                sums[tid] = 0.f; sums[128+tid] = 0.f;
                float m = a0*inv_n;
                float var = a1*inv_n - m*m;
                fmean[tid] = m;
                frstd[tid] = rsqrtf(var + EPSBN);
            }
        }
    }
}

// fused XC+XO gather + conv-bias + ELU + pool; one warp per (node, channel)
__global__ __launch_bounds__(256) void gather2(
    const float* __restrict__ tc_, const float* __restrict__ to_,
    const int* __restrict__ rowptr, const int* __restrict__ csrc,
    const float* __restrict__ degP,
    const float* __restrict__ eperm,
    const float* __restrict__ xcb, const float* __restrict__ xob,
    const int* __restrict__ batch,
    float* __restrict__ cat, int n)
{
    int lane = threadIdx.x & 31;
    int w0 = (blockIdx.x*blockDim.x + threadIdx.x) >> 5;
    int nw = (gridDim.x*blockDim.x) >> 5;

    for (int wi = w0; wi < 2*n; wi += nw) {
        int v  = wi >> 1;
        int ch = wi & 1;
        const float4* t4 = (const float4*)(ch ? to_ : tc_);
        const float*  ds = degP + ch*Nn;
        const float*  ea = eperm + ch*Ee;
        const float4* bptr = (const float4*)(ch ? xob : xcb);
        float4 bb = bptr[lane];

        float dv = ds[v];
        float4 acc = t4[v*32 + lane];
        float d2 = dv*dv;
        acc.x *= d2; acc.y *= d2; acc.z *= d2; acc.w *= d2;
        int p = rowptr[v], en = rowptr[v+1];
        for (; p + 4 <= en; p += 4) {
            int s0 = __ldg(&csrc[p+0]);
            int s1 = __ldg(&csrc[p+1]);
            int s2 = __ldg(&csrc[p+2]);
            int s3 = __ldg(&csrc[p+3]);
            float e0 = __ldg(&ea[p+0]);
            float e1 = __ldg(&ea[p+1]);
            float e2 = __ldg(&ea[p+2]);
            float e3 = __ldg(&ea[p+3]);
            float w0_ = __ldg(&ds[s0]);
            float w1_ = __ldg(&ds[s1]);
            float w2_ = __ldg(&ds[s2]);
            float w3_ = __ldg(&ds[s3]);
            float4 x0 = t4[s0*32 + lane];
            float4 x1 = t4[s1*32 + lane];
            float4 x2 = t4[s2*32 + lane];
            float4 x3 = t4[s3*32 + lane];
            w0_ *= dv*e0; w1_ *= dv*e1; w2_ *= dv*e2; w3_ *= dv*e3;
            acc.x += w0_*x0.x + w1_*x1.x + w2_*x2.x + w3_*x3.x;
            acc.y += w0_*x0.y + w1_*x1.y + w2_*x2.y + w3_*x3.y;
            acc.z += w0_*x0.z + w1_*x1.z + w2_*x2.z + w3_*x3.z;
            acc.w += w0_*x0.w + w1_*x1.w + w2_*x2.w + w3_*x3.w;
        }
        for (; p < en; p++) {
            int s = __ldg(&csrc[p]);
            float w = __ldg(&ds[s]) * dv * __ldg(&ea[p]);
            float4 x = t4[s*32 + lane];
            acc.x += w*x.x; acc.y += w*x.y; acc.z += w*x.z; acc.w += w*x.w;
        }
        float z[4] = {acc.x+bb.x, acc.y+bb.y, acc.z+bb.z, acc.w+bb.w};
        #pragma unroll
        for (int j = 0; j < 4; j++)
            z[j] = (z[j] > 0.f) ? z[j] : expm1f(z[j]);
        int g = __ldg(&batch[v]);
        float* pc = cat + g*256 + ch*128 + lane*4;
        asm volatile("red.global.add.v4.f32 [%0], {%1, %2, %3, %4};"
                     :: "l"(pc), "f"(z[0]), "f"(z[1]), "f"(z[2]), "f"(z[3]) : "memory");
    }
}

// ---------------- attention ----------------
__global__ void edge_att_kernel(const int* __restrict__ src, const int* __restrict__ dst,
                                const int* __restrict__ pos,
                                const float* __restrict__ epro, const float* __restrict__ eb,
                                float* __restrict__ eperm, float* __restrict__ degP, int E) {
    int e = blockIdx.x*blockDim.x + threadIdx.x;
    if (e >= E) return;
    int s = src[e], d = dst[e];
    float2 ps = *(const float2*)&epro[s*4];
    float2 qd = *(const float2*)&epro[d*4+2];
    float l0 = ps.x + qd.x + eb[0];
    float l1 = ps.y + qd.y + eb[1];
    float m = fmaxf(l0, l1);
    float e0 = expf(l0 - m), e1 = expf(l1 - m);
    float inv = 1.f/(e0+e1);
    float a0 = e0*inv, a1 = e1*inv;
    int p = pos[e];
    eperm[p] = a0;
    eperm[Ee + p] = a1;
    atomicAdd(&degP[s], a0);
    atomicAdd(&degP[Nn + s], a1);
}

__global__ void natt_gather(const float* __restrict__ t2,
                            const int* __restrict__ rowptr, const int* __restrict__ csrc,
                            const float* __restrict__ disU,
                            const float* __restrict__ nab,
                            float* __restrict__ natt, int n) {
    int v = blockIdx.x*blockDim.x + threadIdx.x;
    if (v >= n) return;
    float dv = disU[v];
    float d2 = dv*dv;
    float a0 = t2[v*2+0]*d2, a1 = t2[v*2+1]*d2;
    int p = rowptr[v], en = rowptr[v+1];
    for (; p + 4 <= en; p += 4) {
        int s0 = __ldg(&csrc[p+0]);
        int s1 = __ldg(&csrc[p+1]);
        int s2 = __ldg(&csrc[p+2]);
        int s3 = __ldg(&csrc[p+3]);
        float w0 = __ldg(&disU[s0]);
        float w1 = __ldg(&disU[s1]);
        float w2 = __ldg(&disU[s2]);
        float w3 = __ldg(&disU[s3]);
        float2 x0 = __ldg((const float2*)&t2[s0*2]);
        float2 x1 = __ldg((const float2*)&t2[s1*2]);
        float2 x2 = __ldg((const float2*)&t2[s2*2]);
        float2 x3 = __ldg((const float2*)&t2[s3*2]);
        w0 *= dv; w1 *= dv; w2 *= dv; w3 *= dv;
        a0 += w0*x0.x + w1*x1.x + w2*x2.x + w3*x3.x;
        a1 += w0*x0.y + w1*x1.y + w2*x2.y + w3*x3.y;
    }
    for (; p < en; p++) {
        int s = __ldg(&csrc[p]);
        float w = __ldg(&disU[s])*dv;
        float2 ts = __ldg((const float2*)&t2[s*2]);
        a0 += w*ts.x;
        a1 += w*ts.y;
    }
    a0 += nab[0]; a1 += nab[1];
    float m = fmaxf(a0, a1);
    float e0 = expf(a0 - m), e1 = expf(a1 - m);
    float inv = 1.f/(e0+e1);
    natt[v*2+0] = e0*inv; natt[v*2+1] = e1*inv;
}

// ---------------- fused heads ----------------
__global__ void head_gemm1(const float* __restrict__ cat,
                           const float* __restrict__ mean, const float* __restrict__ rstd,
                           const float* __restrict__ cW1, const float* __restrict__ cb1,
                           const float* __restrict__ oW1, const float* __restrict__ ob1,
                           const float* __restrict__ coW1, const float* __restrict__ cob1,
                           float* __restrict__ hd) {
    __shared__ float a[256];
    int r = blockIdx.x, head = blockIdx.y;
    for (int k = threadIdx.x; k < 256; k += 128)
        a[k] = (cat[r*256 + k] - mean[k]) * rstd[k] + BNB;
    __syncthreads();
    const float* W; const float* b; int K, koff, act;
    if (head == 0)      { W = cW1;  b = cb1;  K = 128; koff = 0;   act = 1; }
    else if (head == 1) { W = oW1;  b = ob1;  K = 128; koff = 128; act = 1; }
    else                { W = coW1; b = cob1; K = 256; koff = 0;   act = 2; }
    int c = threadIdx.x;
    float acc = b[c];
    for (int k = 0; k < K; k++) acc += a[koff + k] * W[k*128 + c];
    if (act == 1) acc = fmaxf(acc, 0.f);
    else {
        acc = (acc > 0.f) ? acc : expm1f(acc);
        acc = (acc > 0.f) ? acc : expm1f(acc);
    }
    hd[(head*Gg + r)*128 + c] = acc;
}

__global__ void head_gemm2_lsm(const float* __restrict__ hd,
                               const float* __restrict__ mean, const float* __restrict__ rstd,
                               const float* __restrict__ cW2, const float* __restrict__ cb2,
                               const float* __restrict__ oW2, const float* __restrict__ ob2,
                               const float* __restrict__ coW2, const float* __restrict__ cob2,
                               float* __restrict__ out) {
    __shared__ float a[128];
    __shared__ float lg[COUT];
    int r = blockIdx.x, head = blockIdx.y;
    int k = threadIdx.x;
    a[k] = (hd[(head*Gg + r)*128 + k] - mean[head*128 + k]) * rstd[head*128 + k] + BNB;
    __syncthreads();
    const float* W = (head == 0) ? cW2 : (head == 1) ? oW2 : coW2;
    const float* b = (head == 0) ? cb2 : (head == 1) ? ob2 : cob2;
    if (k < COUT) {
        float acc = b[k];
        for (int kk = 0; kk < 128; kk++) acc += a[kk] * W[kk*COUT + k];
        lg[k] = acc;
    }
    __syncthreads();
    if (k < COUT) {
        float m = -1e30f;
        #pragma unroll
        for (int i = 0; i < COUT; i++) m = fmaxf(m, lg[i]);
        float s = 0.f;
        #pragma unroll
        for (int i = 0; i < COUT; i++) s += expf(lg[i] - m);
        out[head*Gg*COUT + r*COUT + k] = lg[k] - m - logf(s);
    }
}

// ---------------- host orchestration ----------------
extern "C" void kernel_launch(void* const* d_in, const int* in_sizes, int n_in,
                              void* d_out, int out_size) {
    const float* x      = (const float*)d_in[0];
    const float* W_feat = (const float*)d_in[1];
    const float* conv_Ws= (const float*)d_in[2];
    const float* conv_bs= (const float*)d_in[3];
    const float* eW     = (const float*)d_in[4];
    const float* eb     = (const float*)d_in[5];
    const float* naW    = (const float*)d_in[6];
    const float* nab    = (const float*)d_in[7];
    const float* xcW    = (const float*)d_in[8];
    const float* xcb    = (const float*)d_in[9];
    const float* xoW    = (const float*)d_in[10];
    const float* xob    = (const float*)d_in[11];
    const float* cW1    = (const float*)d_in[12];
    const float* cb1    = (const float*)d_in[13];
    const float* cW2    = (const float*)d_in[14];
    const float* cb2    = (const float*)d_in[15];
    const float* oW1    = (const float*)d_in[16];
    const float* ob1    = (const float*)d_in[17];
    const float* oW2    = (const float*)d_in[18];
    const float* ob2    = (const float*)d_in[19];
    const float* coW1   = (const float*)d_in[20];
    const float* cob1   = (const float*)d_in[21];
    const float* coW2   = (const float*)d_in[22];
    const float* cob2   = (const float*)d_in[23];
    const int* esrc     = (const int*)d_in[24];
    const int* edst     = (const int*)d_in[25];
    const int* batch    = (const int*)d_in[26];
    float* out = (float*)d_out;

    float *p_h,*p_t,*p_t2b,*p_stats,*p_mean,*p_rstd,*p_disU,*p_degP;
    float *p_epro,*p_t2,*p_natt,*p_eperm,*p_bias2,*p_cat,*p_hd;
    int *p_cnt,*p_incl,*p_bsum,*p_rowptr,*p_cursor,*p_csrc,*p_pos;
    int *p_ctrA,*p_ctrB,*p_ctrC,*p_ctrD;
    cudaGetSymbolAddress((void**)&p_h, g_h);
    cudaGetSymbolAddress((void**)&p_t, g_t);
    cudaGetSymbolAddress((void**)&p_t2b, g_t2b);
    cudaGetSymbolAddress((void**)&p_stats, g_stats);
    cudaGetSymbolAddress((void**)&p_mean, g_mean);
    cudaGetSymbolAddress((void**)&p_rstd, g_rstd);
    cudaGetSymbolAddress((void**)&p_disU, g_disU);
    cudaGetSymbolAddress((void**)&p_degP, g_degP);
    cudaGetSymbolAddress((void**)&p_epro, g_epro);
    cudaGetSymbolAddress((void**)&p_t2, g_t2);
    cudaGetSymbolAddress((void**)&p_natt, g_natt);
    cudaGetSymbolAddress((void**)&p_eperm, g_eperm);
    cudaGetSymbolAddress((void**)&p_bias2, g_bias2);
    cudaGetSymbolAddress((void**)&p_cat, g_cat);
    cudaGetSymbolAddress((void**)&p_hd, g_hd);
    cudaGetSymbolAddress((void**)&p_cnt, g_cnt);
    cudaGetSymbolAddress((void**)&p_incl, g_incl);
    cudaGetSymbolAddress((void**)&p_bsum, g_bsum);
    cudaGetSymbolAddress((void**)&p_rowptr, g_rowptr);
    cudaGetSymbolAddress((void**)&p_cursor, g_cursor);
    cudaGetSymbolAddress((void**)&p_csrc, g_csrc);
    cudaGetSymbolAddress((void**)&p_pos, g_pos);
    cudaGetSymbolAddress((void**)&p_ctrA, g_ctrA);
    cudaGetSymbolAddress((void**)&p_ctrB, g_ctrB);
    cudaGetSymbolAddress((void**)&p_ctrC, g_ctrC);
    cudaGetSymbolAddress((void**)&p_ctrD, g_ctrD);

    cudaFuncSetAttribute(gemm128, cudaFuncAttributeMaxDynamicSharedMemorySize, GEMM_SMEM);
    cudaFuncSetAttribute(gemm256, cudaFuncAttributeMaxDynamicSharedMemorySize, GEMM_SMEM);

    const int N = Nn, E = Ee, G = Gg;
    const int NB = (N + 63) / 64;
    const int NT = (N + 255) / 256;
    const int ET = (E + 255) / 256;
    const int GB = 1024;
    const int NSCAN = (N + 1023) / 1024;
    const float invN = 1.f/N;

    cudaStream_t sA;
    cudaStreamCreateWithFlags(&sA, cudaStreamNonBlocking);
    cudaEvent_t evF1, evJ1, evF2, evJ2;
    cudaEventCreateWithFlags(&evF1, cudaEventDisableTiming);
    cudaEventCreateWithFlags(&evJ1, cudaEventDisableTiming);
    cudaEventCreateWithFlags(&evF2, cudaEventDisableTiming);
    cudaEventCreateWithFlags(&evJ2, cudaEventDisableTiming);

    // ==== FORK 1: CSR build on sA ====
    cudaEventRecord(evF1, 0);
    cudaStreamWaitEvent(sA, evF1, 0);
    init_kernel<<<NT,256,0,sA>>>(p_disU, p_degP, p_cnt, N);
    deg_hist<<<ET,256,0,sA>>>(esrc, edst, p_disU, p_cnt, E);
    scan_block<<<NSCAN,1024,0,sA>>>(p_cnt, p_incl, p_bsum, N);
    scan_tops<<<1,32,0,sA>>>(p_bsum, NSCAN);
    make_rowptr<<<NT,256,0,sA>>>(p_cnt, p_incl, p_bsum, p_rowptr, p_cursor, p_disU, N, E);
    fill_csr<<<ET,256,0,sA>>>(esrc, edst, p_cursor, p_csrc, p_pos, E);
    cudaEventRecord(evJ1, sA);

    // main chain: stats(x) -> gemm0 (h-stats fused) -> layer-0 gemm
    colstats<<<512,256>>>(x, N, p_stats, p_mean, p_rstd, invN, p_ctrA);
    gemm128<<<NB,256,GEMM_SMEM>>>(x, p_mean, p_rstd, W_feat, p_h, p_stats,
                                  p_mean, p_rstd, invN, p_ctrB, N, 1);
    gemm128<<<NB,256,GEMM_SMEM>>>(p_h, p_mean, p_rstd, conv_Ws, p_t, nullptr,
                                  nullptr, nullptr, 0.f, nullptr, N, 0);

    cudaStreamWaitEvent(0, evJ1, 0);

    // ---- GCN layers ----
    gather128<<<GB,256>>>(p_t, p_rowptr, p_csrc, p_disU, conv_bs, p_h, p_stats,
                          p_mean, p_rstd, invN, p_ctrC,
                          nullptr, nullptr, nullptr, nullptr, N, 1);
    for (int l = 1; l < 3; l++) {
        gemm128<<<NB,256,GEMM_SMEM>>>(p_h, p_mean, p_rstd,
                                      conv_Ws + l*128*128, p_t, nullptr,
                                      nullptr, nullptr, 0.f, nullptr, N, 0);
        if (l < 2) {
            gather128<<<GB,256>>>(p_t, p_rowptr, p_csrc, p_disU,
                                  conv_bs + l*128, p_h, p_stats,
                                  p_mean, p_rstd, invN, p_ctrC,
                                  nullptr, nullptr, nullptr, nullptr, N, 1);
        } else {
            gather128<<<GB,256>>>(p_t, p_rowptr, p_csrc, p_disU,
                                  conv_bs + l*128, p_h, nullptr,
                                  nullptr, nullptr, 0.f, nullptr,
                                  eW, naW, p_epro, p_t2, N, 1);
        }
    }

    // ==== FORK 2: edge attention on sA ====
    cudaEventRecord(evF2, 0);
    cudaStreamWaitEvent(sA, evF2, 0);
    edge_att_kernel<<<ET,256,0,sA>>>(esrc, edst, p_pos, p_epro, eb, p_eperm, p_degP, E);
    rsqrt_arr<<<(2*N+255)/256,256,0,sA>>>(p_degP, 2*N);
    cudaMemsetAsync(p_cat, 0, Gg*256*sizeof(float), sA);
    cudaEventRecord(evJ2, sA);

    // main: node attention + XC/XO stats (finalize + bias fused) + merged GEMM
    natt_gather<<<NT,256>>>(p_t2, p_rowptr, p_csrc, p_disU, nab, p_natt, N);
    colstats2<<<512,256>>>(p_h, p_natt, N, p_stats, p_mean, p_rstd, invN,
                           xcW, xoW, p_bias2, p_ctrD);
    gemm256<<<NB,256,GEMM_SMEM>>>(p_h, p_natt, p_rstd, xcW, xoW, p_bias2,
                                  p_t, p_t2b, N);

    cudaStreamWaitEvent(0, evJ2, 0);
    gather2<<<GB,256>>>(p_t, p_t2b, p_rowptr, p_csrc, p_degP, p_eperm,
                        xcb, xob, batch, p_cat, N);

    // ---- heads ----
    head_stats<<<256,128>>>(p_cat, 256, G, p_mean, p_rstd);
    dim3 hg1(G, 3);
    head_gemm1<<<hg1,128>>>(p_cat, p_mean, p_rstd, cW1, cb1, oW1, ob1,
                            coW1, cob1, p_hd);
    head_stats3<<<384,128>>>(p_hd, G, p_mean, p_rstd);
    dim3 hg2(G, 3);
    head_gemm2_lsm<<<hg2,128>>>(p_hd, p_mean, p_rstd, cW2, cb2, oW2, ob2,
                                coW2, cob2, out);

    cudaEventDestroy(evF1);
    cudaEventDestroy(evJ1);
    cudaEventDestroy(evF2);
    cudaEventDestroy(evJ2);
    cudaStreamDestroy(sA);
}

// round 12
// speedup vs baseline: 1.0179x; 1.0179x over previous
#include <cuda_runtime.h>
#include <math.h>

#define Nn 50000
#define Ee 400000
#define Hh 128
#define Gg 512
#define COUT 10

typedef unsigned long long u64;

static constexpr float EPSBN = 1e-5f;
static constexpr float BNB   = 1e-4f;

// ---------------- scratch (static device allocations) ----------------
__device__ float g_h[Nn*Hh];
__device__ float g_t[Nn*Hh];
__device__ float g_t2b[Nn*Hh];
__device__ float g_stats[512];      // zero-init; every consumer re-zeroes
__device__ float g_mean[512];
__device__ float g_rstd[512];
__device__ float g_disU[Nn];
__device__ float2 g_deg01[Nn];
__device__ float g_epro[Nn*4];
__device__ float g_t2[Nn*2];
__device__ float g_natt[Nn*2];
__device__ float g_eperm[Ee*2];
__device__ float g_bias2[256];
__device__ float g_cat[Gg*256];
__device__ float g_hd[3*Gg*128];
// CSR by destination
__device__ int g_cnt[Nn];
__device__ int g_incl[Nn];
__device__ int g_bsum[64];
__device__ int g_rowptr[Nn+1];
__device__ int g_cursor[Nn];
__device__ int g_csrc[Ee];
__device__ int g_pos[Ee];

// ---------------- small utility kernels ----------------
__global__ void init_kernel(float* disU, float2* deg01, int* cnt, int n) {
    int i = blockIdx.x*blockDim.x + threadIdx.x;
    if (i < n) { disU[i] = 1.f; deg01[i] = make_float2(1.f, 1.f); cnt[i] = 0; }
}

__global__ void deg_hist(const int* __restrict__ src, const int* __restrict__ dst,
                         float* degU, int* cnt, int E) {
    int i = blockIdx.x*blockDim.x + threadIdx.x;
    if (i < E) {
        atomicAdd(&degU[src[i]], 1.0f);
        atomicAdd(&cnt[dst[i]], 1);
    }
}

__global__ void rsqrt_arr(float* p, int n) {
    int i = blockIdx.x*blockDim.x + threadIdx.x;
    if (i < n) p[i] = rsqrtf(p[i]);
}

// ---------------- CSR build ----------------
__global__ void scan_block(const int* __restrict__ cnt, int* incl, int* bsum, int n) {
    __shared__ int sm[1024];
    int i = blockIdx.x*1024 + threadIdx.x;
    sm[threadIdx.x] = (i < n) ? cnt[i] : 0;
    __syncthreads();
    for (int off = 1; off < 1024; off <<= 1) {
        int t = (threadIdx.x >= off) ? sm[threadIdx.x - off] : 0;
        __syncthreads();
        sm[threadIdx.x] += t;
        __syncthreads();
    }
    if (i < n) incl[i] = sm[threadIdx.x];
    if (threadIdx.x == 1023) bsum[blockIdx.x] = sm[1023];
}

__global__ void scan_tops(int* bsum, int nb) {
    int lane = threadIdx.x;
    int v0 = (lane < nb) ? bsum[lane] : 0;
    int v1 = (32 + lane < nb) ? bsum[32 + lane] : 0;
    #pragma unroll
    for (int o = 1; o < 32; o <<= 1) {
        int t = __shfl_up_sync(0xffffffffu, v0, o);
        if (lane >= o) v0 += t;
    }
    int tot0 = __shfl_sync(0xffffffffu, v0, 31);
    #pragma unroll
    for (int o = 1; o < 32; o <<= 1) {
        int t = __shfl_up_sync(0xffffffffu, v1, o);
        if (lane >= o) v1 += t;
    }
    v1 += tot0;
    if (lane < nb) bsum[lane] = v0;
    if (32 + lane < nb) bsum[32 + lane] = v1;
}

__global__ void make_rowptr(const int* __restrict__ cnt, const int* __restrict__ incl,
                            const int* __restrict__ bsum,
                            int* rowptr, int* cursor, float* disU, int n, int E) {
    int i = blockIdx.x*blockDim.x + threadIdx.x;
    if (i < n) {
        int b = i >> 10;
        int ex = incl[i] - cnt[i] + ((b > 0) ? bsum[b-1] : 0);
        rowptr[i] = ex;
        cursor[i] = ex;
        disU[i] = rsqrtf(disU[i]);
    }
    if (i == 0) rowptr[n] = E;
}

__global__ void fill_csr(const int* __restrict__ src, const int* __restrict__ dst,
                         int* cursor, int* csrc, int* pos, int E) {
    int e = blockIdx.x*blockDim.x + threadIdx.x;
    if (e < E) {
        int p = atomicAdd(&cursor[dst[e]], 1);
        csrc[p] = src[e];
        pos[e] = p;
    }
}

// ---------------- BatchNorm stats ----------------
__global__ void colstats(const float* __restrict__ A, int n, float* sums) {
    long total  = (long)n * 128;
    long stride = (long)gridDim.x * blockDim.x;
    long i0     = (long)blockIdx.x*blockDim.x + threadIdx.x;
    if (i0 >= total) return;
    int c = (int)(i0 % 128);
    float s0 = 0.f, s1 = 0.f;
    for (long i = i0; i < total; i += stride) {
        int r = (int)(i / 128);
        float v = A[(long)r*128 + c];
        s0 += v; s1 += v*v;
    }
    atomicAdd(&sums[c], s0);
    atomicAdd(&sums[128+c], s1);
}

__global__ void colstats2(const float* __restrict__ A, const float* __restrict__ natt,
                          int n, float* sums) {
    long total  = (long)n * 128;
    long stride = (long)gridDim.x * blockDim.x;
    long i0     = (long)blockIdx.x*blockDim.x + threadIdx.x;
    if (i0 >= total) return;
    int c = (int)(i0 % 128);
    float s00=0.f, s01=0.f, s10=0.f, s11=0.f;
    for (long i = i0; i < total; i += stride) {
        int r = (int)(i / 128);
        float v = A[(long)r*128 + c];
        float v0 = v * natt[r*2+0];
        float v1 = v * natt[r*2+1];
        s00 += v0; s01 += v0*v0;
        s10 += v1; s11 += v1*v1;
    }
    atomicAdd(&sums[c], s00);
    atomicAdd(&sums[128+c], s01);
    atomicAdd(&sums[256+c], s10);
    atomicAdd(&sums[384+c], s11);
}

__global__ void finalize_stats(float* sums, int C, float inv_n,
                               float* mean, float* rstd) {
    int c = threadIdx.x + blockIdx.x*blockDim.x;
    if (c < C) {
        float s0 = sums[c], s1 = sums[C+c];
        sums[c] = 0.f; sums[C+c] = 0.f;
        float m = s0*inv_n;
        float var = s1*inv_n - m*m;
        mean[c] = m;
        rstd[c] = rsqrtf(var + EPSBN);
    }
}

__global__ void finalize2(float* sums, float inv_n, float* mean, float* rstd) {
    int c = threadIdx.x;               // 0..255
    int ch = c >> 7, cc = c & 127;
    float s0 = sums[ch*256 + cc], s1 = sums[ch*256 + 128 + cc];
    sums[ch*256 + cc] = 0.f; sums[ch*256 + 128 + cc] = 0.f;
    float m = s0*inv_n;
    float var = s1*inv_n - m*m;
    mean[c] = m;
    rstd[c] = rsqrtf(var + EPSBN);
}

__global__ void head_stats(const float* __restrict__ A, int lda, int n,
                           float* mean, float* rstd) {
    __shared__ float s0s[4], s1s[4];
    int c = blockIdx.x;
    int lane = threadIdx.x & 31, warp = threadIdx.x >> 5;
    float s0 = 0.f, s1 = 0.f;
    for (int r = threadIdx.x; r < n; r += blockDim.x) {
        float v = A[r*lda + c];
        s0 += v; s1 += v*v;
    }
    #pragma unroll
    for (int o = 16; o; o >>= 1) {
        s0 += __shfl_xor_sync(0xffffffffu, s0, o);
        s1 += __shfl_xor_sync(0xffffffffu, s1, o);
    }
    if (lane == 0) { s0s[warp] = s0; s1s[warp] = s1; }
    __syncthreads();
    if (threadIdx.x == 0) {
        float t0 = 0.f, t1 = 0.f;
        for (int w = 0; w < 4; w++) { t0 += s0s[w]; t1 += s1s[w]; }
        float m = t0 / n;
        float var = t1 / n - m*m;
        mean[c] = m;
        rstd[c] = rsqrtf(var + EPSBN);
    }
}

__global__ void head_stats3(const float* __restrict__ hd, int n,
                            float* mean, float* rstd) {
    __shared__ float s0s[4], s1s[4];
    int cg = blockIdx.x;
    int head = cg >> 7, c = cg & 127;
    const float* A = hd + head*Gg*128;
    int lane = threadIdx.x & 31, warp = threadIdx.x >> 5;
    float s0 = 0.f, s1 = 0.f;
    for (int r = threadIdx.x; r < n; r += blockDim.x) {
        float v = A[r*128 + c];
        s0 += v; s1 += v*v;
    }
    #pragma unroll
    for (int o = 16; o; o >>= 1) {
        s0 += __shfl_xor_sync(0xffffffffu, s0, o);
        s1 += __shfl_xor_sync(0xffffffffu, s1, o);
    }
    if (lane == 0) { s0s[warp] = s0; s1s[warp] = s1; }
    __syncthreads();
    if (threadIdx.x == 0) {
        float t0 = 0.f, t1 = 0.f;
        for (int w = 0; w < 4; w++) { t0 += s0s[w]; t1 += s1s[w]; }
        float m = t0 / n;
        float var = t1 / n - m*m;
        mean[cg] = m;
        rstd[cg] = rsqrtf(var + EPSBN);
    }
}

__global__ void bias_kernel(const float* __restrict__ mean, const float* __restrict__ rstd,
                            const float* __restrict__ xcW, const float* __restrict__ xoW,
                            float* __restrict__ bias2) {
    __shared__ float coef[128];
    int hh = blockIdx.x;
    int j = threadIdx.x;
    const float* W = hh ? xoW : xcW;
    coef[j] = BNB - mean[hh*128+j]*rstd[hh*128+j];
    __syncthreads();
    float acc = 0.f;
    for (int k = 0; k < 128; k++) acc += coef[k]*W[k*128+j];
    bias2[hh*128+j] = acc;
}

// ---------------- big GEMM (packed f32x2 FMA, BM=64, K-chunked W) ----------------
static constexpr int GEMM_SMEM = (64*128 + 64*128) * 4;   // 64 KB -> 3 CTAs/SM

__global__ __launch_bounds__(256) void gemm128(
    const float* __restrict__ A,
    const float* __restrict__ mean, const float* __restrict__ rstd,
    const float* __restrict__ W,
    float* __restrict__ out,
    float* __restrict__ sums,
    int n, int act)
{
    extern __shared__ float sm[];
    float* As = sm;               // [64][128]
    float* Ws = sm + 64*128;      // [64][128] W chunk
    int tid  = threadIdx.x;
    int row0 = blockIdx.x * 64;

    #pragma unroll 2
    for (int i = tid; i < 64*32; i += 256) {
        int r = i >> 5, cq = i & 31;
        int gr = row0 + r;
        float4 v = make_float4(0.f,0.f,0.f,0.f);
        if (gr < n) {
            v = ((const float4*)A)[gr*32 + cq];
            int c = cq*4;
            v.x = (v.x - mean[c+0])*rstd[c+0] + BNB;
            v.y = (v.y - mean[c+1])*rstd[c+1] + BNB;
            v.z = (v.z - mean[c+2])*rstd[c+2] + BNB;
            v.w = (v.w - mean[c+3])*rstd[c+3] + BNB;
        }
        ((float4*)As)[i] = v;
    }

    int tc = tid & 15, tr = tid >> 4;
    int r0 = tr*4;
    int c0 = tc*4, c1 = 64 + tc*4;

    u64 accp[4][4];
    #pragma unroll
    for (int i = 0; i < 4; i++)
        #pragma unroll
        for (int j = 0; j < 4; j++) accp[i][j] = 0ull;

    const float4* Wg = (const float4*)W;
    float4* Ws4 = (float4*)Ws;

    #pragma unroll
    for (int kc = 0; kc < 128; kc += 64) {
        __syncthreads();
        #pragma unroll 2
        for (int i = tid; i < 64*32; i += 256)
            Ws4[i] = Wg[(kc + (i >> 5))*32 + (i & 31)];
        __syncthreads();

        for (int k = 0; k < 64; k += 4) {
            float4 a4[4];
            #pragma unroll
            for (int i = 0; i < 4; i++)
                a4[i] = *(const float4*)&As[(r0+i)*128 + kc + k];
            #pragma unroll
            for (int kk = 0; kk < 4; kk++) {
                ulonglong2 w01 = *(const ulonglong2*)&Ws[(k+kk)*128 + c0];
                ulonglong2 w23 = *(const ulonglong2*)&Ws[(k+kk)*128 + c1];
                u64 wp0 = w01.x, wp1 = w01.y, wp2 = w23.x, wp3 = w23.y;
                #pragma unroll
                for (int i = 0; i < 4; i++) {
                    float a = ((const float*)&a4[i])[kk];
                    unsigned int ai = __float_as_uint(a);
                    u64 ap;
                    asm("mov.b64 %0, {%1, %1};" : "=l"(ap) : "r"(ai));
                    asm("fma.rn.f32x2 %0, %1, %2, %0;" : "+l"(accp[i][0]) : "l"(ap), "l"(wp0));
                    asm("fma.rn.f32x2 %0, %1, %2, %0;" : "+l"(accp[i][1]) : "l"(ap), "l"(wp1));
                    asm("fma.rn.f32x2 %0, %1, %2, %0;" : "+l"(accp[i][2]) : "l"(ap), "l"(wp2));
                    asm("fma.rn.f32x2 %0, %1, %2, %0;" : "+l"(accp[i][3]) : "l"(ap), "l"(wp3));
                }
            }
        }
    }

    float t0[8], t1[8];
    #pragma unroll
    for (int j = 0; j < 8; j++) { t0[j] = 0.f; t1[j] = 0.f; }

    float4* O4 = (float4*)out;
    #pragma unroll
    for (int i = 0; i < 4; i++) {
        int gr = row0 + r0 + i;
        if (gr < n) {
            float o[8];
            #pragma unroll
            for (int j = 0; j < 4; j++) {
                unsigned int lo, hi;
                asm("mov.b64 {%0, %1}, %2;" : "=r"(lo), "=r"(hi) : "l"(accp[i][j]));
                o[2*j]   = __uint_as_float(lo);
                o[2*j+1] = __uint_as_float(hi);
            }
            if (act == 1) {
                #pragma unroll
                for (int j = 0; j < 8; j++) o[j] = fmaxf(o[j], 0.f);
            }
            if (sums) {
                #pragma unroll
                for (int j = 0; j < 8; j++) { t0[j] += o[j]; t1[j] += o[j]*o[j]; }
            }
            O4[gr*32 + tc]      = make_float4(o[0], o[1], o[2], o[3]);
            O4[gr*32 + 16 + tc] = make_float4(o[4], o[5], o[6], o[7]);
        }
    }

    if (sums) {
        __syncthreads();
        float* ss = sm;
        ss[tid] = 0.f;
        __syncthreads();
        #pragma unroll
        for (int j = 0; j < 4; j++) {
            atomicAdd(&ss[c0+j],     t0[j]);   atomicAdd(&ss[128+c0+j], t1[j]);
            atomicAdd(&ss[c1+j],     t0[4+j]); atomicAdd(&ss[128+c1+j], t1[4+j]);
        }
        __syncthreads();
        atomicAdd(&sums[tid], ss[tid]);
    }
}

// ---------------- merged XC/XO GEMM (K-chunked W) ----------------
__global__ __launch_bounds__(256) void gemm256(
    const float* __restrict__ h,
    const float* __restrict__ natt,
    const float* __restrict__ rstd2,
    const float* __restrict__ xcW, const float* __restrict__ xoW,
    const float* __restrict__ bias2,
    float* __restrict__ outc, float* __restrict__ outo, int n)
{
    extern __shared__ float sm[];
    float* As = sm;               // [64][128]
    float* Ws = sm + 64*128;      // [64][128] chunk
    int tid  = threadIdx.x;
    int row0 = blockIdx.x * 64;

    #pragma unroll 2
    for (int i = tid; i < 64*32; i += 256) {
        int r = i >> 5, cq = i & 31;
        int gr = row0 + r;
        float4 v = (gr < n) ? ((const float4*)h)[gr*32 + cq]
                            : make_float4(0.f,0.f,0.f,0.f);
        ((float4*)As)[i] = v;
    }

    int tc = tid & 15, tr = tid >> 4;
    int r0 = tr*4;
    int c0 = tc*4, c1 = 64 + tc*4;

    #pragma unroll
    for (int half = 0; half < 2; half++) {
        const float* W  = half ? xoW : xcW;
        const float* rs = rstd2 + half*128;
        const float* bs = bias2 + half*128;
        float* out = half ? outo : outc;

        float nv[4];
        #pragma unroll
        for (int i = 0; i < 4; i++) {
            int gr = row0 + r0 + i;
            nv[i] = (gr < n) ? natt[gr*2 + half] : 0.f;
        }

        u64 accp[4][4];
        #pragma unroll
        for (int i = 0; i < 4; i++)
            #pragma unroll
            for (int j = 0; j < 4; j++) accp[i][j] = 0ull;

        #pragma unroll
        for (int kc = 0; kc < 128; kc += 64) {
            __syncthreads();
            #pragma unroll 2
            for (int i = tid; i < 64*32; i += 256) {
                int r = kc + (i >> 5);
                float4 w = ((const float4*)W)[r*32 + (i & 31)];
                float sc = rs[r];
                w.x *= sc; w.y *= sc; w.z *= sc; w.w *= sc;
                ((float4*)Ws)[i] = w;
            }
            __syncthreads();

            for (int k = 0; k < 64; k += 4) {
                float4 a4[4];
                #pragma unroll
                for (int i = 0; i < 4; i++)
                    a4[i] = *(const float4*)&As[(r0+i)*128 + kc + k];
                #pragma unroll
                for (int kk = 0; kk < 4; kk++) {
                    ulonglong2 w01 = *(const ulonglong2*)&Ws[(k+kk)*128 + c0];
                    ulonglong2 w23 = *(const ulonglong2*)&Ws[(k+kk)*128 + c1];
                    u64 wp0 = w01.x, wp1 = w01.y, wp2 = w23.x, wp3 = w23.y;
                    #pragma unroll
                    for (int i = 0; i < 4; i++) {
                        float a = ((const float*)&a4[i])[kk] * nv[i];
                        unsigned int ai = __float_as_uint(a);
                        u64 ap;
                        asm("mov.b64 %0, {%1, %1};" : "=l"(ap) : "r"(ai));
                        asm("fma.rn.f32x2 %0, %1, %2, %0;" : "+l"(accp[i][0]) : "l"(ap), "l"(wp0));
                        asm("fma.rn.f32x2 %0, %1, %2, %0;" : "+l"(accp[i][1]) : "l"(ap), "l"(wp1));
                        asm("fma.rn.f32x2 %0, %1, %2, %0;" : "+l"(accp[i][2]) : "l"(ap), "l"(wp2));
                        asm("fma.rn.f32x2 %0, %1, %2, %0;" : "+l"(accp[i][3]) : "l"(ap), "l"(wp3));
                    }
                }
            }
        }

        float4 b0 = *(const float4*)&bs[c0];
        float4 b1 = *(const float4*)&bs[c1];
        float4* O4 = (float4*)out;
        #pragma unroll
        for (int i = 0; i < 4; i++) {
            int gr = row0 + r0 + i;
            if (gr < n) {
                float o[8];
                #pragma unroll
                for (int j = 0; j < 4; j++) {
                    unsigned int lo, hi;
                    asm("mov.b64 {%0, %1}, %2;" : "=r"(lo), "=r"(hi) : "l"(accp[i][j]));
                    o[2*j]   = __uint_as_float(lo);
                    o[2*j+1] = __uint_as_float(hi);
                }
                O4[gr*32 + tc]      = make_float4(o[0]+b0.x, o[1]+b0.y, o[2]+b0.z, o[3]+b0.w);
                O4[gr*32 + 16 + tc] = make_float4(o[4]+b1.x, o[5]+b1.y, o[6]+b1.z, o[7]+b1.w);
            }
        }
    }
}

// ---------------- CSR gather conv (MLP-4) ----------------
__global__ __launch_bounds__(256) void gather128(
    const float* __restrict__ t,
    const int* __restrict__ rowptr, const int* __restrict__ csrc,
    const float* __restrict__ dis,
    const float* __restrict__ bias,
    float* __restrict__ out, float* __restrict__ sums,
    const float* __restrict__ eWg, const float* __restrict__ naWg,
    float* __restrict__ epro, float* __restrict__ t2,
    int n, int act)
{
    __shared__ float sEW[512];
    __shared__ float sNA[256];
    if (eWg) {
        for (int i = threadIdx.x; i < 512; i += 256) sEW[i] = eWg[i];
        for (int i = threadIdx.x; i < 256; i += 256) sNA[i] = naWg[i];
        __syncthreads();
    }
    int lane = threadIdx.x & 31;
    int w0 = (blockIdx.x*blockDim.x + threadIdx.x) >> 5;
    int nw = (gridDim.x*blockDim.x) >> 5;
    float4 bb = bias ? ((const float4*)bias)[lane] : make_float4(0.f,0.f,0.f,0.f);
    float ls0[4] = {0.f,0.f,0.f,0.f}, ls1[4] = {0.f,0.f,0.f,0.f};
    const float4* t4 = (const float4*)t;

    for (int v = w0; v < n; v += nw) {
        float dv = dis[v];
        float4 acc = t4[v*32 + lane];
        float d2 = dv*dv;
        acc.x *= d2; acc.y *= d2; acc.z *= d2; acc.w *= d2;
        int p = rowptr[v], en = rowptr[v+1];
        for (; p + 4 <= en; p += 4) {
            int s0 = __ldg(&csrc[p+0]);
            int s1 = __ldg(&csrc[p+1]);
            int s2 = __ldg(&csrc[p+2]);
            int s3 = __ldg(&csrc[p+3]);
            float w0_ = __ldg(&dis[s0]);
            float w1_ = __ldg(&dis[s1]);
            float w2_ = __ldg(&dis[s2]);
            float w3_ = __ldg(&dis[s3]);
            float4 x0 = t4[s0*32 + lane];
            float4 x1 = t4[s1*32 + lane];
            float4 x2 = t4[s2*32 + lane];
            float4 x3 = t4[s3*32 + lane];
            w0_ *= dv; w1_ *= dv; w2_ *= dv; w3_ *= dv;
            acc.x += w0_*x0.x + w1_*x1.x + w2_*x2.x + w3_*x3.x;
            acc.y += w0_*x0.y + w1_*x1.y + w2_*x2.y + w3_*x3.y;
            acc.z += w0_*x0.z + w1_*x1.z + w2_*x2.z + w3_*x3.z;
            acc.w += w0_*x0.w + w1_*x1.w + w2_*x2.w + w3_*x3.w;
        }
        for (; p < en; p++) {
            int s = __ldg(&csrc[p]);
            float w = __ldg(&dis[s]) * dv;
            float4 x = t4[s*32 + lane];
            acc.x += w*x.x; acc.y += w*x.y; acc.z += w*x.z; acc.w += w*x.w;
        }
        acc.x += bb.x; acc.y += bb.y; acc.z += bb.z; acc.w += bb.w;
        if (act == 1) {
            acc.x = fmaxf(acc.x, 0.f); acc.y = fmaxf(acc.y, 0.f);
            acc.z = fmaxf(acc.z, 0.f); acc.w = fmaxf(acc.w, 0.f);
        }
        if (sums) {
            ls0[0]+=acc.x; ls1[0]+=acc.x*acc.x;
            ls0[1]+=acc.y; ls1[1]+=acc.y*acc.y;
            ls0[2]+=acc.z; ls1[2]+=acc.z*acc.z;
            ls0[3]+=acc.w; ls1[3]+=acc.w*acc.w;
        }
        ((float4*)out)[v*32 + lane] = acc;

        if (eWg) {
            float hx[4] = {acc.x, acc.y, acc.z, acc.w};
            float p0=0,p1=0,q0=0,q1=0,u0=0,u1=0;
            #pragma unroll
            for (int i = 0; i < 4; i++) {
                int k = lane*4 + i; float xv = hx[i];
                p0 += xv*sEW[k*2+0];        p1 += xv*sEW[k*2+1];
                q0 += xv*sEW[(128+k)*2+0];  q1 += xv*sEW[(128+k)*2+1];
                u0 += xv*sNA[k*2+0];        u1 += xv*sNA[k*2+1];
            }
            #pragma unroll
            for (int o = 16; o; o >>= 1) {
                p0 += __shfl_xor_sync(0xffffffffu, p0, o);
                p1 += __shfl_xor_sync(0xffffffffu, p1, o);
                q0 += __shfl_xor_sync(0xffffffffu, q0, o);
                q1 += __shfl_xor_sync(0xffffffffu, q1, o);
                u0 += __shfl_xor_sync(0xffffffffu, u0, o);
                u1 += __shfl_xor_sync(0xffffffffu, u1, o);
            }
            if (lane == 0) {
                epro[v*4+0]=p0; epro[v*4+1]=p1; epro[v*4+2]=q0; epro[v*4+3]=q1;
                t2[v*2+0]=u0; t2[v*2+1]=u1;
            }
        }
    }

    if (sums) {
        __shared__ float ss[256];
        ss[threadIdx.x] = 0.f;
        __syncthreads();
        #pragma unroll
        for (int j = 0; j < 4; j++) {
            atomicAdd(&ss[lane*4+j],     ls0[j]);
            atomicAdd(&ss[128+lane*4+j], ls1[j]);
        }
        __syncthreads();
        atomicAdd(&sums[threadIdx.x], ss[threadIdx.x]);
    }
}

// fused XC+XO gather + conv-bias + ELU + global_add_pool
__global__ __launch_bounds__(256) void gather2(
    const float* __restrict__ tc_, const float* __restrict__ to_,
    const int* __restrict__ rowptr, const int* __restrict__ csrc,
    const float2* __restrict__ dis01,
    const float* __restrict__ eperm,
    const float* __restrict__ xcb, const float* __restrict__ xob,
    const int* __restrict__ batch,
    float* __restrict__ cat, int n)
{
    int lane = threadIdx.x & 31;
    int w0 = (blockIdx.x*blockDim.x + threadIdx.x) >> 5;
    int nw = (gridDim.x*blockDim.x) >> 5;
    const float4* tc4 = (const float4*)tc_;
    const float4* to4 = (const float4*)to_;
    float4 bc = ((const float4*)xcb)[lane];
    float4 bo = ((const float4*)xob)[lane];

    for (int v = w0; v < n; v += nw) {
        float2 dv = dis01[v];
        float4 ac = tc4[v*32 + lane];
        float4 ao = to4[v*32 + lane];
        float d02 = dv.x*dv.x, d12 = dv.y*dv.y;
        ac.x *= d02; ac.y *= d02; ac.z *= d02; ac.w *= d02;
        ao.x *= d12; ao.y *= d12; ao.z *= d12; ao.w *= d12;
        int p = rowptr[v], en = rowptr[v+1];
        for (; p + 2 <= en; p += 2) {
            int s0 = __ldg(&csrc[p+0]);
            int s1 = __ldg(&csrc[p+1]);
            float2 ea0 = __ldg((const float2*)&eperm[(p+0)*2]);
            float2 ea1 = __ldg((const float2*)&eperm[(p+1)*2]);
            float2 ds0 = __ldg(&dis01[s0]);
            float2 ds1 = __ldg(&dis01[s1]);
            float4 xc0 = tc4[s0*32 + lane];
            float4 xo0 = to4[s0*32 + lane];
            float4 xc1 = tc4[s1*32 + lane];
            float4 xo1 = to4[s1*32 + lane];
            float wc0 = ds0.x * dv.x * ea0.x, wo0 = ds0.y * dv.y * ea0.y;
            float wc1 = ds1.x * dv.x * ea1.x, wo1 = ds1.y * dv.y * ea1.y;
            ac.x += wc0*xc0.x + wc1*xc1.x; ac.y += wc0*xc0.y + wc1*xc1.y;
            ac.z += wc0*xc0.z + wc1*xc1.z; ac.w += wc0*xc0.w + wc1*xc1.w;
            ao.x += wo0*xo0.x + wo1*xo1.x; ao.y += wo0*xo0.y + wo1*xo1.y;
            ao.z += wo0*xo0.z + wo1*xo1.z; ao.w += wo0*xo0.w + wo1*xo1.w;
        }
        for (; p < en; p++) {
            int s = __ldg(&csrc[p]);
            float2 ea = __ldg((const float2*)&eperm[p*2]);
            float2 ds = __ldg(&dis01[s]);
            float wc = ds.x * dv.x * ea.x;
            float wo = ds.y * dv.y * ea.y;
            float4 xc = tc4[s*32 + lane];
            float4 xo = to4[s*32 + lane];
            ac.x += wc*xc.x; ac.y += wc*xc.y; ac.z += wc*xc.z; ac.w += wc*xc.w;
            ao.x += wo*xo.x; ao.y += wo*xo.y; ao.z += wo*xo.z; ao.w += wo*xo.w;
        }
        float zc[4] = {ac.x+bc.x, ac.y+bc.y, ac.z+bc.z, ac.w+bc.w};
        float zo[4] = {ao.x+bo.x, ao.y+bo.y, ao.z+bo.z, ao.w+bo.w};
        #pragma unroll
        for (int j = 0; j < 4; j++) {
            zc[j] = (zc[j] > 0.f) ? zc[j] : expm1f(zc[j]);
            zo[j] = (zo[j] > 0.f) ? zo[j] : expm1f(zo[j]);
        }
        int g = __ldg(&batch[v]);
        float* pc = cat + g*256 + lane*4;
        float* po = pc + 128;
        asm volatile("red.global.add.v4.f32 [%0], {%1, %2, %3, %4};"
                     :: "l"(pc), "f"(zc[0]), "f"(zc[1]), "f"(zc[2]), "f"(zc[3]) : "memory");
        asm volatile("red.global.add.v4.f32 [%0], {%1, %2, %3, %4};"
                     :: "l"(po), "f"(zo[0]), "f"(zo[1]), "f"(zo[2]), "f"(zo[3]) : "memory");
    }
}

// ---------------- attention ----------------
__global__ void edge_att_kernel(const int* __restrict__ src, const int* __restrict__ dst,
                                const int* __restrict__ pos,
                                const float* __restrict__ epro, const float* __restrict__ eb,
                                float* __restrict__ eperm, float2* __restrict__ deg01, int E) {
    int e = blockIdx.x*blockDim.x + threadIdx.x;
    if (e >= E) return;
    int s = src[e], d = dst[e];
    float2 ps = *(const float2*)&epro[s*4];
    float2 qd = *(const float2*)&epro[d*4+2];
    float l0 = ps.x + qd.x + eb[0];
    float l1 = ps.y + qd.y + eb[1];
    float m = fmaxf(l0, l1);
    float e0 = expf(l0 - m), e1 = expf(l1 - m);
    float inv = 1.f/(e0+e1);
    float a0 = e0*inv, a1 = e1*inv;
    int p = pos[e];
    *(float2*)&eperm[p*2] = make_float2(a0, a1);
    asm volatile("red.global.add.v2.f32 [%0], {%1, %2};"
                 :: "l"(&deg01[s]), "f"(a0), "f"(a1) : "memory");
}

__global__ void natt_gather(const float* __restrict__ t2,
                            const int* __restrict__ rowptr, const int* __restrict__ csrc,
                            const float* __restrict__ disU,
                            const float* __restrict__ nab,
                            float* __restrict__ natt, int n) {
    int v = blockIdx.x*blockDim.x + threadIdx.x;
    if (v >= n) return;
    float dv = disU[v];
    float d2 = dv*dv;
    float a0 = t2[v*2+0]*d2, a1 = t2[v*2+1]*d2;
    int p = rowptr[v], en = rowptr[v+1];
    for (; p + 4 <= en; p += 4) {
        int s0 = __ldg(&csrc[p+0]);
        int s1 = __ldg(&csrc[p+1]);
        int s2 = __ldg(&csrc[p+2]);
        int s3 = __ldg(&csrc[p+3]);
        float w0 = __ldg(&disU[s0]);
        float w1 = __ldg(&disU[s1]);
        float w2 = __ldg(&disU[s2]);
        float w3 = __ldg(&disU[s3]);
        float2 x0 = __ldg((const float2*)&t2[s0*2]);
        float2 x1 = __ldg((const float2*)&t2[s1*2]);
        float2 x2 = __ldg((const float2*)&t2[s2*2]);
        float2 x3 = __ldg((const float2*)&t2[s3*2]);
        w0 *= dv; w1 *= dv; w2 *= dv; w3 *= dv;
        a0 += w0*x0.x + w1*x1.x + w2*x2.x + w3*x3.x;
        a1 += w0*x0.y + w1*x1.y + w2*x2.y + w3*x3.y;
    }
    for (; p < en; p++) {
        int s = __ldg(&csrc[p]);
        float w = __ldg(&disU[s])*dv;
        float2 ts = __ldg((const float2*)&t2[s*2]);
        a0 += w*ts.x;
        a1 += w*ts.y;
    }
    a0 += nab[0]; a1 += nab[1];
    float m = fmaxf(a0, a1);
    float e0 = expf(a0 - m), e1 = expf(a1 - m);
    float inv = 1.f/(e0+e1);
    natt[v*2+0] = e0*inv; natt[v*2+1] = e1*inv;
}

// ---------------- fused heads ----------------
__global__ void head_gemm1(const float* __restrict__ cat,
                           const float* __restrict__ mean, const float* __restrict__ rstd,
                           const float* __restrict__ cW1, const float* __restrict__ cb1,
                           const float* __restrict__ oW1, const float* __restrict__ ob1,
                           const float* __restrict__ coW1, const float* __restrict__ cob1,
                           float* __restrict__ hd) {
    __shared__ float a[256];
    int r = blockIdx.x, head = blockIdx.y;
    for (int k = threadIdx.x; k < 256; k += 128)
        a[k] = (cat[r*256 + k] - mean[k]) * rstd[k] + BNB;
    __syncthreads();
    const float* W; const float* b; int K, koff, act;
    if (head == 0)      { W = cW1;  b = cb1;  K = 128; koff = 0;   act = 1; }
    else if (head == 1) { W = oW1;  b = ob1;  K = 128; koff = 128; act = 1; }
    else                { W = coW1; b = cob1; K = 256; koff = 0;   act = 2; }
    int c = threadIdx.x;
    float acc = b[c];
    for (int k = 0; k < K; k++) acc += a[koff + k] * W[k*128 + c];
    if (act == 1) acc = fmaxf(acc, 0.f);
    else {
        acc = (acc > 0.f) ? acc : expm1f(acc);
        acc = (acc > 0.f) ? acc : expm1f(acc);
    }
    hd[(head*Gg + r)*128 + c] = acc;
}

__global__ void head_gemm2_lsm(const float* __restrict__ hd,
                               const float* __restrict__ mean, const float* __restrict__ rstd,
                               const float* __restrict__ cW2, const float* __restrict__ cb2,
                               const float* __restrict__ oW2, const float* __restrict__ ob2,
                               const float* __restrict__ coW2, const float* __restrict__ cob2,
                               float* __restrict__ out) {
    __shared__ float a[128];
    __shared__ float lg[COUT];
    int r = blockIdx.x, head = blockIdx.y;
    int k = threadIdx.x;
    a[k] = (hd[(head*Gg + r)*128 + k] - mean[head*128 + k]) * rstd[head*128 + k] + BNB;
    __syncthreads();
    const float* W = (head == 0) ? cW2 : (head == 1) ? oW2 : coW2;
    const float* b = (head == 0) ? cb2 : (head == 1) ? ob2 : cob2;
    if (k < COUT) {
        float acc = b[k];
        for (int kk = 0; kk < 128; kk++) acc += a[kk] * W[kk*COUT + k];
        lg[k] = acc;
    }
    __syncthreads();
    if (k < COUT) {
        float m = -1e30f;
        #pragma unroll
        for (int i = 0; i < COUT; i++) m = fmaxf(m, lg[i]);
        float s = 0.f;
        #pragma unroll
        for (int i = 0; i < COUT; i++) s += expf(lg[i] - m);
        out[head*Gg*COUT + r*COUT + k] = lg[k] - m - logf(s);
    }
}

// ---------------- host orchestration ----------------
extern "C" void kernel_launch(void* const* d_in, const int* in_sizes, int n_in,
                              void* d_out, int out_size) {
    const float* x      = (const float*)d_in[0];
    const float* W_feat = (const float*)d_in[1];
    const float* conv_Ws= (const float*)d_in[2];
    const float* conv_bs= (const float*)d_in[3];
    const float* eW     = (const float*)d_in[4];
    const float* eb     = (const float*)d_in[5];
    const float* naW    = (const float*)d_in[6];
    const float* nab    = (const float*)d_in[7];
    const float* xcW    = (const float*)d_in[8];
    const float* xcb    = (const float*)d_in[9];
    const float* xoW    = (const float*)d_in[10];
    const float* xob    = (const float*)d_in[11];
    const float* cW1    = (const float*)d_in[12];
    const float* cb1    = (const float*)d_in[13];
    const float* cW2    = (const float*)d_in[14];
    const float* cb2    = (const float*)d_in[15];
    const float* oW1    = (const float*)d_in[16];
    const float* ob1    = (const float*)d_in[17];
    const float* oW2    = (const float*)d_in[18];
    const float* ob2    = (const float*)d_in[19];
    const float* coW1   = (const float*)d_in[20];
    const float* cob1   = (const float*)d_in[21];
    const float* coW2   = (const float*)d_in[22];
    const float* cob2   = (const float*)d_in[23];
    const int* esrc     = (const int*)d_in[24];
    const int* edst     = (const int*)d_in[25];
    const int* batch    = (const int*)d_in[26];
    float* out = (float*)d_out;

    float *p_h,*p_t,*p_t2b,*p_stats,*p_mean,*p_rstd,*p_disU;
    float *p_epro,*p_t2,*p_natt,*p_eperm,*p_bias2,*p_cat,*p_hd;
    float2* p_deg01;
    int *p_cnt,*p_incl,*p_bsum,*p_rowptr,*p_cursor,*p_csrc,*p_pos;
    cudaGetSymbolAddress((void**)&p_h, g_h);
    cudaGetSymbolAddress((void**)&p_t, g_t);
    cudaGetSymbolAddress((void**)&p_t2b, g_t2b);
    cudaGetSymbolAddress((void**)&p_stats, g_stats);
    cudaGetSymbolAddress((void**)&p_mean, g_mean);
    cudaGetSymbolAddress((void**)&p_rstd, g_rstd);
    cudaGetSymbolAddress((void**)&p_disU, g_disU);
    cudaGetSymbolAddress((void**)&p_deg01, g_deg01);
    cudaGetSymbolAddress((void**)&p_epro, g_epro);
    cudaGetSymbolAddress((void**)&p_t2, g_t2);
    cudaGetSymbolAddress((void**)&p_natt, g_natt);
    cudaGetSymbolAddress((void**)&p_eperm, g_eperm);
    cudaGetSymbolAddress((void**)&p_bias2, g_bias2);
    cudaGetSymbolAddress((void**)&p_cat, g_cat);
    cudaGetSymbolAddress((void**)&p_hd, g_hd);
    cudaGetSymbolAddress((void**)&p_cnt, g_cnt);
    cudaGetSymbolAddress((void**)&p_incl, g_incl);
    cudaGetSymbolAddress((void**)&p_bsum, g_bsum);
    cudaGetSymbolAddress((void**)&p_rowptr, g_rowptr);
    cudaGetSymbolAddress((void**)&p_cursor, g_cursor);
    cudaGetSymbolAddress((void**)&p_csrc, g_csrc);
    cudaGetSymbolAddress((void**)&p_pos, g_pos);

    cudaFuncSetAttribute(gemm128, cudaFuncAttributeMaxDynamicSharedMemorySize, GEMM_SMEM);
    cudaFuncSetAttribute(gemm256, cudaFuncAttributeMaxDynamicSharedMemorySize, GEMM_SMEM);

    const int N = Nn, E = Ee, G = Gg;
    const int NB = (N + 63) / 64;
    const int NT = (N + 255) / 256;
    const int ET = (E + 255) / 256;
    const int GB = 1024;
    const int NSCAN = (N + 1023) / 1024;

    cudaStream_t sA;
    cudaStreamCreateWithFlags(&sA, cudaStreamNonBlocking);
    cudaEvent_t evF1, evJ1, evF2, evJ2;
    cudaEventCreateWithFlags(&evF1, cudaEventDisableTiming);
    cudaEventCreateWithFlags(&evJ1, cudaEventDisableTiming);
    cudaEventCreateWithFlags(&evF2, cudaEventDisableTiming);
    cudaEventCreateWithFlags(&evJ2, cudaEventDisableTiming);

    // ==== FORK 1: CSR build on sA ====
    cudaEventRecord(evF1, 0);
    cudaStreamWaitEvent(sA, evF1, 0);
    init_kernel<<<NT,256,0,sA>>>(p_disU, p_deg01, p_cnt, N);
    deg_hist<<<ET,256,0,sA>>>(esrc, edst, p_disU, p_cnt, E);
    scan_block<<<NSCAN,1024,0,sA>>>(p_cnt, p_incl, p_bsum, N);
    scan_tops<<<1,32,0,sA>>>(p_bsum, NSCAN);
    make_rowptr<<<NT,256,0,sA>>>(p_cnt, p_incl, p_bsum, p_rowptr, p_cursor, p_disU, N, E);
    fill_csr<<<ET,256,0,sA>>>(esrc, edst, p_cursor, p_csrc, p_pos, E);
    cudaEventRecord(evJ1, sA);

    // main chain: h = relu(BN(x) @ W_feat), stats fused; layer-0 GEMM
    colstats<<<512,256>>>(x, N, p_stats);
    finalize_stats<<<1,256>>>(p_stats, 128, 1.f/N, p_mean, p_rstd);
    gemm128<<<NB,256,GEMM_SMEM>>>(x, p_mean, p_rstd, W_feat, p_h, p_stats, N, 1);
    finalize_stats<<<1,256>>>(p_stats, 128, 1.f/N, p_mean, p_rstd);
    gemm128<<<NB,256,GEMM_SMEM>>>(p_h, p_mean, p_rstd, conv_Ws, p_t, nullptr, N, 0);

    // JOIN 1 (gather needs CSR + disU)
    cudaStreamWaitEvent(0, evJ1, 0);

    // ---- GCN layers ----
    gather128<<<GB,256>>>(p_t, p_rowptr, p_csrc, p_disU, conv_bs, p_h, p_stats,
                          nullptr, nullptr, nullptr, nullptr, N, 1);
    finalize_stats<<<1,256>>>(p_stats, 128, 1.f/N, p_mean, p_rstd);
    for (int l = 1; l < 3; l++) {
        gemm128<<<NB,256,GEMM_SMEM>>>(p_h, p_mean, p_rstd,
                                      conv_Ws + l*128*128, p_t, nullptr, N, 0);
        if (l < 2) {
            gather128<<<GB,256>>>(p_t, p_rowptr, p_csrc, p_disU,
                                  conv_bs + l*128, p_h, p_stats,
                                  nullptr, nullptr, nullptr, nullptr, N, 1);
            finalize_stats<<<1,256>>>(p_stats, 128, 1.f/N, p_mean, p_rstd);
        } else {
            gather128<<<GB,256>>>(p_t, p_rowptr, p_csrc, p_disU,
                                  conv_bs + l*128, p_h, nullptr,
                                  eW, naW, p_epro, p_t2, N, 1);
        }
    }

    // ==== FORK 2: edge attention on sA ====
    cudaEventRecord(evF2, 0);
    cudaStreamWaitEvent(sA, evF2, 0);
    edge_att_kernel<<<ET,256,0,sA>>>(esrc, edst, p_pos, p_epro, eb, p_eperm, p_deg01, E);
    rsqrt_arr<<<(2*N+255)/256,256,0,sA>>>((float*)p_deg01, 2*N);
    cudaMemsetAsync(p_cat, 0, Gg*256*sizeof(float), sA);
    cudaEventRecord(evJ2, sA);

    // main: node attention + XC/XO stats + merged GEMM
    natt_gather<<<NT,256>>>(p_t2, p_rowptr, p_csrc, p_disU, nab, p_natt, N);
    colstats2<<<512,256>>>(p_h, p_natt, N, p_stats);
    finalize2<<<1,256>>>(p_stats, 1.f/N, p_mean, p_rstd);
    bias_kernel<<<2,128>>>(p_mean, p_rstd, xcW, xoW, p_bias2);
    gemm256<<<NB,256,GEMM_SMEM>>>(p_h, p_natt, p_rstd, xcW, xoW, p_bias2,
                                  p_t, p_t2b, N);

    // JOIN 2 (gather2 needs eperm + deg01 + zeroed cat)
    cudaStreamWaitEvent(0, evJ2, 0);
    gather2<<<GB,256>>>(p_t, p_t2b, p_rowptr, p_csrc, p_deg01, p_eperm,
                        xcb, xob, batch, p_cat, N);

    // ---- heads ----
    head_stats<<<256,128>>>(p_cat, 256, G, p_mean, p_rstd);
    dim3 hg1(G, 3);
    head_gemm1<<<hg1,128>>>(p_cat, p_mean, p_rstd, cW1, cb1, oW1, ob1,
                            coW1, cob1, p_hd);
    head_stats3<<<384,128>>>(p_hd, G, p_mean, p_rstd);
    dim3 hg2(G, 3);
    head_gemm2_lsm<<<hg2,128>>>(p_hd, p_mean, p_rstd, cW2, cb2, oW2, ob2,
                                coW2, cob2, out);

    cudaEventDestroy(evF1);
    cudaEventDestroy(evJ1);
    cudaEventDestroy(evF2);
    cudaEventDestroy(evJ2);
    cudaStreamDestroy(sA);
}

// round 13
// speedup vs baseline: 1.0246x; 1.0065x over previous
#include <cuda_runtime.h>
#include <math.h>

#define Nn 50000
#define Ee 400000
#define Hh 128
#define Gg 512
#define COUT 10

typedef unsigned long long u64;

static constexpr float EPSBN = 1e-5f;
static constexpr float BNB   = 1e-4f;

// ---------------- scratch (static device allocations) ----------------
__device__ float g_h[Nn*Hh];
__device__ float g_t[Nn*Hh];
__device__ float g_t2b[Nn*Hh];
__device__ float g_stats[512];      // zero-init; every consumer re-zeroes
__device__ float g_mean[512];
__device__ float g_rstd[512];
__device__ float g_disU[Nn];
__device__ float2 g_deg01[Nn];
__device__ float g_epro[Nn*4];
__device__ float g_t2[Nn*2];
__device__ float g_natt[Nn*2];
__device__ float g_eperm[Ee*2];
__device__ float g_bias2[256];
__device__ float g_cat[Gg*256];
__device__ float g_hd[3*Gg*128];
// CSR by destination
__device__ int g_cnt[Nn];
__device__ int g_incl[Nn];
__device__ int g_bsum[64];
__device__ int g_rowptr[Nn+1];
__device__ int g_cursor[Nn];
__device__ int g_csrc[Ee];
__device__ int g_pos[Ee];

// ---------------- small utility kernels ----------------
__global__ void init_kernel(float* disU, float2* deg01, int* cnt, int n) {
    int i = blockIdx.x*blockDim.x + threadIdx.x;
    if (i < n) { disU[i] = 1.f; deg01[i] = make_float2(1.f, 1.f); cnt[i] = 0; }
}

__global__ void deg_hist(const int* __restrict__ src, const int* __restrict__ dst,
                         float* degU, int* cnt, int E) {
    int i = blockIdx.x*blockDim.x + threadIdx.x;
    if (i < E) {
        atomicAdd(&degU[src[i]], 1.0f);
        atomicAdd(&cnt[dst[i]], 1);
    }
}

__global__ void rsqrt_arr(float* p, int n) {
    int i = blockIdx.x*blockDim.x + threadIdx.x;
    if (i < n) p[i] = rsqrtf(p[i]);
}

// ---------------- CSR build ----------------
__global__ void scan_block(const int* __restrict__ cnt, int* incl, int* bsum, int n) {
    __shared__ int sm[1024];
    int i = blockIdx.x*1024 + threadIdx.x;
    sm[threadIdx.x] = (i < n) ? cnt[i] : 0;
    __syncthreads();
    for (int off = 1; off < 1024; off <<= 1) {
        int t = (threadIdx.x >= off) ? sm[threadIdx.x - off] : 0;
        __syncthreads();
        sm[threadIdx.x] += t;
        __syncthreads();
    }
    if (i < n) incl[i] = sm[threadIdx.x];
    if (threadIdx.x == 1023) bsum[blockIdx.x] = sm[1023];
}

__global__ void scan_tops(int* bsum, int nb) {
    int lane = threadIdx.x;
    int v0 = (lane < nb) ? bsum[lane] : 0;
    int v1 = (32 + lane < nb) ? bsum[32 + lane] : 0;
    #pragma unroll
    for (int o = 1; o < 32; o <<= 1) {
        int t = __shfl_up_sync(0xffffffffu, v0, o);
        if (lane >= o) v0 += t;
    }
    int tot0 = __shfl_sync(0xffffffffu, v0, 31);
    #pragma unroll
    for (int o = 1; o < 32; o <<= 1) {
        int t = __shfl_up_sync(0xffffffffu, v1, o);
        if (lane >= o) v1 += t;
    }
    v1 += tot0;
    if (lane < nb) bsum[lane] = v0;
    if (32 + lane < nb) bsum[32 + lane] = v1;
}

__global__ void make_rowptr(const int* __restrict__ cnt, const int* __restrict__ incl,
                            const int* __restrict__ bsum,
                            int* rowptr, int* cursor, float* disU, int n, int E) {
    int i = blockIdx.x*blockDim.x + threadIdx.x;
    if (i < n) {
        int b = i >> 10;
        int ex = incl[i] - cnt[i] + ((b > 0) ? bsum[b-1] : 0);
        rowptr[i] = ex;
        cursor[i] = ex;
        disU[i] = rsqrtf(disU[i]);
    }
    if (i == 0) rowptr[n] = E;
}

__global__ void fill_csr(const int* __restrict__ src, const int* __restrict__ dst,
                         int* cursor, int* csrc, int* pos, int E) {
    int e = blockIdx.x*blockDim.x + threadIdx.x;
    if (e < E) {
        int p = atomicAdd(&cursor[dst[e]], 1);
        csrc[p] = src[e];
        pos[e] = p;
    }
}

// ---------------- BatchNorm stats ----------------
__global__ void colstats(const float* __restrict__ A, int n, float* sums) {
    long total  = (long)n * 128;
    long stride = (long)gridDim.x * blockDim.x;
    long i0     = (long)blockIdx.x*blockDim.x + threadIdx.x;
    if (i0 >= total) return;
    int c = (int)(i0 % 128);
    float s0 = 0.f, s1 = 0.f;
    for (long i = i0; i < total; i += stride) {
        int r = (int)(i / 128);
        float v = A[(long)r*128 + c];
        s0 += v; s1 += v*v;
    }
    atomicAdd(&sums[c], s0);
    atomicAdd(&sums[128+c], s1);
}

__global__ void colstats2(const float* __restrict__ A, const float* __restrict__ natt,
                          int n, float* sums) {
    long total  = (long)n * 128;
    long stride = (long)gridDim.x * blockDim.x;
    long i0     = (long)blockIdx.x*blockDim.x + threadIdx.x;
    if (i0 >= total) return;
    int c = (int)(i0 % 128);
    float s00=0.f, s01=0.f, s10=0.f, s11=0.f;
    for (long i = i0; i < total; i += stride) {
        int r = (int)(i / 128);
        float v = A[(long)r*128 + c];
        float v0 = v * natt[r*2+0];
        float v1 = v * natt[r*2+1];
        s00 += v0; s01 += v0*v0;
        s10 += v1; s11 += v1*v1;
    }
    atomicAdd(&sums[c], s00);
    atomicAdd(&sums[128+c], s01);
    atomicAdd(&sums[256+c], s10);
    atomicAdd(&sums[384+c], s11);
}

__global__ void finalize_stats(float* sums, int C, float inv_n,
                               float* mean, float* rstd) {
    int c = threadIdx.x + blockIdx.x*blockDim.x;
    if (c < C) {
        float s0 = sums[c], s1 = sums[C+c];
        sums[c] = 0.f; sums[C+c] = 0.f;
        float m = s0*inv_n;
        float var = s1*inv_n - m*m;
        mean[c] = m;
        rstd[c] = rsqrtf(var + EPSBN);
    }
}

__global__ void finalize2(float* sums, float inv_n, float* mean, float* rstd) {
    int c = threadIdx.x;               // 0..255
    int ch = c >> 7, cc = c & 127;
    float s0 = sums[ch*256 + cc], s1 = sums[ch*256 + 128 + cc];
    sums[ch*256 + cc] = 0.f; sums[ch*256 + 128 + cc] = 0.f;
    float m = s0*inv_n;
    float var = s1*inv_n - m*m;
    mean[c] = m;
    rstd[c] = rsqrtf(var + EPSBN);
}

__global__ void head_stats(const float* __restrict__ A, int lda, int n,
                           float* mean, float* rstd) {
    __shared__ float s0s[4], s1s[4];
    int c = blockIdx.x;
    int lane = threadIdx.x & 31, warp = threadIdx.x >> 5;
    float s0 = 0.f, s1 = 0.f;
    for (int r = threadIdx.x; r < n; r += blockDim.x) {
        float v = A[r*lda + c];
        s0 += v; s1 += v*v;
    }
    #pragma unroll
    for (int o = 16; o; o >>= 1) {
        s0 += __shfl_xor_sync(0xffffffffu, s0, o);
        s1 += __shfl_xor_sync(0xffffffffu, s1, o);
    }
    if (lane == 0) { s0s[warp] = s0; s1s[warp] = s1; }
    __syncthreads();
    if (threadIdx.x == 0) {
        float t0 = 0.f, t1 = 0.f;
        for (int w = 0; w < 4; w++) { t0 += s0s[w]; t1 += s1s[w]; }
        float m = t0 / n;
        float var = t1 / n - m*m;
        mean[c] = m;
        rstd[c] = rsqrtf(var + EPSBN);
    }
}

__global__ void head_stats3(const float* __restrict__ hd, int n,
                            float* mean, float* rstd) {
    __shared__ float s0s[4], s1s[4];
    int cg = blockIdx.x;
    int head = cg >> 7, c = cg & 127;
    const float* A = hd + head*Gg*128;
    int lane = threadIdx.x & 31, warp = threadIdx.x >> 5;
    float s0 = 0.f, s1 = 0.f;
    for (int r = threadIdx.x; r < n; r += blockDim.x) {
        float v = A[r*128 + c];
        s0 += v; s1 += v*v;
    }
    #pragma unroll
    for (int o = 16; o; o >>= 1) {
        s0 += __shfl_xor_sync(0xffffffffu, s0, o);
        s1 += __shfl_xor_sync(0xffffffffu, s1, o);
    }
    if (lane == 0) { s0s[warp] = s0; s1s[warp] = s1; }
    __syncthreads();
    if (threadIdx.x == 0) {
        float t0 = 0.f, t1 = 0.f;
        for (int w = 0; w < 4; w++) { t0 += s0s[w]; t1 += s1s[w]; }
        float m = t0 / n;
        float var = t1 / n - m*m;
        mean[cg] = m;
        rstd[cg] = rsqrtf(var + EPSBN);
    }
}

__global__ void bias_kernel(const float* __restrict__ mean, const float* __restrict__ rstd,
                            const float* __restrict__ xcW, const float* __restrict__ xoW,
                            float* __restrict__ bias2) {
    __shared__ float coef[128];
    int hh = blockIdx.x;
    int j = threadIdx.x;
    const float* W = hh ? xoW : xcW;
    coef[j] = BNB - mean[hh*128+j]*rstd[hh*128+j];
    __syncthreads();
    float acc = 0.f;
    for (int k = 0; k < 128; k++) acc += coef[k]*W[k*128+j];
    bias2[hh*128+j] = acc;
}

// ---------------- big GEMM (packed f32x2 FMA, BM=64, K-chunked W, 3 CTAs/SM) ----------------
static constexpr int GEMM_SMEM = (64*128 + 64*128) * 4;   // 64 KB

__global__ __launch_bounds__(256, 3) void gemm128(
    const float* __restrict__ A,
    const float* __restrict__ mean, const float* __restrict__ rstd,
    const float* __restrict__ W,
    float* __restrict__ out,
    float* __restrict__ sums,
    int n, int act)
{
    extern __shared__ float sm[];
    float* As = sm;               // [64][128]
    float* Ws = sm + 64*128;      // [64][128] W chunk
    int tid  = threadIdx.x;
    int row0 = blockIdx.x * 64;

    #pragma unroll 2
    for (int i = tid; i < 64*32; i += 256) {
        int r = i >> 5, cq = i & 31;
        int gr = row0 + r;
        float4 v = make_float4(0.f,0.f,0.f,0.f);
        if (gr < n) {
            v = ((const float4*)A)[gr*32 + cq];
            int c = cq*4;
            v.x = (v.x - mean[c+0])*rstd[c+0] + BNB;
            v.y = (v.y - mean[c+1])*rstd[c+1] + BNB;
            v.z = (v.z - mean[c+2])*rstd[c+2] + BNB;
            v.w = (v.w - mean[c+3])*rstd[c+3] + BNB;
        }
        ((float4*)As)[i] = v;
    }

    int tc = tid & 15, tr = tid >> 4;
    int r0 = tr*4;
    int c0 = tc*4, c1 = 64 + tc*4;

    u64 accp[4][4];
    #pragma unroll
    for (int i = 0; i < 4; i++)
        #pragma unroll
        for (int j = 0; j < 4; j++) accp[i][j] = 0ull;

    const float4* Wg = (const float4*)W;
    float4* Ws4 = (float4*)Ws;

    #pragma unroll
    for (int kc = 0; kc < 128; kc += 64) {
        __syncthreads();
        #pragma unroll 2
        for (int i = tid; i < 64*32; i += 256)
            Ws4[i] = Wg[(kc + (i >> 5))*32 + (i & 31)];
        __syncthreads();

        for (int k = 0; k < 64; k += 4) {
            float4 a4[4];
            #pragma unroll
            for (int i = 0; i < 4; i++)
                a4[i] = *(const float4*)&As[(r0+i)*128 + kc + k];
            #pragma unroll
            for (int kk = 0; kk < 4; kk++) {
                ulonglong2 w01 = *(const ulonglong2*)&Ws[(k+kk)*128 + c0];
                ulonglong2 w23 = *(const ulonglong2*)&Ws[(k+kk)*128 + c1];
                u64 wp0 = w01.x, wp1 = w01.y, wp2 = w23.x, wp3 = w23.y;
                #pragma unroll
                for (int i = 0; i < 4; i++) {
                    float a = ((const float*)&a4[i])[kk];
                    unsigned int ai = __float_as_uint(a);
                    u64 ap;
                    asm("mov.b64 %0, {%1, %1};" : "=l"(ap) : "r"(ai));
                    asm("fma.rn.f32x2 %0, %1, %2, %0;" : "+l"(accp[i][0]) : "l"(ap), "l"(wp0));
                    asm("fma.rn.f32x2 %0, %1, %2, %0;" : "+l"(accp[i][1]) : "l"(ap), "l"(wp1));
                    asm("fma.rn.f32x2 %0, %1, %2, %0;" : "+l"(accp[i][2]) : "l"(ap), "l"(wp2));
                    asm("fma.rn.f32x2 %0, %1, %2, %0;" : "+l"(accp[i][3]) : "l"(ap), "l"(wp3));
                }
            }
        }
    }

    float t0[8], t1[8];
    #pragma unroll
    for (int j = 0; j < 8; j++) { t0[j] = 0.f; t1[j] = 0.f; }

    float4* O4 = (float4*)out;
    #pragma unroll
    for (int i = 0; i < 4; i++) {
        int gr = row0 + r0 + i;
        if (gr < n) {
            float o[8];
            #pragma unroll
            for (int j = 0; j < 4; j++) {
                unsigned int lo, hi;
                asm("mov.b64 {%0, %1}, %2;" : "=r"(lo), "=r"(hi) : "l"(accp[i][j]));
                o[2*j]   = __uint_as_float(lo);
                o[2*j+1] = __uint_as_float(hi);
            }
            if (act == 1) {
                #pragma unroll
                for (int j = 0; j < 8; j++) o[j] = fmaxf(o[j], 0.f);
            }
            if (sums) {
                #pragma unroll
                for (int j = 0; j < 8; j++) { t0[j] += o[j]; t1[j] += o[j]*o[j]; }
            }
            O4[gr*32 + tc]      = make_float4(o[0], o[1], o[2], o[3]);
            O4[gr*32 + 16 + tc] = make_float4(o[4], o[5], o[6], o[7]);
        }
    }

    if (sums) {
        __syncthreads();
        float* ss = sm;
        ss[tid] = 0.f;
        __syncthreads();
        #pragma unroll
        for (int j = 0; j < 4; j++) {
            atomicAdd(&ss[c0+j],     t0[j]);   atomicAdd(&ss[128+c0+j], t1[j]);
            atomicAdd(&ss[c1+j],     t0[4+j]); atomicAdd(&ss[128+c1+j], t1[4+j]);
        }
        __syncthreads();
        atomicAdd(&sums[tid], ss[tid]);
    }
}

// ---------------- merged XC/XO GEMM (K-chunked W, 3 CTAs/SM) ----------------
__global__ __launch_bounds__(256, 3) void gemm256(
    const float* __restrict__ h,
    const float* __restrict__ natt,
    const float* __restrict__ rstd2,
    const float* __restrict__ xcW, const float* __restrict__ xoW,
    const float* __restrict__ bias2,
    float* __restrict__ outc, float* __restrict__ outo, int n)
{
    extern __shared__ float sm[];
    float* As = sm;               // [64][128]
    float* Ws = sm + 64*128;      // [64][128] chunk
    int tid  = threadIdx.x;
    int row0 = blockIdx.x * 64;

    #pragma unroll 2
    for (int i = tid; i < 64*32; i += 256) {
        int r = i >> 5, cq = i & 31;
        int gr = row0 + r;
        float4 v = (gr < n) ? ((const float4*)h)[gr*32 + cq]
                            : make_float4(0.f,0.f,0.f,0.f);
        ((float4*)As)[i] = v;
    }

    int tc = tid & 15, tr = tid >> 4;
    int r0 = tr*4;
    int c0 = tc*4, c1 = 64 + tc*4;

    #pragma unroll
    for (int half = 0; half < 2; half++) {
        const float* W  = half ? xoW : xcW;
        const float* rs = rstd2 + half*128;
        const float* bs = bias2 + half*128;
        float* out = half ? outo : outc;

        float nv[4];
        #pragma unroll
        for (int i = 0; i < 4; i++) {
            int gr = row0 + r0 + i;
            nv[i] = (gr < n) ? natt[gr*2 + half] : 0.f;
        }

        u64 accp[4][4];
        #pragma unroll
        for (int i = 0; i < 4; i++)
            #pragma unroll
            for (int j = 0; j < 4; j++) accp[i][j] = 0ull;

        #pragma unroll
        for (int kc = 0; kc < 128; kc += 64) {
            __syncthreads();
            #pragma unroll 2
            for (int i = tid; i < 64*32; i += 256) {
                int r = kc + (i >> 5);
                float4 w = ((const float4*)W)[r*32 + (i & 31)];
                float sc = rs[r];
                w.x *= sc; w.y *= sc; w.z *= sc; w.w *= sc;
                ((float4*)Ws)[i] = w;
            }
            __syncthreads();

            for (int k = 0; k < 64; k += 4) {
                float4 a4[4];
                #pragma unroll
                for (int i = 0; i < 4; i++)
                    a4[i] = *(const float4*)&As[(r0+i)*128 + kc + k];
                #pragma unroll
                for (int kk = 0; kk < 4; kk++) {
                    ulonglong2 w01 = *(const ulonglong2*)&Ws[(k+kk)*128 + c0];
                    ulonglong2 w23 = *(const ulonglong2*)&Ws[(k+kk)*128 + c1];
                    u64 wp0 = w01.x, wp1 = w01.y, wp2 = w23.x, wp3 = w23.y;
                    #pragma unroll
                    for (int i = 0; i < 4; i++) {
                        float a = ((const float*)&a4[i])[kk] * nv[i];
                        unsigned int ai = __float_as_uint(a);
                        u64 ap;
                        asm("mov.b64 %0, {%1, %1};" : "=l"(ap) : "r"(ai));
                        asm("fma.rn.f32x2 %0, %1, %2, %0;" : "+l"(accp[i][0]) : "l"(ap), "l"(wp0));
                        asm("fma.rn.f32x2 %0, %1, %2, %0;" : "+l"(accp[i][1]) : "l"(ap), "l"(wp1));
                        asm("fma.rn.f32x2 %0, %1, %2, %0;" : "+l"(accp[i][2]) : "l"(ap), "l"(wp2));
                        asm("fma.rn.f32x2 %0, %1, %2, %0;" : "+l"(accp[i][3]) : "l"(ap), "l"(wp3));
                    }
                }
            }
        }

        float4 b0 = *(const float4*)&bs[c0];
        float4 b1 = *(const float4*)&bs[c1];
        float4* O4 = (float4*)out;
        #pragma unroll
        for (int i = 0; i < 4; i++) {
            int gr = row0 + r0 + i;
            if (gr < n) {
                float o[8];
                #pragma unroll
                for (int j = 0; j < 4; j++) {
                    unsigned int lo, hi;
                    asm("mov.b64 {%0, %1}, %2;" : "=r"(lo), "=r"(hi) : "l"(accp[i][j]));
                    o[2*j]   = __uint_as_float(lo);
                    o[2*j+1] = __uint_as_float(hi);
                }
                O4[gr*32 + tc]      = make_float4(o[0]+b0.x, o[1]+b0.y, o[2]+b0.z, o[3]+b0.w);
                O4[gr*32 + 16 + tc] = make_float4(o[4]+b1.x, o[5]+b1.y, o[6]+b1.z, o[7]+b1.w);
            }
        }
    }
}

// ---------------- CSR gather conv (MLP-4) ----------------
__global__ __launch_bounds__(256) void gather128(
    const float* __restrict__ t,
    const int* __restrict__ rowptr, const int* __restrict__ csrc,
    const float* __restrict__ dis,
    const float* __restrict__ bias,
    float* __restrict__ out, float* __restrict__ sums,
    const float* __restrict__ eWg, const float* __restrict__ naWg,
    float* __restrict__ epro, float* __restrict__ t2,
    int n, int act)
{
    __shared__ float sEW[512];
    __shared__ float sNA[256];
    if (eWg) {
        for (int i = threadIdx.x; i < 512; i += 256) sEW[i] = eWg[i];
        for (int i = threadIdx.x; i < 256; i += 256) sNA[i] = naWg[i];
        __syncthreads();
    }
    int lane = threadIdx.x & 31;
    int w0 = (blockIdx.x*blockDim.x + threadIdx.x) >> 5;
    int nw = (gridDim.x*blockDim.x) >> 5;
    float4 bb = bias ? ((const float4*)bias)[lane] : make_float4(0.f,0.f,0.f,0.f);
    float ls0[4] = {0.f,0.f,0.f,0.f}, ls1[4] = {0.f,0.f,0.f,0.f};
    const float4* t4 = (const float4*)t;

    for (int v = w0; v < n; v += nw) {
        float dv = dis[v];
        float4 acc = t4[v*32 + lane];
        float d2 = dv*dv;
        acc.x *= d2; acc.y *= d2; acc.z *= d2; acc.w *= d2;
        int p = rowptr[v], en = rowptr[v+1];
        for (; p + 4 <= en; p += 4) {
            int s0 = __ldg(&csrc[p+0]);
            int s1 = __ldg(&csrc[p+1]);
            int s2 = __ldg(&csrc[p+2]);
            int s3 = __ldg(&csrc[p+3]);
            float w0_ = __ldg(&dis[s0]);
            float w1_ = __ldg(&dis[s1]);
            float w2_ = __ldg(&dis[s2]);
            float w3_ = __ldg(&dis[s3]);
            float4 x0 = t4[s0*32 + lane];
            float4 x1 = t4[s1*32 + lane];
            float4 x2 = t4[s2*32 + lane];
            float4 x3 = t4[s3*32 + lane];
            w0_ *= dv; w1_ *= dv; w2_ *= dv; w3_ *= dv;
            acc.x += w0_*x0.x + w1_*x1.x + w2_*x2.x + w3_*x3.x;
            acc.y += w0_*x0.y + w1_*x1.y + w2_*x2.y + w3_*x3.y;
            acc.z += w0_*x0.z + w1_*x1.z + w2_*x2.z + w3_*x3.z;
            acc.w += w0_*x0.w + w1_*x1.w + w2_*x2.w + w3_*x3.w;
        }
        for (; p < en; p++) {
            int s = __ldg(&csrc[p]);
            float w = __ldg(&dis[s]) * dv;
            float4 x = t4[s*32 + lane];
            acc.x += w*x.x; acc.y += w*x.y; acc.z += w*x.z; acc.w += w*x.w;
        }
        acc.x += bb.x; acc.y += bb.y; acc.z += bb.z; acc.w += bb.w;
        if (act == 1) {
            acc.x = fmaxf(acc.x, 0.f); acc.y = fmaxf(acc.y, 0.f);
            acc.z = fmaxf(acc.z, 0.f); acc.w = fmaxf(acc.w, 0.f);
        }
        if (sums) {
            ls0[0]+=acc.x; ls1[0]+=acc.x*acc.x;
            ls0[1]+=acc.y; ls1[1]+=acc.y*acc.y;
            ls0[2]+=acc.z; ls1[2]+=acc.z*acc.z;
            ls0[3]+=acc.w; ls1[3]+=acc.w*acc.w;
        }
        ((float4*)out)[v*32 + lane] = acc;

        if (eWg) {
            float hx[4] = {acc.x, acc.y, acc.z, acc.w};
            float p0=0,p1=0,q0=0,q1=0,u0=0,u1=0;
            #pragma unroll
            for (int i = 0; i < 4; i++) {
                int k = lane*4 + i; float xv = hx[i];
                p0 += xv*sEW[k*2+0];        p1 += xv*sEW[k*2+1];
                q0 += xv*sEW[(128+k)*2+0];  q1 += xv*sEW[(128+k)*2+1];
                u0 += xv*sNA[k*2+0];        u1 += xv*sNA[k*2+1];
            }
            #pragma unroll
            for (int o = 16; o; o >>= 1) {
                p0 += __shfl_xor_sync(0xffffffffu, p0, o);
                p1 += __shfl_xor_sync(0xffffffffu, p1, o);
                q0 += __shfl_xor_sync(0xffffffffu, q0, o);
                q1 += __shfl_xor_sync(0xffffffffu, q1, o);
                u0 += __shfl_xor_sync(0xffffffffu, u0, o);
                u1 += __shfl_xor_sync(0xffffffffu, u1, o);
            }
            if (lane == 0) {
                epro[v*4+0]=p0; epro[v*4+1]=p1; epro[v*4+2]=q0; epro[v*4+3]=q1;
                t2[v*2+0]=u0; t2[v*2+1]=u1;
            }
        }
    }

    if (sums) {
        __shared__ float ss[256];
        ss[threadIdx.x] = 0.f;
        __syncthreads();
        #pragma unroll
        for (int j = 0; j < 4; j++) {
            atomicAdd(&ss[lane*4+j],     ls0[j]);
            atomicAdd(&ss[128+lane*4+j], ls1[j]);
        }
        __syncthreads();
        atomicAdd(&sums[threadIdx.x], ss[threadIdx.x]);
    }
}

// fused XC+XO gather + conv-bias + ELU + global_add_pool
__global__ __launch_bounds__(256) void gather2(
    const float* __restrict__ tc_, const float* __restrict__ to_,
    const int* __restrict__ rowptr, const int* __restrict__ csrc,
    const float2* __restrict__ dis01,
    const float* __restrict__ eperm,
    const float* __restrict__ xcb, const float* __restrict__ xob,
    const int* __restrict__ batch,
    float* __restrict__ cat, int n)
{
    int lane = threadIdx.x & 31;
    int w0 = (blockIdx.x*blockDim.x + threadIdx.x) >> 5;
    int nw = (gridDim.x*blockDim.x) >> 5;
    const float4* tc4 = (const float4*)tc_;
    const float4* to4 = (const float4*)to_;
    float4 bc = ((const float4*)xcb)[lane];
    float4 bo = ((const float4*)xob)[lane];

    for (int v = w0; v < n; v += nw) {
        float2 dv = dis01[v];
        float4 ac = tc4[v*32 + lane];
        float4 ao = to4[v*32 + lane];
        float d02 = dv.x*dv.x, d12 = dv.y*dv.y;
        ac.x *= d02; ac.y *= d02; ac.z *= d02; ac.w *= d02;
        ao.x *= d12; ao.y *= d12; ao.z *= d12; ao.w *= d12;
        int p = rowptr[v], en = rowptr[v+1];
        for (; p + 2 <= en; p += 2) {
            int s0 = __ldg(&csrc[p+0]);
            int s1 = __ldg(&csrc[p+1]);
            float2 ea0 = __ldg((const float2*)&eperm[(p+0)*2]);
            float2 ea1 = __ldg((const float2*)&eperm[(p+1)*2]);
            float2 ds0 = __ldg(&dis01[s0]);
            float2 ds1 = __ldg(&dis01[s1]);
            float4 xc0 = tc4[s0*32 + lane];
            float4 xo0 = to4[s0*32 + lane];
            float4 xc1 = tc4[s1*32 + lane];
            float4 xo1 = to4[s1*32 + lane];
            float wc0 = ds0.x * dv.x * ea0.x, wo0 = ds0.y * dv.y * ea0.y;
            float wc1 = ds1.x * dv.x * ea1.x, wo1 = ds1.y * dv.y * ea1.y;
            ac.x += wc0*xc0.x + wc1*xc1.x; ac.y += wc0*xc0.y + wc1*xc1.y;
            ac.z += wc0*xc0.z + wc1*xc1.z; ac.w += wc0*xc0.w + wc1*xc1.w;
            ao.x += wo0*xo0.x + wo1*xo1.x; ao.y += wo0*xo0.y + wo1*xo1.y;
            ao.z += wo0*xo0.z + wo1*xo1.z; ao.w += wo0*xo0.w + wo1*xo1.w;
        }
        for (; p < en; p++) {
            int s = __ldg(&csrc[p]);
            float2 ea = __ldg((const float2*)&eperm[p*2]);
            float2 ds = __ldg(&dis01[s]);
            float wc = ds.x * dv.x * ea.x;
            float wo = ds.y * dv.y * ea.y;
            float4 xc = tc4[s*32 + lane];
            float4 xo = to4[s*32 + lane];
            ac.x += wc*xc.x; ac.y += wc*xc.y; ac.z += wc*xc.z; ac.w += wc*xc.w;
            ao.x += wo*xo.x; ao.y += wo*xo.y; ao.z += wo*xo.z; ao.w += wo*xo.w;
        }
        float zc[4] = {ac.x+bc.x, ac.y+bc.y, ac.z+bc.z, ac.w+bc.w};
        float zo[4] = {ao.x+bo.x, ao.y+bo.y, ao.z+bo.z, ao.w+bo.w};
        #pragma unroll
        for (int j = 0; j < 4; j++) {
            zc[j] = (zc[j] > 0.f) ? zc[j] : expm1f(zc[j]);
            zo[j] = (zo[j] > 0.f) ? zo[j] : expm1f(zo[j]);
        }
        int g = __ldg(&batch[v]);
        float* pc = cat + g*256 + lane*4;
        float* po = pc + 128;
        asm volatile("red.global.add.v4.f32 [%0], {%1, %2, %3, %4};"
                     :: "l"(pc), "f"(zc[0]), "f"(zc[1]), "f"(zc[2]), "f"(zc[3]) : "memory");
        asm volatile("red.global.add.v4.f32 [%0], {%1, %2, %3, %4};"
                     :: "l"(po), "f"(zo[0]), "f"(zo[1]), "f"(zo[2]), "f"(zo[3]) : "memory");
    }
}

// ---------------- attention ----------------
__global__ void edge_att_kernel(const int* __restrict__ src, const int* __restrict__ dst,
                                const int* __restrict__ pos,
                                const float* __restrict__ epro, const float* __restrict__ eb,
                                float* __restrict__ eperm, float2* __restrict__ deg01, int E) {
    int e = blockIdx.x*blockDim.x + threadIdx.x;
    if (e >= E) return;
    int s = src[e], d = dst[e];
    float2 ps = *(const float2*)&epro[s*4];
    float2 qd = *(const float2*)&epro[d*4+2];
    float l0 = ps.x + qd.x + eb[0];
    float l1 = ps.y + qd.y + eb[1];
    float m = fmaxf(l0, l1);
    float e0 = expf(l0 - m), e1 = expf(l1 - m);
    float inv = 1.f/(e0+e1);
    float a0 = e0*inv, a1 = e1*inv;
    int p = pos[e];
    *(float2*)&eperm[p*2] = make_float2(a0, a1);
    asm volatile("red.global.add.v2.f32 [%0], {%1, %2};"
                 :: "l"(&deg01[s]), "f"(a0), "f"(a1) : "memory");
}

__global__ void natt_gather(const float* __restrict__ t2,
                            const int* __restrict__ rowptr, const int* __restrict__ csrc,
                            const float* __restrict__ disU,
                            const float* __restrict__ nab,
                            float* __restrict__ natt, int n) {
    int v = blockIdx.x*blockDim.x + threadIdx.x;
    if (v >= n) return;
    float dv = disU[v];
    float d2 = dv*dv;
    float a0 = t2[v*2+0]*d2, a1 = t2[v*2+1]*d2;
    int p = rowptr[v], en = rowptr[v+1];
    for (; p + 4 <= en; p += 4) {
        int s0 = __ldg(&csrc[p+0]);
        int s1 = __ldg(&csrc[p+1]);
        int s2 = __ldg(&csrc[p+2]);
        int s3 = __ldg(&csrc[p+3]);
        float w0 = __ldg(&disU[s0]);
        float w1 = __ldg(&disU[s1]);
        float w2 = __ldg(&disU[s2]);
        float w3 = __ldg(&disU[s3]);
        float2 x0 = __ldg((const float2*)&t2[s0*2]);
        float2 x1 = __ldg((const float2*)&t2[s1*2]);
        float2 x2 = __ldg((const float2*)&t2[s2*2]);
        float2 x3 = __ldg((const float2*)&t2[s3*2]);
        w0 *= dv; w1 *= dv; w2 *= dv; w3 *= dv;
        a0 += w0*x0.x + w1*x1.x + w2*x2.x + w3*x3.x;
        a1 += w0*x0.y + w1*x1.y + w2*x2.y + w3*x3.y;
    }
    for (; p < en; p++) {
        int s = __ldg(&csrc[p]);
        float w = __ldg(&disU[s])*dv;
        float2 ts = __ldg((const float2*)&t2[s*2]);
        a0 += w*ts.x;
        a1 += w*ts.y;
    }
    a0 += nab[0]; a1 += nab[1];
    float m = fmaxf(a0, a1);
    float e0 = expf(a0 - m), e1 = expf(a1 - m);
    float inv = 1.f/(e0+e1);
    natt[v*2+0] = e0*inv; natt[v*2+1] = e1*inv;
}

// ---------------- fused heads ----------------
__global__ void head_gemm1(const float* __restrict__ cat,
                           const float* __restrict__ mean, const float* __restrict__ rstd,
                           const float* __restrict__ cW1, const float* __restrict__ cb1,
                           const float* __restrict__ oW1, const float* __restrict__ ob1,
                           const float* __restrict__ coW1, const float* __restrict__ cob1,
                           float* __restrict__ hd) {
    __shared__ float a[256];
    int r = blockIdx.x, head = blockIdx.y;
    for (int k = threadIdx.x; k < 256; k += 128)
        a[k] = (cat[r*256 + k] - mean[k]) * rstd[k] + BNB;
    __syncthreads();
    const float* W; const float* b; int K, koff, act;
    if (head == 0)      { W = cW1;  b = cb1;  K = 128; koff = 0;   act = 1; }
    else if (head == 1) { W = oW1;  b = ob1;  K = 128; koff = 128; act = 1; }
    else                { W = coW1; b = cob1; K = 256; koff = 0;   act = 2; }
    int c = threadIdx.x;
    float acc = b[c];
    for (int k = 0; k < K; k++) acc += a[koff + k] * W[k*128 + c];
    if (act == 1) acc = fmaxf(acc, 0.f);
    else {
        acc = (acc > 0.f) ? acc : expm1f(acc);
        acc = (acc > 0.f) ? acc : expm1f(acc);
    }
    hd[(head*Gg + r)*128 + c] = acc;
}

__global__ void head_gemm2_lsm(const float* __restrict__ hd,
                               const float* __restrict__ mean, const float* __restrict__ rstd,
                               const float* __restrict__ cW2, const float* __restrict__ cb2,
                               const float* __restrict__ oW2, const float* __restrict__ ob2,
                               const float* __restrict__ coW2, const float* __restrict__ cob2,
                               float* __restrict__ out) {
    __shared__ float a[128];
    __shared__ float lg[COUT];
    int r = blockIdx.x, head = blockIdx.y;
    int k = threadIdx.x;
    a[k] = (hd[(head*Gg + r)*128 + k] - mean[head*128 + k]) * rstd[head*128 + k] + BNB;
    __syncthreads();
    const float* W = (head == 0) ? cW2 : (head == 1) ? oW2 : coW2;
    const float* b = (head == 0) ? cb2 : (head == 1) ? ob2 : cob2;
    if (k < COUT) {
        float acc = b[k];
        for (int kk = 0; kk < 128; kk++) acc += a[kk] * W[kk*COUT + k];
        lg[k] = acc;
    }
    __syncthreads();
    if (k < COUT) {
        float m = -1e30f;
        #pragma unroll
        for (int i = 0; i < COUT; i++) m = fmaxf(m, lg[i]);
        float s = 0.f;
        #pragma unroll
        for (int i = 0; i < COUT; i++) s += expf(lg[i] - m);
        out[head*Gg*COUT + r*COUT + k] = lg[k] - m - logf(s);
    }
}

// ---------------- host orchestration ----------------
extern "C" void kernel_launch(void* const* d_in, const int* in_sizes, int n_in,
                              void* d_out, int out_size) {
    const float* x      = (const float*)d_in[0];
    const float* W_feat = (const float*)d_in[1];
    const float* conv_Ws= (const float*)d_in[2];
    const float* conv_bs= (const float*)d_in[3];
    const float* eW     = (const float*)d_in[4];
    const float* eb     = (const float*)d_in[5];
    const float* naW    = (const float*)d_in[6];
    const float* nab    = (const float*)d_in[7];
    const float* xcW    = (const float*)d_in[8];
    const float* xcb    = (const float*)d_in[9];
    const float* xoW    = (const float*)d_in[10];
    const float* xob    = (const float*)d_in[11];
    const float* cW1    = (const float*)d_in[12];
    const float* cb1    = (const float*)d_in[13];
    const float* cW2    = (const float*)d_in[14];
    const float* cb2    = (const float*)d_in[15];
    const float* oW1    = (const float*)d_in[16];
    const float* ob1    = (const float*)d_in[17];
    const float* oW2    = (const float*)d_in[18];
    const float* ob2    = (const float*)d_in[19];
    const float* coW1   = (const float*)d_in[20];
    const float* cob1   = (const float*)d_in[21];
    const float* coW2   = (const float*)d_in[22];
    const float* cob2   = (const float*)d_in[23];
    const int* esrc     = (const int*)d_in[24];
    const int* edst     = (const int*)d_in[25];
    const int* batch    = (const int*)d_in[26];
    float* out = (float*)d_out;

    float *p_h,*p_t,*p_t2b,*p_stats,*p_mean,*p_rstd,*p_disU;
    float *p_epro,*p_t2,*p_natt,*p_eperm,*p_bias2,*p_cat,*p_hd;
    float2* p_deg01;
    int *p_cnt,*p_incl,*p_bsum,*p_rowptr,*p_cursor,*p_csrc,*p_pos;
    cudaGetSymbolAddress((void**)&p_h, g_h);
    cudaGetSymbolAddress((void**)&p_t, g_t);
    cudaGetSymbolAddress((void**)&p_t2b, g_t2b);
    cudaGetSymbolAddress((void**)&p_stats, g_stats);
    cudaGetSymbolAddress((void**)&p_mean, g_mean);
    cudaGetSymbolAddress((void**)&p_rstd, g_rstd);
    cudaGetSymbolAddress((void**)&p_disU, g_disU);
    cudaGetSymbolAddress((void**)&p_deg01, g_deg01);
    cudaGetSymbolAddress((void**)&p_epro, g_epro);
    cudaGetSymbolAddress((void**)&p_t2, g_t2);
    cudaGetSymbolAddress((void**)&p_natt, g_natt);
    cudaGetSymbolAddress((void**)&p_eperm, g_eperm);
    cudaGetSymbolAddress((void**)&p_bias2, g_bias2);
    cudaGetSymbolAddress((void**)&p_cat, g_cat);
    cudaGetSymbolAddress((void**)&p_hd, g_hd);
    cudaGetSymbolAddress((void**)&p_cnt, g_cnt);
    cudaGetSymbolAddress((void**)&p_incl, g_incl);
    cudaGetSymbolAddress((void**)&p_bsum, g_bsum);
    cudaGetSymbolAddress((void**)&p_rowptr, g_rowptr);
    cudaGetSymbolAddress((void**)&p_cursor, g_cursor);
    cudaGetSymbolAddress((void**)&p_csrc, g_csrc);
    cudaGetSymbolAddress((void**)&p_pos, g_pos);

    cudaFuncSetAttribute(gemm128, cudaFuncAttributeMaxDynamicSharedMemorySize, GEMM_SMEM);
    cudaFuncSetAttribute(gemm256, cudaFuncAttributeMaxDynamicSharedMemorySize, GEMM_SMEM);

    const int N = Nn, E = Ee, G = Gg;
    const int NB = (N + 63) / 64;
    const int NT = (N + 255) / 256;
    const int ET = (E + 255) / 256;
    const int GB = 1024;
    const int NSCAN = (N + 1023) / 1024;

    cudaStream_t sA;
    cudaStreamCreateWithFlags(&sA, cudaStreamNonBlocking);
    cudaEvent_t evF1, evJ1, evF2, evJ2;
    cudaEventCreateWithFlags(&evF1, cudaEventDisableTiming);
    cudaEventCreateWithFlags(&evJ1, cudaEventDisableTiming);
    cudaEventCreateWithFlags(&evF2, cudaEventDisableTiming);
    cudaEventCreateWithFlags(&evJ2, cudaEventDisableTiming);

    // ==== FORK 1: CSR build on sA ====
    cudaEventRecord(evF1, 0);
    cudaStreamWaitEvent(sA, evF1, 0);
    init_kernel<<<NT,256,0,sA>>>(p_disU, p_deg01, p_cnt, N);
    deg_hist<<<ET,256,0,sA>>>(esrc, edst, p_disU, p_cnt, E);
    scan_block<<<NSCAN,1024,0,sA>>>(p_cnt, p_incl, p_bsum, N);
    scan_tops<<<1,32,0,sA>>>(p_bsum, NSCAN);
    make_rowptr<<<NT,256,0,sA>>>(p_cnt, p_incl, p_bsum, p_rowptr, p_cursor, p_disU, N, E);
    fill_csr<<<ET,256,0,sA>>>(esrc, edst, p_cursor, p_csrc, p_pos, E);
    cudaEventRecord(evJ1, sA);

    // main chain: h = relu(BN(x) @ W_feat), stats fused; layer-0 GEMM
    colstats<<<512,256>>>(x, N, p_stats);
    finalize_stats<<<1,256>>>(p_stats, 128, 1.f/N, p_mean, p_rstd);
    gemm128<<<NB,256,GEMM_SMEM>>>(x, p_mean, p_rstd, W_feat, p_h, p_stats, N, 1);
    finalize_stats<<<1,256>>>(p_stats, 128, 1.f/N, p_mean, p_rstd);
    gemm128<<<NB,256,GEMM_SMEM>>>(p_h, p_mean, p_rstd, conv_Ws, p_t, nullptr, N, 0);

    // JOIN 1 (gather needs CSR + disU)
    cudaStreamWaitEvent(0, evJ1, 0);

    // ---- GCN layers ----
    gather128<<<GB,256>>>(p_t, p_rowptr, p_csrc, p_disU, conv_bs, p_h, p_stats,
                          nullptr, nullptr, nullptr, nullptr, N, 1);
    finalize_stats<<<1,256>>>(p_stats, 128, 1.f/N, p_mean, p_rstd);
    for (int l = 1; l < 3; l++) {
        gemm128<<<NB,256,GEMM_SMEM>>>(p_h, p_mean, p_rstd,
                                      conv_Ws + l*128*128, p_t, nullptr, N, 0);
        if (l < 2) {
            gather128<<<GB,256>>>(p_t, p_rowptr, p_csrc, p_disU,
                                  conv_bs + l*128, p_h, p_stats,
                                  nullptr, nullptr, nullptr, nullptr, N, 1);
            finalize_stats<<<1,256>>>(p_stats, 128, 1.f/N, p_mean, p_rstd);
        } else {
            gather128<<<GB,256>>>(p_t, p_rowptr, p_csrc, p_disU,
                                  conv_bs + l*128, p_h, nullptr,
                                  eW, naW, p_epro, p_t2, N, 1);
        }
    }

    // ==== FORK 2: edge attention on sA ====
    cudaEventRecord(evF2, 0);
    cudaStreamWaitEvent(sA, evF2, 0);
    edge_att_kernel<<<ET,256,0,sA>>>(esrc, edst, p_pos, p_epro, eb, p_eperm, p_deg01, E);
    rsqrt_arr<<<(2*N+255)/256,256,0,sA>>>((float*)p_deg01, 2*N);
    cudaMemsetAsync(p_cat, 0, Gg*256*sizeof(float), sA);
    cudaEventRecord(evJ2, sA);

    // main: node attention + XC/XO stats + merged GEMM
    natt_gather<<<NT,256>>>(p_t2, p_rowptr, p_csrc, p_disU, nab, p_natt, N);
    colstats2<<<512,256>>>(p_h, p_natt, N, p_stats);
    finalize2<<<1,256>>>(p_stats, 1.f/N, p_mean, p_rstd);
    bias_kernel<<<2,128>>>(p_mean, p_rstd, xcW, xoW, p_bias2);
    gemm256<<<NB,256,GEMM_SMEM>>>(p_h, p_natt, p_rstd, xcW, xoW, p_bias2,
                                  p_t, p_t2b, N);

    // JOIN 2 (gather2 needs eperm + deg01 + zeroed cat)
    cudaStreamWaitEvent(0, evJ2, 0);
    gather2<<<GB,256>>>(p_t, p_t2b, p_rowptr, p_csrc, p_deg01, p_eperm,
                        xcb, xob, batch, p_cat, N);

    // ---- heads ----
    head_stats<<<256,128>>>(p_cat, 256, G, p_mean, p_rstd);
    dim3 hg1(G, 3);
    head_gemm1<<<hg1,128>>>(p_cat, p_mean, p_rstd, cW1, cb1, oW1, ob1,
                            coW1, cob1, p_hd);
    head_stats3<<<384,128>>>(p_hd, G, p_mean, p_rstd);
    dim3 hg2(G, 3);
    head_gemm2_lsm<<<hg2,128>>>(p_hd, p_mean, p_rstd, cW2, cb2, oW2, ob2,
                                coW2, cob2, out);

    cudaEventDestroy(evF1);
    cudaEventDestroy(evJ1);
    cudaEventDestroy(evF2);
    cudaEventDestroy(evJ2);
    cudaStreamDestroy(sA);
}

// round 14
// speedup vs baseline: 1.0928x; 1.0665x over previous
#include <cuda_runtime.h>
#include <math.h>

#define Nn 50000
#define Ee 400000
#define Hh 128
#define Gg 512
#define COUT 10

typedef unsigned long long u64;

static constexpr float EPSBN = 1e-5f;
static constexpr float BNB   = 1e-4f;

// ---------------- scratch (static device allocations) ----------------
__device__ float g_h[Nn*Hh];
__device__ float g_t[Nn*Hh];
__device__ float g_t2b[Nn*Hh];
__device__ float g_stats[512];      // zero-init; every consumer re-zeroes
__device__ float g_mean[512];
__device__ float g_rstd[512];
__device__ float g_disU[Nn];
__device__ float2 g_deg01[Nn];
__device__ float g_epro[Nn*4];
__device__ float g_t2[Nn*2];        // disU-scaled naW projections
__device__ float g_natt[Nn*2];
__device__ float g_eperm[Ee*2];
__device__ float g_bias2[256];
__device__ float g_cat[Gg*256];
__device__ float g_hd[3*Gg*128];
// CSR by destination
__device__ int g_cnt[Nn];
__device__ int g_incl[Nn];
__device__ int g_bsum[64];
__device__ int g_rowptr[Nn+1];
__device__ int g_cursor[Nn];
__device__ int g_csrc[Ee];
__device__ int g_pos[Ee];

// ---------------- small utility kernels ----------------
__global__ void init_kernel(float* disU, float2* deg01, int* cnt, int n) {
    int i = blockIdx.x*blockDim.x + threadIdx.x;
    if (i < n) { disU[i] = 1.f; deg01[i] = make_float2(1.f, 1.f); cnt[i] = 0; }
}

__global__ void deg_hist(const int* __restrict__ src, const int* __restrict__ dst,
                         float* degU, int* cnt, int E) {
    int i = blockIdx.x*blockDim.x + threadIdx.x;
    if (i < E) {
        atomicAdd(&degU[src[i]], 1.0f);
        atomicAdd(&cnt[dst[i]], 1);
    }
}

__global__ void rsqrt_arr(float* p, int n) {
    int i = blockIdx.x*blockDim.x + threadIdx.x;
    if (i < n) p[i] = rsqrtf(p[i]);
}

// ---------------- CSR build ----------------
__global__ void scan_block(const int* __restrict__ cnt, int* incl, int* bsum, int n) {
    __shared__ int sm[1024];
    int i = blockIdx.x*1024 + threadIdx.x;
    sm[threadIdx.x] = (i < n) ? cnt[i] : 0;
    __syncthreads();
    for (int off = 1; off < 1024; off <<= 1) {
        int t = (threadIdx.x >= off) ? sm[threadIdx.x - off] : 0;
        __syncthreads();
        sm[threadIdx.x] += t;
        __syncthreads();
    }
    if (i < n) incl[i] = sm[threadIdx.x];
    if (threadIdx.x == 1023) bsum[blockIdx.x] = sm[1023];
}

__global__ void scan_tops(int* bsum, int nb) {
    int lane = threadIdx.x;
    int v0 = (lane < nb) ? bsum[lane] : 0;
    int v1 = (32 + lane < nb) ? bsum[32 + lane] : 0;
    #pragma unroll
    for (int o = 1; o < 32; o <<= 1) {
        int t = __shfl_up_sync(0xffffffffu, v0, o);
        if (lane >= o) v0 += t;
    }
    int tot0 = __shfl_sync(0xffffffffu, v0, 31);
    #pragma unroll
    for (int o = 1; o < 32; o <<= 1) {
        int t = __shfl_up_sync(0xffffffffu, v1, o);
        if (lane >= o) v1 += t;
    }
    v1 += tot0;
    if (lane < nb) bsum[lane] = v0;
    if (32 + lane < nb) bsum[32 + lane] = v1;
}

__global__ void make_rowptr(const int* __restrict__ cnt, const int* __restrict__ incl,
                            const int* __restrict__ bsum,
                            int* rowptr, int* cursor, float* disU, int n, int E) {
    int i = blockIdx.x*blockDim.x + threadIdx.x;
    if (i < n) {
        int b = i >> 10;
        int ex = incl[i] - cnt[i] + ((b > 0) ? bsum[b-1] : 0);
        rowptr[i] = ex;
        cursor[i] = ex;
        disU[i] = rsqrtf(disU[i]);
    }
    if (i == 0) rowptr[n] = E;
}

__global__ void fill_csr(const int* __restrict__ src, const int* __restrict__ dst,
                         int* cursor, int* csrc, int* pos, int E) {
    int e = blockIdx.x*blockDim.x + threadIdx.x;
    if (e < E) {
        int p = atomicAdd(&cursor[dst[e]], 1);
        csrc[p] = src[e];
        pos[e] = p;
    }
}

// ---------------- BatchNorm stats ----------------
__global__ void colstats(const float* __restrict__ A, int n, float* sums) {
    long total  = (long)n * 128;
    long stride = (long)gridDim.x * blockDim.x;
    long i0     = (long)blockIdx.x*blockDim.x + threadIdx.x;
    if (i0 >= total) return;
    int c = (int)(i0 % 128);
    float s0 = 0.f, s1 = 0.f;
    for (long i = i0; i < total; i += stride) {
        int r = (int)(i / 128);
        float v = A[(long)r*128 + c];
        s0 += v; s1 += v*v;
    }
    atomicAdd(&sums[c], s0);
    atomicAdd(&sums[128+c], s1);
}

__global__ void colstats2(const float* __restrict__ A, const float* __restrict__ natt,
                          int n, float* sums) {
    long total  = (long)n * 128;
    long stride = (long)gridDim.x * blockDim.x;
    long i0     = (long)blockIdx.x*blockDim.x + threadIdx.x;
    if (i0 >= total) return;
    int c = (int)(i0 % 128);
    float s00=0.f, s01=0.f, s10=0.f, s11=0.f;
    for (long i = i0; i < total; i += stride) {
        int r = (int)(i / 128);
        float v = A[(long)r*128 + c];
        float v0 = v * natt[r*2+0];
        float v1 = v * natt[r*2+1];
        s00 += v0; s01 += v0*v0;
        s10 += v1; s11 += v1*v1;
    }
    atomicAdd(&sums[c], s00);
    atomicAdd(&sums[128+c], s01);
    atomicAdd(&sums[256+c], s10);
    atomicAdd(&sums[384+c], s11);
}

__global__ void finalize_stats(float* sums, int C, float inv_n,
                               float* mean, float* rstd) {
    int c = threadIdx.x + blockIdx.x*blockDim.x;
    if (c < C) {
        float s0 = sums[c], s1 = sums[C+c];
        sums[c] = 0.f; sums[C+c] = 0.f;
        float m = s0*inv_n;
        float var = s1*inv_n - m*m;
        mean[c] = m;
        rstd[c] = rsqrtf(var + EPSBN);
    }
}

__global__ void finalize2(float* sums, float inv_n, float* mean, float* rstd) {
    int c = threadIdx.x;               // 0..255
    int ch = c >> 7, cc = c & 127;
    float s0 = sums[ch*256 + cc], s1 = sums[ch*256 + 128 + cc];
    sums[ch*256 + cc] = 0.f; sums[ch*256 + 128 + cc] = 0.f;
    float m = s0*inv_n;
    float var = s1*inv_n - m*m;
    mean[c] = m;
    rstd[c] = rsqrtf(var + EPSBN);
}

__global__ void head_stats(const float* __restrict__ A, int lda, int n,
                           float* mean, float* rstd) {
    __shared__ float s0s[4], s1s[4];
    int c = blockIdx.x;
    int lane = threadIdx.x & 31, warp = threadIdx.x >> 5;
    float s0 = 0.f, s1 = 0.f;
    for (int r = threadIdx.x; r < n; r += blockDim.x) {
        float v = A[r*lda + c];
        s0 += v; s1 += v*v;
    }
    #pragma unroll
    for (int o = 16; o; o >>= 1) {
        s0 += __shfl_xor_sync(0xffffffffu, s0, o);
        s1 += __shfl_xor_sync(0xffffffffu, s1, o);
    }
    if (lane == 0) { s0s[warp] = s0; s1s[warp] = s1; }
    __syncthreads();
    if (threadIdx.x == 0) {
        float t0 = 0.f, t1 = 0.f;
        for (int w = 0; w < 4; w++) { t0 += s0s[w]; t1 += s1s[w]; }
        float m = t0 / n;
        float var = t1 / n - m*m;
        mean[c] = m;
        rstd[c] = rsqrtf(var + EPSBN);
    }
}

__global__ void head_stats3(const float* __restrict__ hd, int n,
                            float* mean, float* rstd) {
    __shared__ float s0s[4], s1s[4];
    int cg = blockIdx.x;
    int head = cg >> 7, c = cg & 127;
    const float* A = hd + head*Gg*128;
    int lane = threadIdx.x & 31, warp = threadIdx.x >> 5;
    float s0 = 0.f, s1 = 0.f;
    for (int r = threadIdx.x; r < n; r += blockDim.x) {
        float v = A[r*128 + c];
        s0 += v; s1 += v*v;
    }
    #pragma unroll
    for (int o = 16; o; o >>= 1) {
        s0 += __shfl_xor_sync(0xffffffffu, s0, o);
        s1 += __shfl_xor_sync(0xffffffffu, s1, o);
    }
    if (lane == 0) { s0s[warp] = s0; s1s[warp] = s1; }
    __syncthreads();
    if (threadIdx.x == 0) {
        float t0 = 0.f, t1 = 0.f;
        for (int w = 0; w < 4; w++) { t0 += s0s[w]; t1 += s1s[w]; }
        float m = t0 / n;
        float var = t1 / n - m*m;
        mean[cg] = m;
        rstd[cg] = rsqrtf(var + EPSBN);
    }
}

__global__ void bias_kernel(const float* __restrict__ mean, const float* __restrict__ rstd,
                            const float* __restrict__ xcW, const float* __restrict__ xoW,
                            float* __restrict__ bias2) {
    __shared__ float coef[128];
    int hh = blockIdx.x;
    int j = threadIdx.x;
    const float* W = hh ? xoW : xcW;
    coef[j] = BNB - mean[hh*128+j]*rstd[hh*128+j];
    __syncthreads();
    float acc = 0.f;
    for (int k = 0; k < 128; k++) acc += coef[k]*W[k*128+j];
    bias2[hh*128+j] = acc;
}

// ---------------- big GEMM (packed f32x2 FMA, BM=64, K-chunked W, 3 CTAs/SM) ----------------
// optional rowscale: out rows multiplied by rowscale[row] (degree pre-scaling)
static constexpr int GEMM_SMEM = (64*128 + 64*128) * 4;   // 64 KB

__global__ __launch_bounds__(256, 3) void gemm128(
    const float* __restrict__ A,
    const float* __restrict__ mean, const float* __restrict__ rstd,
    const float* __restrict__ W,
    float* __restrict__ out,
    float* __restrict__ sums,
    const float* __restrict__ rowscale,
    int n, int act)
{
    extern __shared__ float sm[];
    float* As = sm;               // [64][128]
    float* Ws = sm + 64*128;      // [64][128] W chunk
    int tid  = threadIdx.x;
    int row0 = blockIdx.x * 64;

    #pragma unroll 2
    for (int i = tid; i < 64*32; i += 256) {
        int r = i >> 5, cq = i & 31;
        int gr = row0 + r;
        float4 v = make_float4(0.f,0.f,0.f,0.f);
        if (gr < n) {
            v = ((const float4*)A)[gr*32 + cq];
            int c = cq*4;
            v.x = (v.x - mean[c+0])*rstd[c+0] + BNB;
            v.y = (v.y - mean[c+1])*rstd[c+1] + BNB;
            v.z = (v.z - mean[c+2])*rstd[c+2] + BNB;
            v.w = (v.w - mean[c+3])*rstd[c+3] + BNB;
        }
        ((float4*)As)[i] = v;
    }

    int tc = tid & 15, tr = tid >> 4;
    int r0 = tr*4;
    int c0 = tc*4, c1 = 64 + tc*4;

    u64 accp[4][4];
    #pragma unroll
    for (int i = 0; i < 4; i++)
        #pragma unroll
        for (int j = 0; j < 4; j++) accp[i][j] = 0ull;

    const float4* Wg = (const float4*)W;
    float4* Ws4 = (float4*)Ws;

    #pragma unroll
    for (int kc = 0; kc < 128; kc += 64) {
        __syncthreads();
        #pragma unroll 2
        for (int i = tid; i < 64*32; i += 256)
            Ws4[i] = Wg[(kc + (i >> 5))*32 + (i & 31)];
        __syncthreads();

        for (int k = 0; k < 64; k += 4) {
            float4 a4[4];
            #pragma unroll
            for (int i = 0; i < 4; i++)
                a4[i] = *(const float4*)&As[(r0+i)*128 + kc + k];
            #pragma unroll
            for (int kk = 0; kk < 4; kk++) {
                ulonglong2 w01 = *(const ulonglong2*)&Ws[(k+kk)*128 + c0];
                ulonglong2 w23 = *(const ulonglong2*)&Ws[(k+kk)*128 + c1];
                u64 wp0 = w01.x, wp1 = w01.y, wp2 = w23.x, wp3 = w23.y;
                #pragma unroll
                for (int i = 0; i < 4; i++) {
                    float a = ((const float*)&a4[i])[kk];
                    unsigned int ai = __float_as_uint(a);
                    u64 ap;
                    asm("mov.b64 %0, {%1, %1};" : "=l"(ap) : "r"(ai));
                    asm("fma.rn.f32x2 %0, %1, %2, %0;" : "+l"(accp[i][0]) : "l"(ap), "l"(wp0));
                    asm("fma.rn.f32x2 %0, %1, %2, %0;" : "+l"(accp[i][1]) : "l"(ap), "l"(wp1));
                    asm("fma.rn.f32x2 %0, %1, %2, %0;" : "+l"(accp[i][2]) : "l"(ap), "l"(wp2));
                    asm("fma.rn.f32x2 %0, %1, %2, %0;" : "+l"(accp[i][3]) : "l"(ap), "l"(wp3));
                }
            }
        }
    }

    float t0[8], t1[8];
    #pragma unroll
    for (int j = 0; j < 8; j++) { t0[j] = 0.f; t1[j] = 0.f; }

    float4* O4 = (float4*)out;
    #pragma unroll
    for (int i = 0; i < 4; i++) {
        int gr = row0 + r0 + i;
        if (gr < n) {
            float o[8];
            #pragma unroll
            for (int j = 0; j < 4; j++) {
                unsigned int lo, hi;
                asm("mov.b64 {%0, %1}, %2;" : "=r"(lo), "=r"(hi) : "l"(accp[i][j]));
                o[2*j]   = __uint_as_float(lo);
                o[2*j+1] = __uint_as_float(hi);
            }
            if (act == 1) {
                #pragma unroll
                for (int j = 0; j < 8; j++) o[j] = fmaxf(o[j], 0.f);
            }
            if (rowscale) {
                float rs = rowscale[gr];
                #pragma unroll
                for (int j = 0; j < 8; j++) o[j] *= rs;
            }
            if (sums) {
                #pragma unroll
                for (int j = 0; j < 8; j++) { t0[j] += o[j]; t1[j] += o[j]*o[j]; }
            }
            O4[gr*32 + tc]      = make_float4(o[0], o[1], o[2], o[3]);
            O4[gr*32 + 16 + tc] = make_float4(o[4], o[5], o[6], o[7]);
        }
    }

    if (sums) {
        __syncthreads();
        float* ss = sm;
        ss[tid] = 0.f;
        __syncthreads();
        #pragma unroll
        for (int j = 0; j < 4; j++) {
            atomicAdd(&ss[c0+j],     t0[j]);   atomicAdd(&ss[128+c0+j], t1[j]);
            atomicAdd(&ss[c1+j],     t0[4+j]); atomicAdd(&ss[128+c1+j], t1[4+j]);
        }
        __syncthreads();
        atomicAdd(&sums[tid], ss[tid]);
    }
}

// ---------------- merged XC/XO GEMM (K-chunked, rows pre-scaled by deg01) ----------------
__global__ __launch_bounds__(256, 3) void gemm256(
    const float* __restrict__ h,
    const float* __restrict__ natt,
    const float* __restrict__ rstd2,
    const float* __restrict__ xcW, const float* __restrict__ xoW,
    const float* __restrict__ bias2,
    const float2* __restrict__ deg01,
    float* __restrict__ outc, float* __restrict__ outo, int n)
{
    extern __shared__ float sm[];
    float* As = sm;               // [64][128]
    float* Ws = sm + 64*128;      // [64][128] chunk
    int tid  = threadIdx.x;
    int row0 = blockIdx.x * 64;

    #pragma unroll 2
    for (int i = tid; i < 64*32; i += 256) {
        int r = i >> 5, cq = i & 31;
        int gr = row0 + r;
        float4 v = (gr < n) ? ((const float4*)h)[gr*32 + cq]
                            : make_float4(0.f,0.f,0.f,0.f);
        ((float4*)As)[i] = v;
    }

    int tc = tid & 15, tr = tid >> 4;
    int r0 = tr*4;
    int c0 = tc*4, c1 = 64 + tc*4;

    #pragma unroll
    for (int half = 0; half < 2; half++) {
        const float* W  = half ? xoW : xcW;
        const float* rs = rstd2 + half*128;
        const float* bs = bias2 + half*128;
        float* out = half ? outo : outc;

        float nv[4], dsc[4];
        #pragma unroll
        for (int i = 0; i < 4; i++) {
            int gr = row0 + r0 + i;
            nv[i] = (gr < n) ? natt[gr*2 + half] : 0.f;
            float2 d = (gr < n) ? deg01[gr] : make_float2(0.f, 0.f);
            dsc[i] = half ? d.y : d.x;
        }

        u64 accp[4][4];
        #pragma unroll
        for (int i = 0; i < 4; i++)
            #pragma unroll
            for (int j = 0; j < 4; j++) accp[i][j] = 0ull;

        #pragma unroll
        for (int kc = 0; kc < 128; kc += 64) {
            __syncthreads();
            #pragma unroll 2
            for (int i = tid; i < 64*32; i += 256) {
                int r = kc + (i >> 5);
                float4 w = ((const float4*)W)[r*32 + (i & 31)];
                float sc = rs[r];
                w.x *= sc; w.y *= sc; w.z *= sc; w.w *= sc;
                ((float4*)Ws)[i] = w;
            }
            __syncthreads();

            for (int k = 0; k < 64; k += 4) {
                float4 a4[4];
                #pragma unroll
                for (int i = 0; i < 4; i++)
                    a4[i] = *(const float4*)&As[(r0+i)*128 + kc + k];
                #pragma unroll
                for (int kk = 0; kk < 4; kk++) {
                    ulonglong2 w01 = *(const ulonglong2*)&Ws[(k+kk)*128 + c0];
                    ulonglong2 w23 = *(const ulonglong2*)&Ws[(k+kk)*128 + c1];
                    u64 wp0 = w01.x, wp1 = w01.y, wp2 = w23.x, wp3 = w23.y;
                    #pragma unroll
                    for (int i = 0; i < 4; i++) {
                        float a = ((const float*)&a4[i])[kk] * nv[i];
                        unsigned int ai = __float_as_uint(a);
                        u64 ap;
                        asm("mov.b64 %0, {%1, %1};" : "=l"(ap) : "r"(ai));
                        asm("fma.rn.f32x2 %0, %1, %2, %0;" : "+l"(accp[i][0]) : "l"(ap), "l"(wp0));
                        asm("fma.rn.f32x2 %0, %1, %2, %0;" : "+l"(accp[i][1]) : "l"(ap), "l"(wp1));
                        asm("fma.rn.f32x2 %0, %1, %2, %0;" : "+l"(accp[i][2]) : "l"(ap), "l"(wp2));
                        asm("fma.rn.f32x2 %0, %1, %2, %0;" : "+l"(accp[i][3]) : "l"(ap), "l"(wp3));
                    }
                }
            }
        }

        float4 b0 = *(const float4*)&bs[c0];
        float4 b1 = *(const float4*)&bs[c1];
        float4* O4 = (float4*)out;
        #pragma unroll
        for (int i = 0; i < 4; i++) {
            int gr = row0 + r0 + i;
            if (gr < n) {
                float o[8];
                #pragma unroll
                for (int j = 0; j < 4; j++) {
                    unsigned int lo, hi;
                    asm("mov.b64 {%0, %1}, %2;" : "=r"(lo), "=r"(hi) : "l"(accp[i][j]));
                    o[2*j]   = __uint_as_float(lo);
                    o[2*j+1] = __uint_as_float(hi);
                }
                float d = dsc[i];
                O4[gr*32 + tc]      = make_float4((o[0]+b0.x)*d, (o[1]+b0.y)*d,
                                                  (o[2]+b0.z)*d, (o[3]+b0.w)*d);
                O4[gr*32 + 16 + tc] = make_float4((o[4]+b1.x)*d, (o[5]+b1.y)*d,
                                                  (o[6]+b1.z)*d, (o[7]+b1.w)*d);
            }
        }
    }
}

// ---------------- CSR gather conv (rows pre-scaled: pure row-add loop) ----------------
__global__ __launch_bounds__(256) void gather128(
    const float* __restrict__ t,           // t' = dis-scaled rows
    const int* __restrict__ rowptr, const int* __restrict__ csrc,
    const float* __restrict__ dis,
    const float* __restrict__ bias,
    float* __restrict__ out, float* __restrict__ sums,
    const float* __restrict__ eWg, const float* __restrict__ naWg,
    float* __restrict__ epro, float* __restrict__ t2,
    int n, int act)
{
    __shared__ float sEW[512];
    __shared__ float sNA[256];
    if (eWg) {
        for (int i = threadIdx.x; i < 512; i += 256) sEW[i] = eWg[i];
        for (int i = threadIdx.x; i < 256; i += 256) sNA[i] = naWg[i];
        __syncthreads();
    }
    int lane = threadIdx.x & 31;
    int w0 = (blockIdx.x*blockDim.x + threadIdx.x) >> 5;
    int nw = (gridDim.x*blockDim.x) >> 5;
    float4 bb = bias ? ((const float4*)bias)[lane] : make_float4(0.f,0.f,0.f,0.f);
    float ls0[4] = {0.f,0.f,0.f,0.f}, ls1[4] = {0.f,0.f,0.f,0.f};
    const float4* t4 = (const float4*)t;

    for (int v = w0; v < n; v += nw) {
        float dv = dis[v];
        float4 acc = t4[v*32 + lane];       // self term t'[v]
        int p = rowptr[v], en = rowptr[v+1];
        for (; p + 4 <= en; p += 4) {
            int s0 = __ldg(&csrc[p+0]);
            int s1 = __ldg(&csrc[p+1]);
            int s2 = __ldg(&csrc[p+2]);
            int s3 = __ldg(&csrc[p+3]);
            float4 x0 = t4[s0*32 + lane];
            float4 x1 = t4[s1*32 + lane];
            float4 x2 = t4[s2*32 + lane];
            float4 x3 = t4[s3*32 + lane];
            acc.x += x0.x + x1.x + x2.x + x3.x;
            acc.y += x0.y + x1.y + x2.y + x3.y;
            acc.z += x0.z + x1.z + x2.z + x3.z;
            acc.w += x0.w + x1.w + x2.w + x3.w;
        }
        for (; p < en; p++) {
            int s = __ldg(&csrc[p]);
            float4 x = t4[s*32 + lane];
            acc.x += x.x; acc.y += x.y; acc.z += x.z; acc.w += x.w;
        }
        // final dis[v] scale, bias, act
        acc.x = acc.x*dv + bb.x; acc.y = acc.y*dv + bb.y;
        acc.z = acc.z*dv + bb.z; acc.w = acc.w*dv + bb.w;
        if (act == 1) {
            acc.x = fmaxf(acc.x, 0.f); acc.y = fmaxf(acc.y, 0.f);
            acc.z = fmaxf(acc.z, 0.f); acc.w = fmaxf(acc.w, 0.f);
        }
        if (sums) {
            ls0[0]+=acc.x; ls1[0]+=acc.x*acc.x;
            ls0[1]+=acc.y; ls1[1]+=acc.y*acc.y;
            ls0[2]+=acc.z; ls1[2]+=acc.z*acc.z;
            ls0[3]+=acc.w; ls1[3]+=acc.w*acc.w;
        }
        ((float4*)out)[v*32 + lane] = acc;

        if (eWg) {
            float hx[4] = {acc.x, acc.y, acc.z, acc.w};
            float p0=0,p1=0,q0=0,q1=0,u0=0,u1=0;
            #pragma unroll
            for (int i = 0; i < 4; i++) {
                int k = lane*4 + i; float xv = hx[i];
                p0 += xv*sEW[k*2+0];        p1 += xv*sEW[k*2+1];
                q0 += xv*sEW[(128+k)*2+0];  q1 += xv*sEW[(128+k)*2+1];
                u0 += xv*sNA[k*2+0];        u1 += xv*sNA[k*2+1];
            }
            #pragma unroll
            for (int o = 16; o; o >>= 1) {
                p0 += __shfl_xor_sync(0xffffffffu, p0, o);
                p1 += __shfl_xor_sync(0xffffffffu, p1, o);
                q0 += __shfl_xor_sync(0xffffffffu, q0, o);
                q1 += __shfl_xor_sync(0xffffffffu, q1, o);
                u0 += __shfl_xor_sync(0xffffffffu, u0, o);
                u1 += __shfl_xor_sync(0xffffffffu, u1, o);
            }
            if (lane == 0) {
                epro[v*4+0]=p0; epro[v*4+1]=p1; epro[v*4+2]=q0; epro[v*4+3]=q1;
                // naW projections stored pre-scaled by disU[v]
                t2[v*2+0]=u0*dv; t2[v*2+1]=u1*dv;
            }
        }
    }

    if (sums) {
        __shared__ float ss[256];
        ss[threadIdx.x] = 0.f;
        __syncthreads();
        #pragma unroll
        for (int j = 0; j < 4; j++) {
            atomicAdd(&ss[lane*4+j],     ls0[j]);
            atomicAdd(&ss[128+lane*4+j], ls1[j]);
        }
        __syncthreads();
        atomicAdd(&sums[threadIdx.x], ss[threadIdx.x]);
    }
}

// fused XC+XO gather + conv-bias + ELU + pool (rows pre-scaled by deg01)
__global__ __launch_bounds__(256) void gather2(
    const float* __restrict__ tc_, const float* __restrict__ to_,
    const int* __restrict__ rowptr, const int* __restrict__ csrc,
    const float2* __restrict__ dis01,
    const float* __restrict__ eperm,
    const float* __restrict__ xcb, const float* __restrict__ xob,
    const int* __restrict__ batch,
    float* __restrict__ cat, int n)
{
    int lane = threadIdx.x & 31;
    int w0 = (blockIdx.x*blockDim.x + threadIdx.x) >> 5;
    int nw = (gridDim.x*blockDim.x) >> 5;
    const float4* tc4 = (const float4*)tc_;
    const float4* to4 = (const float4*)to_;
    float4 bc = ((const float4*)xcb)[lane];
    float4 bo = ((const float4*)xob)[lane];

    for (int v = w0; v < n; v += nw) {
        float2 dv = dis01[v];
        float4 ac = tc4[v*32 + lane];   // self term t'_c[v]
        float4 ao = to4[v*32 + lane];
        int p = rowptr[v], en = rowptr[v+1];
        for (; p + 2 <= en; p += 2) {
            int s0 = __ldg(&csrc[p+0]);
            int s1 = __ldg(&csrc[p+1]);
            float2 ea0 = __ldg((const float2*)&eperm[(p+0)*2]);
            float2 ea1 = __ldg((const float2*)&eperm[(p+1)*2]);
            float4 xc0 = tc4[s0*32 + lane];
            float4 xo0 = to4[s0*32 + lane];
            float4 xc1 = tc4[s1*32 + lane];
            float4 xo1 = to4[s1*32 + lane];
            ac.x += ea0.x*xc0.x + ea1.x*xc1.x; ac.y += ea0.x*xc0.y + ea1.x*xc1.y;
            ac.z += ea0.x*xc0.z + ea1.x*xc1.z; ac.w += ea0.x*xc0.w + ea1.x*xc1.w;
            ao.x += ea0.y*xo0.x + ea1.y*xo1.x; ao.y += ea0.y*xo0.y + ea1.y*xo1.y;
            ao.z += ea0.y*xo0.z + ea1.y*xo1.z; ao.w += ea0.y*xo0.w + ea1.y*xo1.w;
        }
        for (; p < en; p++) {
            int s = __ldg(&csrc[p]);
            float2 ea = __ldg((const float2*)&eperm[p*2]);
            float4 xc = tc4[s*32 + lane];
            float4 xo = to4[s*32 + lane];
            ac.x += ea.x*xc.x; ac.y += ea.x*xc.y; ac.z += ea.x*xc.z; ac.w += ea.x*xc.w;
            ao.x += ea.y*xo.x; ao.y += ea.y*xo.y; ao.z += ea.y*xo.z; ao.w += ea.y*xo.w;
        }
        float zc[4] = {ac.x*dv.x+bc.x, ac.y*dv.x+bc.y, ac.z*dv.x+bc.z, ac.w*dv.x+bc.w};
        float zo[4] = {ao.x*dv.y+bo.x, ao.y*dv.y+bo.y, ao.z*dv.y+bo.z, ao.w*dv.y+bo.w};
        #pragma unroll
        for (int j = 0; j < 4; j++) {
            zc[j] = (zc[j] > 0.f) ? zc[j] : expm1f(zc[j]);
            zo[j] = (zo[j] > 0.f) ? zo[j] : expm1f(zo[j]);
        }
        int g = __ldg(&batch[v]);
        float* pc = cat + g*256 + lane*4;
        float* po = pc + 128;
        asm volatile("red.global.add.v4.f32 [%0], {%1, %2, %3, %4};"
                     :: "l"(pc), "f"(zc[0]), "f"(zc[1]), "f"(zc[2]), "f"(zc[3]) : "memory");
        asm volatile("red.global.add.v4.f32 [%0], {%1, %2, %3, %4};"
                     :: "l"(po), "f"(zo[0]), "f"(zo[1]), "f"(zo[2]), "f"(zo[3]) : "memory");
    }
}

// ---------------- attention ----------------
__global__ void edge_att_kernel(const int* __restrict__ src, const int* __restrict__ dst,
                                const int* __restrict__ pos,
                                const float* __restrict__ epro, const float* __restrict__ eb,
                                float* __restrict__ eperm, float2* __restrict__ deg01, int E) {
    int e = blockIdx.x*blockDim.x + threadIdx.x;
    if (e >= E) return;
    int s = src[e], d = dst[e];
    float2 ps = *(const float2*)&epro[s*4];
    float2 qd = *(const float2*)&epro[d*4+2];
    float l0 = ps.x + qd.x + eb[0];
    float l1 = ps.y + qd.y + eb[1];
    float m = fmaxf(l0, l1);
    float e0 = expf(l0 - m), e1 = expf(l1 - m);
    float inv = 1.f/(e0+e1);
    float a0 = e0*inv, a1 = e1*inv;
    int p = pos[e];
    *(float2*)&eperm[p*2] = make_float2(a0, a1);
    asm volatile("red.global.add.v2.f32 [%0], {%1, %2};"
                 :: "l"(&deg01[s]), "f"(a0), "f"(a1) : "memory");
}

// t2 rows are pre-scaled by disU; logits = dv*(t2'[v] + sum t2'[s]) + nab
__global__ void natt_gather(const float* __restrict__ t2,
                            const int* __restrict__ rowptr, const int* __restrict__ csrc,
                            const float* __restrict__ disU,
                            const float* __restrict__ nab,
                            float* __restrict__ natt, int n) {
    int v = blockIdx.x*blockDim.x + threadIdx.x;
    if (v >= n) return;
    float dv = disU[v];
    float2 selfv = __ldg((const float2*)&t2[v*2]);
    float a0 = selfv.x, a1 = selfv.y;
    int p = rowptr[v], en = rowptr[v+1];
    for (; p + 4 <= en; p += 4) {
        int s0 = __ldg(&csrc[p+0]);
        int s1 = __ldg(&csrc[p+1]);
        int s2 = __ldg(&csrc[p+2]);
        int s3 = __ldg(&csrc[p+3]);
        float2 x0 = __ldg((const float2*)&t2[s0*2]);
        float2 x1 = __ldg((const float2*)&t2[s1*2]);
        float2 x2 = __ldg((const float2*)&t2[s2*2]);
        float2 x3 = __ldg((const float2*)&t2[s3*2]);
        a0 += x0.x + x1.x + x2.x + x3.x;
        a1 += x0.y + x1.y + x2.y + x3.y;
    }
    for (; p < en; p++) {
        int s = __ldg(&csrc[p]);
        float2 ts = __ldg((const float2*)&t2[s*2]);
        a0 += ts.x;
        a1 += ts.y;
    }
    a0 = a0*dv + nab[0];
    a1 = a1*dv + nab[1];
    float m = fmaxf(a0, a1);
    float e0 = expf(a0 - m), e1 = expf(a1 - m);
    float inv = 1.f/(e0+e1);
    natt[v*2+0] = e0*inv; natt[v*2+1] = e1*inv;
}

// ---------------- fused heads ----------------
__global__ void head_gemm1(const float* __restrict__ cat,
                           const float* __restrict__ mean, const float* __restrict__ rstd,
                           const float* __restrict__ cW1, const float* __restrict__ cb1,
                           const float* __restrict__ oW1, const float* __restrict__ ob1,
                           const float* __restrict__ coW1, const float* __restrict__ cob1,
                           float* __restrict__ hd) {
    __shared__ float a[256];
    int r = blockIdx.x, head = blockIdx.y;
    for (int k = threadIdx.x; k < 256; k += 128)
        a[k] = (cat[r*256 + k] - mean[k]) * rstd[k] + BNB;
    __syncthreads();
    const float* W; const float* b; int K, koff, act;
    if (head == 0)      { W = cW1;  b = cb1;  K = 128; koff = 0;   act = 1; }
    else if (head == 1) { W = oW1;  b = ob1;  K = 128; koff = 128; act = 1; }
    else                { W = coW1; b = cob1; K = 256; koff = 0;   act = 2; }
    int c = threadIdx.x;
    float acc = b[c];
    for (int k = 0; k < K; k++) acc += a[koff + k] * W[k*128 + c];
    if (act == 1) acc = fmaxf(acc, 0.f);
    else {
        acc = (acc > 0.f) ? acc : expm1f(acc);
        acc = (acc > 0.f) ? acc : expm1f(acc);
    }
    hd[(head*Gg + r)*128 + c] = acc;
}

__global__ void head_gemm2_lsm(const float* __restrict__ hd,
                               const float* __restrict__ mean, const float* __restrict__ rstd,
                               const float* __restrict__ cW2, const float* __restrict__ cb2,
                               const float* __restrict__ oW2, const float* __restrict__ ob2,
                               const float* __restrict__ coW2, const float* __restrict__ cob2,
                               float* __restrict__ out) {
    __shared__ float a[128];
    __shared__ float lg[COUT];
    int r = blockIdx.x, head = blockIdx.y;
    int k = threadIdx.x;
    a[k] = (hd[(head*Gg + r)*128 + k] - mean[head*128 + k]) * rstd[head*128 + k] + BNB;
    __syncthreads();
    const float* W = (head == 0) ? cW2 : (head == 1) ? oW2 : coW2;
    const float* b = (head == 0) ? cb2 : (head == 1) ? ob2 : cob2;
    if (k < COUT) {
        float acc = b[k];
        for (int kk = 0; kk < 128; kk++) acc += a[kk] * W[kk*COUT + k];
        lg[k] = acc;
    }
    __syncthreads();
    if (k < COUT) {
        float m = -1e30f;
        #pragma unroll
        for (int i = 0; i < COUT; i++) m = fmaxf(m, lg[i]);
        float s = 0.f;
        #pragma unroll
        for (int i = 0; i < COUT; i++) s += expf(lg[i] - m);
        out[head*Gg*COUT + r*COUT + k] = lg[k] - m - logf(s);
    }
}

// ---------------- host orchestration ----------------
extern "C" void kernel_launch(void* const* d_in, const int* in_sizes, int n_in,
                              void* d_out, int out_size) {
    const float* x      = (const float*)d_in[0];
    const float* W_feat = (const float*)d_in[1];
    const float* conv_Ws= (const float*)d_in[2];
    const float* conv_bs= (const float*)d_in[3];
    const float* eW     = (const float*)d_in[4];
    const float* eb     = (const float*)d_in[5];
    const float* naW    = (const float*)d_in[6];
    const float* nab    = (const float*)d_in[7];
    const float* xcW    = (const float*)d_in[8];
    const float* xcb    = (const float*)d_in[9];
    const float* xoW    = (const float*)d_in[10];
    const float* xob    = (const float*)d_in[11];
    const float* cW1    = (const float*)d_in[12];
    const float* cb1    = (const float*)d_in[13];
    const float* cW2    = (const float*)d_in[14];
    const float* cb2    = (const float*)d_in[15];
    const float* oW1    = (const float*)d_in[16];
    const float* ob1    = (const float*)d_in[17];
    const float* oW2    = (const float*)d_in[18];
    const float* ob2    = (const float*)d_in[19];
    const float* coW1   = (const float*)d_in[20];
    const float* cob1   = (const float*)d_in[21];
    const float* coW2   = (const float*)d_in[22];
    const float* cob2   = (const float*)d_in[23];
    const int* esrc     = (const int*)d_in[24];
    const int* edst     = (const int*)d_in[25];
    const int* batch    = (const int*)d_in[26];
    float* out = (float*)d_out;

    float *p_h,*p_t,*p_t2b,*p_stats,*p_mean,*p_rstd,*p_disU;
    float *p_epro,*p_t2,*p_natt,*p_eperm,*p_bias2,*p_cat,*p_hd;
    float2* p_deg01;
    int *p_cnt,*p_incl,*p_bsum,*p_rowptr,*p_cursor,*p_csrc,*p_pos;
    cudaGetSymbolAddress((void**)&p_h, g_h);
    cudaGetSymbolAddress((void**)&p_t, g_t);
    cudaGetSymbolAddress((void**)&p_t2b, g_t2b);
    cudaGetSymbolAddress((void**)&p_stats, g_stats);
    cudaGetSymbolAddress((void**)&p_mean, g_mean);
    cudaGetSymbolAddress((void**)&p_rstd, g_rstd);
    cudaGetSymbolAddress((void**)&p_disU, g_disU);
    cudaGetSymbolAddress((void**)&p_deg01, g_deg01);
    cudaGetSymbolAddress((void**)&p_epro, g_epro);
    cudaGetSymbolAddress((void**)&p_t2, g_t2);
    cudaGetSymbolAddress((void**)&p_natt, g_natt);
    cudaGetSymbolAddress((void**)&p_eperm, g_eperm);
    cudaGetSymbolAddress((void**)&p_bias2, g_bias2);
    cudaGetSymbolAddress((void**)&p_cat, g_cat);
    cudaGetSymbolAddress((void**)&p_hd, g_hd);
    cudaGetSymbolAddress((void**)&p_cnt, g_cnt);
    cudaGetSymbolAddress((void**)&p_incl, g_incl);
    cudaGetSymbolAddress((void**)&p_bsum, g_bsum);
    cudaGetSymbolAddress((void**)&p_rowptr, g_rowptr);
    cudaGetSymbolAddress((void**)&p_cursor, g_cursor);
    cudaGetSymbolAddress((void**)&p_csrc, g_csrc);
    cudaGetSymbolAddress((void**)&p_pos, g_pos);

    cudaFuncSetAttribute(gemm128, cudaFuncAttributeMaxDynamicSharedMemorySize, GEMM_SMEM);
    cudaFuncSetAttribute(gemm256, cudaFuncAttributeMaxDynamicSharedMemorySize, GEMM_SMEM);

    const int N = Nn, E = Ee, G = Gg;
    const int NB = (N + 63) / 64;
    const int NT = (N + 255) / 256;
    const int ET = (E + 255) / 256;
    const int GB = 1024;
    const int NSCAN = (N + 1023) / 1024;

    cudaStream_t sA;
    cudaStreamCreateWithFlags(&sA, cudaStreamNonBlocking);
    cudaEvent_t evF1, evJ1, evF2, evJ2;
    cudaEventCreateWithFlags(&evF1, cudaEventDisableTiming);
    cudaEventCreateWithFlags(&evJ1, cudaEventDisableTiming);
    cudaEventCreateWithFlags(&evF2, cudaEventDisableTiming);
    cudaEventCreateWithFlags(&evJ2, cudaEventDisableTiming);

    // ==== FORK 1: CSR build on sA ====
    cudaEventRecord(evF1, 0);
    cudaStreamWaitEvent(sA, evF1, 0);
    init_kernel<<<NT,256,0,sA>>>(p_disU, p_deg01, p_cnt, N);
    deg_hist<<<ET,256,0,sA>>>(esrc, edst, p_disU, p_cnt, E);
    scan_block<<<NSCAN,1024,0,sA>>>(p_cnt, p_incl, p_bsum, N);
    scan_tops<<<1,32,0,sA>>>(p_bsum, NSCAN);
    make_rowptr<<<NT,256,0,sA>>>(p_cnt, p_incl, p_bsum, p_rowptr, p_cursor, p_disU, N, E);
    fill_csr<<<ET,256,0,sA>>>(esrc, edst, p_cursor, p_csrc, p_pos, E);
    cudaEventRecord(evJ1, sA);

    // main chain: h = relu(BN(x) @ W_feat), stats fused; layer-0 GEMM
    colstats<<<512,256>>>(x, N, p_stats);
    finalize_stats<<<1,256>>>(p_stats, 128, 1.f/N, p_mean, p_rstd);
    gemm128<<<NB,256,GEMM_SMEM>>>(x, p_mean, p_rstd, W_feat, p_h, p_stats,
                                  nullptr, N, 1);
    finalize_stats<<<1,256>>>(p_stats, 128, 1.f/N, p_mean, p_rstd);

    // JOIN 1 (layer GEMM output is dis-scaled -> needs disU; gather needs CSR)
    cudaStreamWaitEvent(0, evJ1, 0);
    gemm128<<<NB,256,GEMM_SMEM>>>(p_h, p_mean, p_rstd, conv_Ws, p_t, nullptr,
                                  p_disU, N, 0);

    // ---- GCN layers ----
    gather128<<<GB,256>>>(p_t, p_rowptr, p_csrc, p_disU, conv_bs, p_h, p_stats,
                          nullptr, nullptr, nullptr, nullptr, N, 1);
    finalize_stats<<<1,256>>>(p_stats, 128, 1.f/N, p_mean, p_rstd);
    for (int l = 1; l < 3; l++) {
        gemm128<<<NB,256,GEMM_SMEM>>>(p_h, p_mean, p_rstd,
                                      conv_Ws + l*128*128, p_t, nullptr,
                                      p_disU, N, 0);
        if (l < 2) {
            gather128<<<GB,256>>>(p_t, p_rowptr, p_csrc, p_disU,
                                  conv_bs + l*128, p_h, p_stats,
                                  nullptr, nullptr, nullptr, nullptr, N, 1);
            finalize_stats<<<1,256>>>(p_stats, 128, 1.f/N, p_mean, p_rstd);
        } else {
            gather128<<<GB,256>>>(p_t, p_rowptr, p_csrc, p_disU,
                                  conv_bs + l*128, p_h, nullptr,
                                  eW, naW, p_epro, p_t2, N, 1);
        }
    }

    // ==== FORK 2: edge attention on sA ====
    cudaEventRecord(evF2, 0);
    cudaStreamWaitEvent(sA, evF2, 0);
    edge_att_kernel<<<ET,256,0,sA>>>(esrc, edst, p_pos, p_epro, eb, p_eperm, p_deg01, E);
    rsqrt_arr<<<(2*N+255)/256,256,0,sA>>>((float*)p_deg01, 2*N);
    cudaMemsetAsync(p_cat, 0, Gg*256*sizeof(float), sA);
    cudaEventRecord(evJ2, sA);

    // main: node attention + XC/XO stats
    natt_gather<<<NT,256>>>(p_t2, p_rowptr, p_csrc, p_disU, nab, p_natt, N);
    colstats2<<<512,256>>>(p_h, p_natt, N, p_stats);
    finalize2<<<1,256>>>(p_stats, 1.f/N, p_mean, p_rstd);
    bias_kernel<<<2,128>>>(p_mean, p_rstd, xcW, xoW, p_bias2);

    // JOIN 2 (gemm256 pre-scales rows by deg01; gather2 needs eperm + zeroed cat)
    cudaStreamWaitEvent(0, evJ2, 0);
    gemm256<<<NB,256,GEMM_SMEM>>>(p_h, p_natt, p_rstd, xcW, xoW, p_bias2,
                                  p_deg01, p_t, p_t2b, N);
    gather2<<<GB,256>>>(p_t, p_t2b, p_rowptr, p_csrc, p_deg01, p_eperm,
                        xcb, xob, batch, p_cat, N);

    // ---- heads ----
    head_stats<<<256,128>>>(p_cat, 256, G, p_mean, p_rstd);
    dim3 hg1(G, 3);
    head_gemm1<<<hg1,128>>>(p_cat, p_mean, p_rstd, cW1, cb1, oW1, ob1,
                            coW1, cob1, p_hd);
    head_stats3<<<384,128>>>(p_hd, G, p_mean, p_rstd);
    dim3 hg2(G, 3);
    head_gemm2_lsm<<<hg2,128>>>(p_hd, p_mean, p_rstd, cW2, cb2, oW2, ob2,
                                coW2, cob2, out);

    cudaEventDestroy(evF1);
    cudaEventDestroy(evJ1);
    cudaEventDestroy(evF2);
    cudaEventDestroy(evJ2);
    cudaStreamDestroy(sA);
}

// round 15
// speedup vs baseline: 1.1414x; 1.0445x over previous
#include <cuda_runtime.h>
#include <math.h>

#define Nn 50000
#define Ee 400000
#define Hh 128
#define Gg 512
#define COUT 10

typedef unsigned long long u64;

static constexpr float EPSBN = 1e-5f;
static constexpr float BNB   = 1e-4f;

// ---------------- scratch (static device allocations) ----------------
__device__ float g_h[Nn*Hh];
__device__ float g_t[Nn*Hh];
__device__ float g_t2b[Nn*Hh];
__device__ float g_stats[5*512];    // 5 stat instances; memset at graph head
__device__ float g_mean[512];
__device__ float g_rstd[512];
__device__ float g_disU[Nn];
__device__ float2 g_deg01[Nn];
__device__ float g_epro[Nn*4];
__device__ float g_t2[Nn*2];        // disU-scaled naW projections
__device__ float g_natt[Nn*2];
__device__ float g_eperm[Ee*2];
__device__ float g_bias2[256];
__device__ float g_cat[Gg*256];
__device__ float g_hd[3*Gg*128];
// CSR by destination
__device__ int g_cnt[Nn];
__device__ int g_incl[Nn];
__device__ int g_bsum[64];
__device__ int g_rowptr[Nn+1];
__device__ int g_cursor[Nn];
__device__ int g_csrc[Ee];
__device__ int g_pos[Ee];

// ---------------- small utility kernels ----------------
__global__ void init_kernel(float* disU, float2* deg01, int* cnt, int n) {
    int i = blockIdx.x*blockDim.x + threadIdx.x;
    if (i < n) { disU[i] = 1.f; deg01[i] = make_float2(1.f, 1.f); cnt[i] = 0; }
}

__global__ void deg_hist(const int* __restrict__ src, const int* __restrict__ dst,
                         float* degU, int* cnt, int E) {
    int i = blockIdx.x*blockDim.x + threadIdx.x;
    if (i < E) {
        atomicAdd(&degU[src[i]], 1.0f);
        atomicAdd(&cnt[dst[i]], 1);
    }
}

__global__ void rsqrt_arr(float* p, int n) {
    int i = blockIdx.x*blockDim.x + threadIdx.x;
    if (i < n) p[i] = rsqrtf(p[i]);
}

// ---------------- CSR build ----------------
__global__ void scan_block(const int* __restrict__ cnt, int* incl, int* bsum, int n) {
    __shared__ int sm[1024];
    int i = blockIdx.x*1024 + threadIdx.x;
    sm[threadIdx.x] = (i < n) ? cnt[i] : 0;
    __syncthreads();
    for (int off = 1; off < 1024; off <<= 1) {
        int t = (threadIdx.x >= off) ? sm[threadIdx.x - off] : 0;
        __syncthreads();
        sm[threadIdx.x] += t;
        __syncthreads();
    }
    if (i < n) incl[i] = sm[threadIdx.x];
    if (threadIdx.x == 1023) bsum[blockIdx.x] = sm[1023];
}

__global__ void scan_tops(int* bsum, int nb) {
    int lane = threadIdx.x;
    int v0 = (lane < nb) ? bsum[lane] : 0;
    int v1 = (32 + lane < nb) ? bsum[32 + lane] : 0;
    #pragma unroll
    for (int o = 1; o < 32; o <<= 1) {
        int t = __shfl_up_sync(0xffffffffu, v0, o);
        if (lane >= o) v0 += t;
    }
    int tot0 = __shfl_sync(0xffffffffu, v0, 31);
    #pragma unroll
    for (int o = 1; o < 32; o <<= 1) {
        int t = __shfl_up_sync(0xffffffffu, v1, o);
        if (lane >= o) v1 += t;
    }
    v1 += tot0;
    if (lane < nb) bsum[lane] = v0;
    if (32 + lane < nb) bsum[32 + lane] = v1;
}

__global__ void make_rowptr(const int* __restrict__ cnt, const int* __restrict__ incl,
                            const int* __restrict__ bsum,
                            int* rowptr, int* cursor, float* disU, int n, int E) {
    int i = blockIdx.x*blockDim.x + threadIdx.x;
    if (i < n) {
        int b = i >> 10;
        int ex = incl[i] - cnt[i] + ((b > 0) ? bsum[b-1] : 0);
        rowptr[i] = ex;
        cursor[i] = ex;
        disU[i] = rsqrtf(disU[i]);
    }
    if (i == 0) rowptr[n] = E;
}

__global__ void fill_csr(const int* __restrict__ src, const int* __restrict__ dst,
                         int* cursor, int* csrc, int* pos, int E) {
    int e = blockIdx.x*blockDim.x + threadIdx.x;
    if (e < E) {
        int p = atomicAdd(&cursor[dst[e]], 1);
        csrc[p] = src[e];
        pos[e] = p;
    }
}

// ---------------- BatchNorm stats (accumulate only; consumers finalize) ----------------
__global__ void colstats(const float* __restrict__ A, int n, float* sums) {
    long total  = (long)n * 128;
    long stride = (long)gridDim.x * blockDim.x;
    long i0     = (long)blockIdx.x*blockDim.x + threadIdx.x;
    if (i0 >= total) return;
    int c = (int)(i0 % 128);
    float s0 = 0.f, s1 = 0.f;
    for (long i = i0; i < total; i += stride) {
        int r = (int)(i / 128);
        float v = A[(long)r*128 + c];
        s0 += v; s1 += v*v;
    }
    atomicAdd(&sums[c], s0);
    atomicAdd(&sums[128+c], s1);
}

__global__ void colstats2(const float* __restrict__ A, const float* __restrict__ natt,
                          int n, float* sums) {
    long total  = (long)n * 128;
    long stride = (long)gridDim.x * blockDim.x;
    long i0     = (long)blockIdx.x*blockDim.x + threadIdx.x;
    if (i0 >= total) return;
    int c = (int)(i0 % 128);
    float s00=0.f, s01=0.f, s10=0.f, s11=0.f;
    for (long i = i0; i < total; i += stride) {
        int r = (int)(i / 128);
        float v = A[(long)r*128 + c];
        float v0 = v * natt[r*2+0];
        float v1 = v * natt[r*2+1];
        s00 += v0; s01 += v0*v0;
        s10 += v1; s11 += v1*v1;
    }
    atomicAdd(&sums[c], s00);
    atomicAdd(&sums[128+c], s01);
    atomicAdd(&sums[256+c], s10);
    atomicAdd(&sums[384+c], s11);
}

// merged finalize (both natt channels) + BN-folded bias rows
__global__ void finalize2bias(const float* __restrict__ sums, float inv_n,
                              float* __restrict__ mean, float* __restrict__ rstd,
                              const float* __restrict__ xcW, const float* __restrict__ xoW,
                              float* __restrict__ bias2) {
    __shared__ float coef[128];
    int ch = blockIdx.x;
    int t = threadIdx.x;
    float s0 = sums[ch*256 + t], s1 = sums[ch*256 + 128 + t];
    float m = s0*inv_n;
    float var = s1*inv_n - m*m;
    float rs = rsqrtf(var + EPSBN);
    mean[ch*128 + t] = m;
    rstd[ch*128 + t] = rs;
    coef[t] = BNB - m*rs;
    __syncthreads();
    const float* W = ch ? xoW : xcW;
    float acc = 0.f;
    for (int k = 0; k < 128; k++) acc += coef[k]*W[k*128+t];
    bias2[ch*128 + t] = acc;
}

__global__ void head_stats(const float* __restrict__ A, int lda, int n,
                           float* mean, float* rstd) {
    __shared__ float s0s[4], s1s[4];
    int c = blockIdx.x;
    int lane = threadIdx.x & 31, warp = threadIdx.x >> 5;
    float s0 = 0.f, s1 = 0.f;
    for (int r = threadIdx.x; r < n; r += blockDim.x) {
        float v = A[r*lda + c];
        s0 += v; s1 += v*v;
    }
    #pragma unroll
    for (int o = 16; o; o >>= 1) {
        s0 += __shfl_xor_sync(0xffffffffu, s0, o);
        s1 += __shfl_xor_sync(0xffffffffu, s1, o);
    }
    if (lane == 0) { s0s[warp] = s0; s1s[warp] = s1; }
    __syncthreads();
    if (threadIdx.x == 0) {
        float t0 = 0.f, t1 = 0.f;
        for (int w = 0; w < 4; w++) { t0 += s0s[w]; t1 += s1s[w]; }
        float m = t0 / n;
        float var = t1 / n - m*m;
        mean[c] = m;
        rstd[c] = rsqrtf(var + EPSBN);
    }
}

__global__ void head_stats3(const float* __restrict__ hd, int n,
                            float* mean, float* rstd) {
    __shared__ float s0s[4], s1s[4];
    int cg = blockIdx.x;
    int head = cg >> 7, c = cg & 127;
    const float* A = hd + head*Gg*128;
    int lane = threadIdx.x & 31, warp = threadIdx.x >> 5;
    float s0 = 0.f, s1 = 0.f;
    for (int r = threadIdx.x; r < n; r += blockDim.x) {
        float v = A[r*128 + c];
        s0 += v; s1 += v*v;
    }
    #pragma unroll
    for (int o = 16; o; o >>= 1) {
        s0 += __shfl_xor_sync(0xffffffffu, s0, o);
        s1 += __shfl_xor_sync(0xffffffffu, s1, o);
    }
    if (lane == 0) { s0s[warp] = s0; s1s[warp] = s1; }
    __syncthreads();
    if (threadIdx.x == 0) {
        float t0 = 0.f, t1 = 0.f;
        for (int w = 0; w < 4; w++) { t0 += s0s[w]; t1 += s1s[w]; }
        float m = t0 / n;
        float var = t1 / n - m*m;
        mean[cg] = m;
        rstd[cg] = rsqrtf(var + EPSBN);
    }
}

// ---------------- big GEMM (packed f32x2 FMA, BM=64, K-chunked W, 3 CTAs/SM) ----------------
// consumes RAW stats (sums_in); each block finalizes mean/rstd into smem.
static constexpr int GEMM_SMEM = (64*128 + 64*128 + 256) * 4;

__global__ __launch_bounds__(256, 3) void gemm128(
    const float* __restrict__ A,
    const float* __restrict__ sums_in, float inv_n,
    const float* __restrict__ W,
    float* __restrict__ out,
    float* __restrict__ sums_out,
    const float* __restrict__ rowscale,
    int n, int act)
{
    extern __shared__ float sm[];
    float* As = sm;                    // [64][128]
    float* Ws = sm + 64*128;           // [64][128] W chunk
    float* smean = sm + 2*64*128;      // [128]
    float* srstd = smean + 128;        // [128]
    int tid  = threadIdx.x;
    int row0 = blockIdx.x * 64;

    if (tid < 128) {
        float s0 = sums_in[tid], s1 = sums_in[128+tid];
        float m = s0*inv_n;
        float var = s1*inv_n - m*m;
        smean[tid] = m;
        srstd[tid] = rsqrtf(var + EPSBN);
    }
    __syncthreads();

    #pragma unroll 2
    for (int i = tid; i < 64*32; i += 256) {
        int r = i >> 5, cq = i & 31;
        int gr = row0 + r;
        float4 v = make_float4(0.f,0.f,0.f,0.f);
        if (gr < n) {
            v = ((const float4*)A)[gr*32 + cq];
            int c = cq*4;
            v.x = (v.x - smean[c+0])*srstd[c+0] + BNB;
            v.y = (v.y - smean[c+1])*srstd[c+1] + BNB;
            v.z = (v.z - smean[c+2])*srstd[c+2] + BNB;
            v.w = (v.w - smean[c+3])*srstd[c+3] + BNB;
        }
        ((float4*)As)[i] = v;
    }

    int tc = tid & 15, tr = tid >> 4;
    int r0 = tr*4;
    int c0 = tc*4, c1 = 64 + tc*4;

    u64 accp[4][4];
    #pragma unroll
    for (int i = 0; i < 4; i++)
        #pragma unroll
        for (int j = 0; j < 4; j++) accp[i][j] = 0ull;

    const float4* Wg = (const float4*)W;
    float4* Ws4 = (float4*)Ws;

    #pragma unroll
    for (int kc = 0; kc < 128; kc += 64) {
        __syncthreads();
        #pragma unroll 2
        for (int i = tid; i < 64*32; i += 256)
            Ws4[i] = Wg[(kc + (i >> 5))*32 + (i & 31)];
        __syncthreads();

        for (int k = 0; k < 64; k += 4) {
            float4 a4[4];
            #pragma unroll
            for (int i = 0; i < 4; i++)
                a4[i] = *(const float4*)&As[(r0+i)*128 + kc + k];
            #pragma unroll
            for (int kk = 0; kk < 4; kk++) {
                ulonglong2 w01 = *(const ulonglong2*)&Ws[(k+kk)*128 + c0];
                ulonglong2 w23 = *(const ulonglong2*)&Ws[(k+kk)*128 + c1];
                u64 wp0 = w01.x, wp1 = w01.y, wp2 = w23.x, wp3 = w23.y;
                #pragma unroll
                for (int i = 0; i < 4; i++) {
                    float a = ((const float*)&a4[i])[kk];
                    unsigned int ai = __float_as_uint(a);
                    u64 ap;
                    asm("mov.b64 %0, {%1, %1};" : "=l"(ap) : "r"(ai));
                    asm("fma.rn.f32x2 %0, %1, %2, %0;" : "+l"(accp[i][0]) : "l"(ap), "l"(wp0));
                    asm("fma.rn.f32x2 %0, %1, %2, %0;" : "+l"(accp[i][1]) : "l"(ap), "l"(wp1));
                    asm("fma.rn.f32x2 %0, %1, %2, %0;" : "+l"(accp[i][2]) : "l"(ap), "l"(wp2));
                    asm("fma.rn.f32x2 %0, %1, %2, %0;" : "+l"(accp[i][3]) : "l"(ap), "l"(wp3));
                }
            }
        }
    }

    float t0[8], t1[8];
    #pragma unroll
    for (int j = 0; j < 8; j++) { t0[j] = 0.f; t1[j] = 0.f; }

    float4* O4 = (float4*)out;
    #pragma unroll
    for (int i = 0; i < 4; i++) {
        int gr = row0 + r0 + i;
        if (gr < n) {
            float o[8];
            #pragma unroll
            for (int j = 0; j < 4; j++) {
                unsigned int lo, hi;
                asm("mov.b64 {%0, %1}, %2;" : "=r"(lo), "=r"(hi) : "l"(accp[i][j]));
                o[2*j]   = __uint_as_float(lo);
                o[2*j+1] = __uint_as_float(hi);
            }
            if (act == 1) {
                #pragma unroll
                for (int j = 0; j < 8; j++) o[j] = fmaxf(o[j], 0.f);
            }
            if (rowscale) {
                float rs = rowscale[gr];
                #pragma unroll
                for (int j = 0; j < 8; j++) o[j] *= rs;
            }
            if (sums_out) {
                #pragma unroll
                for (int j = 0; j < 8; j++) { t0[j] += o[j]; t1[j] += o[j]*o[j]; }
            }
            O4[gr*32 + tc]      = make_float4(o[0], o[1], o[2], o[3]);
            O4[gr*32 + 16 + tc] = make_float4(o[4], o[5], o[6], o[7]);
        }
    }

    if (sums_out) {
        __syncthreads();
        float* ss = sm;
        ss[tid] = 0.f;
        __syncthreads();
        #pragma unroll
        for (int j = 0; j < 4; j++) {
            atomicAdd(&ss[c0+j],     t0[j]);   atomicAdd(&ss[128+c0+j], t1[j]);
            atomicAdd(&ss[c1+j],     t0[4+j]); atomicAdd(&ss[128+c1+j], t1[4+j]);
        }
        __syncthreads();
        atomicAdd(&sums_out[tid], ss[tid]);
    }
}

// ---------------- merged XC/XO GEMM (K-chunked, rows pre-scaled by deg01) ----------------
__global__ __launch_bounds__(256, 3) void gemm256(
    const float* __restrict__ h,
    const float* __restrict__ natt,
    const float* __restrict__ rstd2,
    const float* __restrict__ xcW, const float* __restrict__ xoW,
    const float* __restrict__ bias2,
    const float2* __restrict__ deg01,
    float* __restrict__ outc, float* __restrict__ outo, int n)
{
    extern __shared__ float sm[];
    float* As = sm;               // [64][128]
    float* Ws = sm + 64*128;      // [64][128] chunk
    int tid  = threadIdx.x;
    int row0 = blockIdx.x * 64;

    #pragma unroll 2
    for (int i = tid; i < 64*32; i += 256) {
        int r = i >> 5, cq = i & 31;
        int gr = row0 + r;
        float4 v = (gr < n) ? ((const float4*)h)[gr*32 + cq]
                            : make_float4(0.f,0.f,0.f,0.f);
        ((float4*)As)[i] = v;
    }

    int tc = tid & 15, tr = tid >> 4;
    int r0 = tr*4;
    int c0 = tc*4, c1 = 64 + tc*4;

    #pragma unroll
    for (int half = 0; half < 2; half++) {
        const float* W  = half ? xoW : xcW;
        const float* rs = rstd2 + half*128;
        const float* bs = bias2 + half*128;
        float* out = half ? outo : outc;

        float nv[4], dsc[4];
        #pragma unroll
        for (int i = 0; i < 4; i++) {
            int gr = row0 + r0 + i;
            nv[i] = (gr < n) ? natt[gr*2 + half] : 0.f;
            float2 d = (gr < n) ? deg01[gr] : make_float2(0.f, 0.f);
            dsc[i] = half ? d.y : d.x;
        }

        u64 accp[4][4];
        #pragma unroll
        for (int i = 0; i < 4; i++)
            #pragma unroll
            for (int j = 0; j < 4; j++) accp[i][j] = 0ull;

        #pragma unroll
        for (int kc = 0; kc < 128; kc += 64) {
            __syncthreads();
            #pragma unroll 2
            for (int i = tid; i < 64*32; i += 256) {
                int r = kc + (i >> 5);
                float4 w = ((const float4*)W)[r*32 + (i & 31)];
                float sc = rs[r];
                w.x *= sc; w.y *= sc; w.z *= sc; w.w *= sc;
                ((float4*)Ws)[i] = w;
            }
            __syncthreads();

            for (int k = 0; k < 64; k += 4) {
                float4 a4[4];
                #pragma unroll
                for (int i = 0; i < 4; i++)
                    a4[i] = *(const float4*)&As[(r0+i)*128 + kc + k];
                #pragma unroll
                for (int kk = 0; kk < 4; kk++) {
                    ulonglong2 w01 = *(const ulonglong2*)&Ws[(k+kk)*128 + c0];
                    ulonglong2 w23 = *(const ulonglong2*)&Ws[(k+kk)*128 + c1];
                    u64 wp0 = w01.x, wp1 = w01.y, wp2 = w23.x, wp3 = w23.y;
                    #pragma unroll
                    for (int i = 0; i < 4; i++) {
                        float a = ((const float*)&a4[i])[kk] * nv[i];
                        unsigned int ai = __float_as_uint(a);
                        u64 ap;
                        asm("mov.b64 %0, {%1, %1};" : "=l"(ap) : "r"(ai));
                        asm("fma.rn.f32x2 %0, %1, %2, %0;" : "+l"(accp[i][0]) : "l"(ap), "l"(wp0));
                        asm("fma.rn.f32x2 %0, %1, %2, %0;" : "+l"(accp[i][1]) : "l"(ap), "l"(wp1));
                        asm("fma.rn.f32x2 %0, %1, %2, %0;" : "+l"(accp[i][2]) : "l"(ap), "l"(wp2));
                        asm("fma.rn.f32x2 %0, %1, %2, %0;" : "+l"(accp[i][3]) : "l"(ap), "l"(wp3));
                    }
                }
            }
        }

        float4 b0 = *(const float4*)&bs[c0];
        float4 b1 = *(const float4*)&bs[c1];
        float4* O4 = (float4*)out;
        #pragma unroll
        for (int i = 0; i < 4; i++) {
            int gr = row0 + r0 + i;
            if (gr < n) {
                float o[8];
                #pragma unroll
                for (int j = 0; j < 4; j++) {
                    unsigned int lo, hi;
                    asm("mov.b64 {%0, %1}, %2;" : "=r"(lo), "=r"(hi) : "l"(accp[i][j]));
                    o[2*j]   = __uint_as_float(lo);
                    o[2*j+1] = __uint_as_float(hi);
                }
                float d = dsc[i];
                O4[gr*32 + tc]      = make_float4((o[0]+b0.x)*d, (o[1]+b0.y)*d,
                                                  (o[2]+b0.z)*d, (o[3]+b0.w)*d);
                O4[gr*32 + 16 + tc] = make_float4((o[4]+b1.x)*d, (o[5]+b1.y)*d,
                                                  (o[6]+b1.z)*d, (o[7]+b1.w)*d);
            }
        }
    }
}

// ---------------- CSR gather conv (rows pre-scaled: pure row-add loop) ----------------
__global__ __launch_bounds__(256) void gather128(
    const float* __restrict__ t,           // t' = dis-scaled rows
    const int* __restrict__ rowptr, const int* __restrict__ csrc,
    const float* __restrict__ dis,
    const float* __restrict__ bias,
    float* __restrict__ out, float* __restrict__ sums,
    const float* __restrict__ eWg, const float* __restrict__ naWg,
    float* __restrict__ epro, float* __restrict__ t2,
    int n, int act)
{
    __shared__ float sEW[512];
    __shared__ float sNA[256];
    if (eWg) {
        for (int i = threadIdx.x; i < 512; i += 256) sEW[i] = eWg[i];
        for (int i = threadIdx.x; i < 256; i += 256) sNA[i] = naWg[i];
        __syncthreads();
    }
    int lane = threadIdx.x & 31;
    int w0 = (blockIdx.x*blockDim.x + threadIdx.x) >> 5;
    int nw = (gridDim.x*blockDim.x) >> 5;
    float4 bb = bias ? ((const float4*)bias)[lane] : make_float4(0.f,0.f,0.f,0.f);
    float ls0[4] = {0.f,0.f,0.f,0.f}, ls1[4] = {0.f,0.f,0.f,0.f};
    const float4* t4 = (const float4*)t;

    for (int v = w0; v < n; v += nw) {
        float dv = dis[v];
        float4 acc = t4[v*32 + lane];       // self term t'[v]
        int p = rowptr[v], en = rowptr[v+1];
        for (; p + 4 <= en; p += 4) {
            int s0 = __ldg(&csrc[p+0]);
            int s1 = __ldg(&csrc[p+1]);
            int s2 = __ldg(&csrc[p+2]);
            int s3 = __ldg(&csrc[p+3]);
            float4 x0 = t4[s0*32 + lane];
            float4 x1 = t4[s1*32 + lane];
            float4 x2 = t4[s2*32 + lane];
            float4 x3 = t4[s3*32 + lane];
            acc.x += x0.x + x1.x + x2.x + x3.x;
            acc.y += x0.y + x1.y + x2.y + x3.y;
            acc.z += x0.z + x1.z + x2.z + x3.z;
            acc.w += x0.w + x1.w + x2.w + x3.w;
        }
        for (; p < en; p++) {
            int s = __ldg(&csrc[p]);
            float4 x = t4[s*32 + lane];
            acc.x += x.x; acc.y += x.y; acc.z += x.z; acc.w += x.w;
        }
        acc.x = acc.x*dv + bb.x; acc.y = acc.y*dv + bb.y;
        acc.z = acc.z*dv + bb.z; acc.w = acc.w*dv + bb.w;
        if (act == 1) {
            acc.x = fmaxf(acc.x, 0.f); acc.y = fmaxf(acc.y, 0.f);
            acc.z = fmaxf(acc.z, 0.f); acc.w = fmaxf(acc.w, 0.f);
        }
        if (sums) {
            ls0[0]+=acc.x; ls1[0]+=acc.x*acc.x;
            ls0[1]+=acc.y; ls1[1]+=acc.y*acc.y;
            ls0[2]+=acc.z; ls1[2]+=acc.z*acc.z;
            ls0[3]+=acc.w; ls1[3]+=acc.w*acc.w;
        }
        ((float4*)out)[v*32 + lane] = acc;

        if (eWg) {
            float hx[4] = {acc.x, acc.y, acc.z, acc.w};
            float p0=0,p1=0,q0=0,q1=0,u0=0,u1=0;
            #pragma unroll
            for (int i = 0; i < 4; i++) {
                int k = lane*4 + i; float xv = hx[i];
                p0 += xv*sEW[k*2+0];        p1 += xv*sEW[k*2+1];
                q0 += xv*sEW[(128+k)*2+0];  q1 += xv*sEW[(128+k)*2+1];
                u0 += xv*sNA[k*2+0];        u1 += xv*sNA[k*2+1];
            }
            #pragma unroll
            for (int o = 16; o; o >>= 1) {
                p0 += __shfl_xor_sync(0xffffffffu, p0, o);
                p1 += __shfl_xor_sync(0xffffffffu, p1, o);
                q0 += __shfl_xor_sync(0xffffffffu, q0, o);
                q1 += __shfl_xor_sync(0xffffffffu, q1, o);
                u0 += __shfl_xor_sync(0xffffffffu, u0, o);
                u1 += __shfl_xor_sync(0xffffffffu, u1, o);
            }
            if (lane == 0) {
                epro[v*4+0]=p0; epro[v*4+1]=p1; epro[v*4+2]=q0; epro[v*4+3]=q1;
                t2[v*2+0]=u0*dv; t2[v*2+1]=u1*dv;
            }
        }
    }

    if (sums) {
        __shared__ float ss[256];
        ss[threadIdx.x] = 0.f;
        __syncthreads();
        #pragma unroll
        for (int j = 0; j < 4; j++) {
            atomicAdd(&ss[lane*4+j],     ls0[j]);
            atomicAdd(&ss[128+lane*4+j], ls1[j]);
        }
        __syncthreads();
        atomicAdd(&sums[threadIdx.x], ss[threadIdx.x]);
    }
}

// fused XC+XO gather + conv-bias + ELU + pool (rows pre-scaled by deg01)
__global__ __launch_bounds__(256) void gather2(
    const float* __restrict__ tc_, const float* __restrict__ to_,
    const int* __restrict__ rowptr, const int* __restrict__ csrc,
    const float2* __restrict__ dis01,
    const float* __restrict__ eperm,
    const float* __restrict__ xcb, const float* __restrict__ xob,
    const int* __restrict__ batch,
    float* __restrict__ cat, int n)
{
    int lane = threadIdx.x & 31;
    int w0 = (blockIdx.x*blockDim.x + threadIdx.x) >> 5;
    int nw = (gridDim.x*blockDim.x) >> 5;
    const float4* tc4 = (const float4*)tc_;
    const float4* to4 = (const float4*)to_;
    float4 bc = ((const float4*)xcb)[lane];
    float4 bo = ((const float4*)xob)[lane];

    for (int v = w0; v < n; v += nw) {
        float2 dv = dis01[v];
        float4 ac = tc4[v*32 + lane];
        float4 ao = to4[v*32 + lane];
        int p = rowptr[v], en = rowptr[v+1];
        for (; p + 2 <= en; p += 2) {
            int s0 = __ldg(&csrc[p+0]);
            int s1 = __ldg(&csrc[p+1]);
            float2 ea0 = __ldg((const float2*)&eperm[(p+0)*2]);
            float2 ea1 = __ldg((const float2*)&eperm[(p+1)*2]);
            float4 xc0 = tc4[s0*32 + lane];
            float4 xo0 = to4[s0*32 + lane];
            float4 xc1 = tc4[s1*32 + lane];
            float4 xo1 = to4[s1*32 + lane];
            ac.x += ea0.x*xc0.x + ea1.x*xc1.x; ac.y += ea0.x*xc0.y + ea1.x*xc1.y;
            ac.z += ea0.x*xc0.z + ea1.x*xc1.z; ac.w += ea0.x*xc0.w + ea1.x*xc1.w;
            ao.x += ea0.y*xo0.x + ea1.y*xo1.x; ao.y += ea0.y*xo0.y + ea1.y*xo1.y;
            ao.z += ea0.y*xo0.z + ea1.y*xo1.z; ao.w += ea0.y*xo0.w + ea1.y*xo1.w;
        }
        for (; p < en; p++) {
            int s = __ldg(&csrc[p]);
            float2 ea = __ldg((const float2*)&eperm[p*2]);
            float4 xc = tc4[s*32 + lane];
            float4 xo = to4[s*32 + lane];
            ac.x += ea.x*xc.x; ac.y += ea.x*xc.y; ac.z += ea.x*xc.z; ac.w += ea.x*xc.w;
            ao.x += ea.y*xo.x; ao.y += ea.y*xo.y; ao.z += ea.y*xo.z; ao.w += ea.y*xo.w;
        }
        float zc[4] = {ac.x*dv.x+bc.x, ac.y*dv.x+bc.y, ac.z*dv.x+bc.z, ac.w*dv.x+bc.w};
        float zo[4] = {ao.x*dv.y+bo.x, ao.y*dv.y+bo.y, ao.z*dv.y+bo.z, ao.w*dv.y+bo.w};
        #pragma unroll
        for (int j = 0; j < 4; j++) {
            zc[j] = (zc[j] > 0.f) ? zc[j] : expm1f(zc[j]);
            zo[j] = (zo[j] > 0.f) ? zo[j] : expm1f(zo[j]);
        }
        int g = __ldg(&batch[v]);
        float* pc = cat + g*256 + lane*4;
        float* po = pc + 128;
        asm volatile("red.global.add.v4.f32 [%0], {%1, %2, %3, %4};"
                     :: "l"(pc), "f"(zc[0]), "f"(zc[1]), "f"(zc[2]), "f"(zc[3]) : "memory");
        asm volatile("red.global.add.v4.f32 [%0], {%1, %2, %3, %4};"
                     :: "l"(po), "f"(zo[0]), "f"(zo[1]), "f"(zo[2]), "f"(zo[3]) : "memory");
    }
}

// ---------------- attention ----------------
__global__ void edge_att_kernel(const int* __restrict__ src, const int* __restrict__ dst,
                                const int* __restrict__ pos,
                                const float* __restrict__ epro, const float* __restrict__ eb,
                                float* __restrict__ eperm, float2* __restrict__ deg01, int E) {
    int e = blockIdx.x*blockDim.x + threadIdx.x;
    if (e >= E) return;
    int s = src[e], d = dst[e];
    float2 ps = *(const float2*)&epro[s*4];
    float2 qd = *(const float2*)&epro[d*4+2];
    float l0 = ps.x + qd.x + eb[0];
    float l1 = ps.y + qd.y + eb[1];
    float m = fmaxf(l0, l1);
    float e0 = expf(l0 - m), e1 = expf(l1 - m);
    float inv = 1.f/(e0+e1);
    float a0 = e0*inv, a1 = e1*inv;
    int p = pos[e];
    *(float2*)&eperm[p*2] = make_float2(a0, a1);
    asm volatile("red.global.add.v2.f32 [%0], {%1, %2};"
                 :: "l"(&deg01[s]), "f"(a0), "f"(a1) : "memory");
}

// t2 rows pre-scaled by disU; logits = dv*(t2'[v] + sum t2'[s]) + nab
__global__ void natt_gather(const float* __restrict__ t2,
                            const int* __restrict__ rowptr, const int* __restrict__ csrc,
                            const float* __restrict__ disU,
                            const float* __restrict__ nab,
                            float* __restrict__ natt, int n) {
    int v = blockIdx.x*blockDim.x + threadIdx.x;
    if (v >= n) return;
    float dv = disU[v];
    float2 selfv = __ldg((const float2*)&t2[v*2]);
    float a0 = selfv.x, a1 = selfv.y;
    int p = rowptr[v], en = rowptr[v+1];
    for (; p + 4 <= en; p += 4) {
        int s0 = __ldg(&csrc[p+0]);
        int s1 = __ldg(&csrc[p+1]);
        int s2 = __ldg(&csrc[p+2]);
        int s3 = __ldg(&csrc[p+3]);
        float2 x0 = __ldg((const float2*)&t2[s0*2]);
        float2 x1 = __ldg((const float2*)&t2[s1*2]);
        float2 x2 = __ldg((const float2*)&t2[s2*2]);
        float2 x3 = __ldg((const float2*)&t2[s3*2]);
        a0 += x0.x + x1.x + x2.x + x3.x;
        a1 += x0.y + x1.y + x2.y + x3.y;
    }
    for (; p < en; p++) {
        int s = __ldg(&csrc[p]);
        float2 ts = __ldg((const float2*)&t2[s*2]);
        a0 += ts.x;
        a1 += ts.y;
    }
    a0 = a0*dv + nab[0];
    a1 = a1*dv + nab[1];
    float m = fmaxf(a0, a1);
    float e0 = expf(a0 - m), e1 = expf(a1 - m);
    float inv = 1.f/(e0+e1);
    natt[v*2+0] = e0*inv; natt[v*2+1] = e1*inv;
}

// ---------------- fused heads ----------------
__global__ void head_gemm1(const float* __restrict__ cat,
                           const float* __restrict__ mean, const float* __restrict__ rstd,
                           const float* __restrict__ cW1, const float* __restrict__ cb1,
                           const float* __restrict__ oW1, const float* __restrict__ ob1,
                           const float* __restrict__ coW1, const float* __restrict__ cob1,
                           float* __restrict__ hd) {
    __shared__ float a[256];
    int r = blockIdx.x, head = blockIdx.y;
    for (int k = threadIdx.x; k < 256; k += 128)
        a[k] = (cat[r*256 + k] - mean[k]) * rstd[k] + BNB;
    __syncthreads();
    const float* W; const float* b; int K, koff, act;
    if (head == 0)      { W = cW1;  b = cb1;  K = 128; koff = 0;   act = 1; }
    else if (head == 1) { W = oW1;  b = ob1;  K = 128; koff = 128; act = 1; }
    else                { W = coW1; b = cob1; K = 256; koff = 0;   act = 2; }
    int c = threadIdx.x;
    float acc = b[c];
    for (int k = 0; k < K; k++) acc += a[koff + k] * W[k*128 + c];
    if (act == 1) acc = fmaxf(acc, 0.f);
    else {
        acc = (acc > 0.f) ? acc : expm1f(acc);
        acc = (acc > 0.f) ? acc : expm1f(acc);
    }
    hd[(head*Gg + r)*128 + c] = acc;
}

__global__ void head_gemm2_lsm(const float* __restrict__ hd,
                               const float* __restrict__ mean, const float* __restrict__ rstd,
                               const float* __restrict__ cW2, const float* __restrict__ cb2,
                               const float* __restrict__ oW2, const float* __restrict__ ob2,
                               const float* __restrict__ coW2, const float* __restrict__ cob2,
                               float* __restrict__ out) {
    __shared__ float a[128];
    __shared__ float lg[COUT];
    int r = blockIdx.x, head = blockIdx.y;
    int k = threadIdx.x;
    a[k] = (hd[(head*Gg + r)*128 + k] - mean[head*128 + k]) * rstd[head*128 + k] + BNB;
    __syncthreads();
    const float* W = (head == 0) ? cW2 : (head == 1) ? oW2 : coW2;
    const float* b = (head == 0) ? cb2 : (head == 1) ? ob2 : cob2;
    if (k < COUT) {
        float acc = b[k];
        for (int kk = 0; kk < 128; kk++) acc += a[kk] * W[kk*COUT + k];
        lg[k] = acc;
    }
    __syncthreads();
    if (k < COUT) {
        float m = -1e30f;
        #pragma unroll
        for (int i = 0; i < COUT; i++) m = fmaxf(m, lg[i]);
        float s = 0.f;
        #pragma unroll
        for (int i = 0; i < COUT; i++) s += expf(lg[i] - m);
        out[head*Gg*COUT + r*COUT + k] = lg[k] - m - logf(s);
    }
}

// ---------------- host orchestration ----------------
extern "C" void kernel_launch(void* const* d_in, const int* in_sizes, int n_in,
                              void* d_out, int out_size) {
    const float* x      = (const float*)d_in[0];
    const float* W_feat = (const float*)d_in[1];
    const float* conv_Ws= (const float*)d_in[2];
    const float* conv_bs= (const float*)d_in[3];
    const float* eW     = (const float*)d_in[4];
    const float* eb     = (const float*)d_in[5];
    const float* naW    = (const float*)d_in[6];
    const float* nab    = (const float*)d_in[7];
    const float* xcW    = (const float*)d_in[8];
    const float* xcb    = (const float*)d_in[9];
    const float* xoW    = (const float*)d_in[10];
    const float* xob    = (const float*)d_in[11];
    const float* cW1    = (const float*)d_in[12];
    const float* cb1    = (const float*)d_in[13];
    const float* cW2    = (const float*)d_in[14];
    const float* cb2    = (const float*)d_in[15];
    const float* oW1    = (const float*)d_in[16];
    const float* ob1    = (const float*)d_in[17];
    const float* oW2    = (const float*)d_in[18];
    const float* ob2    = (const float*)d_in[19];
    const float* coW1   = (const float*)d_in[20];
    const float* cob1   = (const float*)d_in[21];
    const float* coW2   = (const float*)d_in[22];
    const float* cob2   = (const float*)d_in[23];
    const int* esrc     = (const int*)d_in[24];
    const int* edst     = (const int*)d_in[25];
    const int* batch    = (const int*)d_in[26];
    float* out = (float*)d_out;

    float *p_h,*p_t,*p_t2b,*p_stats,*p_mean,*p_rstd,*p_disU;
    float *p_epro,*p_t2,*p_natt,*p_eperm,*p_bias2,*p_cat,*p_hd;
    float2* p_deg01;
    int *p_cnt,*p_incl,*p_bsum,*p_rowptr,*p_cursor,*p_csrc,*p_pos;
    cudaGetSymbolAddress((void**)&p_h, g_h);
    cudaGetSymbolAddress((void**)&p_t, g_t);
    cudaGetSymbolAddress((void**)&p_t2b, g_t2b);
    cudaGetSymbolAddress((void**)&p_stats, g_stats);
    cudaGetSymbolAddress((void**)&p_mean, g_mean);
    cudaGetSymbolAddress((void**)&p_rstd, g_rstd);
    cudaGetSymbolAddress((void**)&p_disU, g_disU);
    cudaGetSymbolAddress((void**)&p_deg01, g_deg01);
    cudaGetSymbolAddress((void**)&p_epro, g_epro);
    cudaGetSymbolAddress((void**)&p_t2, g_t2);
    cudaGetSymbolAddress((void**)&p_natt, g_natt);
    cudaGetSymbolAddress((void**)&p_eperm, g_eperm);
    cudaGetSymbolAddress((void**)&p_bias2, g_bias2);
    cudaGetSymbolAddress((void**)&p_cat, g_cat);
    cudaGetSymbolAddress((void**)&p_hd, g_hd);
    cudaGetSymbolAddress((void**)&p_cnt, g_cnt);
    cudaGetSymbolAddress((void**)&p_incl, g_incl);
    cudaGetSymbolAddress((void**)&p_bsum, g_bsum);
    cudaGetSymbolAddress((void**)&p_rowptr, g_rowptr);
    cudaGetSymbolAddress((void**)&p_cursor, g_cursor);
    cudaGetSymbolAddress((void**)&p_csrc, g_csrc);
    cudaGetSymbolAddress((void**)&p_pos, g_pos);

    cudaFuncSetAttribute(gemm128, cudaFuncAttributeMaxDynamicSharedMemorySize, GEMM_SMEM);
    cudaFuncSetAttribute(gemm256, cudaFuncAttributeMaxDynamicSharedMemorySize, GEMM_SMEM);

    const int N = Nn, E = Ee, G = Gg;
    const int NB = (N + 63) / 64;
    const int NT = (N + 255) / 256;
    const int ET = (E + 255) / 256;
    const int GB = 1024;
    const int NSCAN = (N + 1023) / 1024;
    const float invN = 1.f/N;

    // stat instance slices
    float* stX  = p_stats + 0*512;   // colstats(x)
    float* stH0 = p_stats + 1*512;   // gemm0 epilogue (h)
    float* stH1 = p_stats + 2*512;   // gather l0
    float* stH2 = p_stats + 3*512;   // gather l1
    float* stNA = p_stats + 4*512;   // colstats2

    cudaStream_t sA;
    cudaStreamCreateWithFlags(&sA, cudaStreamNonBlocking);
    cudaEvent_t evF1, evJ1, evF2, evJ2;
    cudaEventCreateWithFlags(&evF1, cudaEventDisableTiming);
    cudaEventCreateWithFlags(&evJ1, cudaEventDisableTiming);
    cudaEventCreateWithFlags(&evF2, cudaEventDisableTiming);
    cudaEventCreateWithFlags(&evJ2, cudaEventDisableTiming);

    // zero ALL stat buffers for this replay (cheap, ordered before colstats)
    cudaMemsetAsync(p_stats, 0, 5*512*sizeof(float));

    // ==== FORK 1: CSR build on sA ====
    cudaEventRecord(evF1, 0);
    cudaStreamWaitEvent(sA, evF1, 0);
    init_kernel<<<NT,256,0,sA>>>(p_disU, p_deg01, p_cnt, N);
    deg_hist<<<ET,256,0,sA>>>(esrc, edst, p_disU, p_cnt, E);
    scan_block<<<NSCAN,1024,0,sA>>>(p_cnt, p_incl, p_bsum, N);
    scan_tops<<<1,32,0,sA>>>(p_bsum, NSCAN);
    make_rowptr<<<NT,256,0,sA>>>(p_cnt, p_incl, p_bsum, p_rowptr, p_cursor, p_disU, N, E);
    fill_csr<<<ET,256,0,sA>>>(esrc, edst, p_cursor, p_csrc, p_pos, E);
    cudaEventRecord(evJ1, sA);

    // main chain: stats(x) -> gemm0 (finalizes per block, h-stats fused)
    colstats<<<512,256>>>(x, N, stX);
    gemm128<<<NB,256,GEMM_SMEM>>>(x, stX, invN, W_feat, p_h, stH0, nullptr, N, 1);

    // JOIN 1 (layer GEMM output is dis-scaled -> needs disU; gather needs CSR)
    cudaStreamWaitEvent(0, evJ1, 0);
    gemm128<<<NB,256,GEMM_SMEM>>>(p_h, stH0, invN, conv_Ws, p_t, nullptr,
                                  p_disU, N, 0);

    // ---- GCN layers ----
    gather128<<<GB,256>>>(p_t, p_rowptr, p_csrc, p_disU, conv_bs, p_h, stH1,
                          nullptr, nullptr, nullptr, nullptr, N, 1);
    gemm128<<<NB,256,GEMM_SMEM>>>(p_h, stH1, invN, conv_Ws + 128*128, p_t, nullptr,
                                  p_disU, N, 0);
    gather128<<<GB,256>>>(p_t, p_rowptr, p_csrc, p_disU, conv_bs + 128, p_h, stH2,
                          nullptr, nullptr, nullptr, nullptr, N, 1);
    gemm128<<<NB,256,GEMM_SMEM>>>(p_h, stH2, invN, conv_Ws + 2*128*128, p_t, nullptr,
                                  p_disU, N, 0);
    gather128<<<GB,256>>>(p_t, p_rowptr, p_csrc, p_disU, conv_bs + 2*128, p_h, nullptr,
                          eW, naW, p_epro, p_t2, N, 1);

    // ==== FORK 2: edge attention on sA ====
    cudaEventRecord(evF2, 0);
    cudaStreamWaitEvent(sA, evF2, 0);
    edge_att_kernel<<<ET,256,0,sA>>>(esrc, edst, p_pos, p_epro, eb, p_eperm, p_deg01, E);
    rsqrt_arr<<<(2*N+255)/256,256,0,sA>>>((float*)p_deg01, 2*N);
    cudaMemsetAsync(p_cat, 0, Gg*256*sizeof(float), sA);
    cudaEventRecord(evJ2, sA);

    // main: node attention + XC/XO stats (finalize+bias merged)
    natt_gather<<<NT,256>>>(p_t2, p_rowptr, p_csrc, p_disU, nab, p_natt, N);
    colstats2<<<512,256>>>(p_h, p_natt, N, stNA);
    finalize2bias<<<2,128>>>(stNA, invN, p_mean, p_rstd, xcW, xoW, p_bias2);

    // JOIN 2 (gemm256 pre-scales rows by deg01; gather2 needs eperm + zeroed cat)
    cudaStreamWaitEvent(0, evJ2, 0);
    gemm256<<<NB,256,GEMM_SMEM>>>(p_h, p_natt, p_rstd, xcW, xoW, p_bias2,
                                  p_deg01, p_t, p_t2b, N);
    gather2<<<GB,256>>>(p_t, p_t2b, p_rowptr, p_csrc, p_deg01, p_eperm,
                        xcb, xob, batch, p_cat, N);

    // ---- heads ----
    head_stats<<<256,128>>>(p_cat, 256, G, p_mean, p_rstd);
    dim3 hg1(G, 3);
    head_gemm1<<<hg1,128>>>(p_cat, p_mean, p_rstd, cW1, cb1, oW1, ob1,
                            coW1, cob1, p_hd);
    head_stats3<<<384,128>>>(p_hd, G, p_mean, p_rstd);
    dim3 hg2(G, 3);
    head_gemm2_lsm<<<hg2,128>>>(p_hd, p_mean, p_rstd, cW2, cb2, oW2, ob2,
                                coW2, cob2, out);

    cudaEventDestroy(evF1);
    cudaEventDestroy(evJ1);
    cudaEventDestroy(evF2);
    cudaEventDestroy(evJ2);
    cudaStreamDestroy(sA);
}

// round 16
// speedup vs baseline: 1.1640x; 1.0198x over previous
#include <cuda_runtime.h>
#include <math.h>

#define Nn 50000
#define Ee 400000
#define Hh 128
#define Gg 512
#define COUT 10

typedef unsigned long long u64;

static constexpr float EPSBN = 1e-5f;
static constexpr float BNB   = 1e-4f;

#define GDC_WAIT()   asm volatile("griddepcontrol.wait;" ::: "memory")
#define GDC_LAUNCH() asm volatile("griddepcontrol.launch_dependents;" ::: "memory")

// ---------------- scratch (static device allocations) ----------------
__device__ float g_h[Nn*Hh];
__device__ float g_t[Nn*Hh];
__device__ float g_t2b[Nn*Hh];
__device__ float g_stats[5*512];
__device__ float g_mean[512];
__device__ float g_rstd[512];
__device__ float g_disU[Nn];
__device__ float2 g_deg01[Nn];
__device__ float g_epro[Nn*4];
__device__ float g_t2[Nn*2];
__device__ float g_natt[Nn*2];
__device__ float g_eperm[Ee*2];
__device__ float g_bias2[256];
__device__ float g_cat[Gg*256];
__device__ float g_hd[3*Gg*128];
// CSR by destination
__device__ int g_cnt[Nn];
__device__ int g_incl[Nn];
__device__ int g_bsum[64];
__device__ int g_rowptr[Nn+1];
__device__ int g_cursor[Nn];
__device__ int g_csrc[Ee];
__device__ int g_pos[Ee];

// ---------------- small utility kernels ----------------
__global__ void init_kernel(float* disU, float2* deg01, int* cnt, int n) {
    int i = blockIdx.x*blockDim.x + threadIdx.x;
    if (i < n) { disU[i] = 1.f; deg01[i] = make_float2(1.f, 1.f); cnt[i] = 0; }
}

__global__ void deg_hist(const int* __restrict__ src, const int* __restrict__ dst,
                         float* degU, int* cnt, int E) {
    int i = blockIdx.x*blockDim.x + threadIdx.x;
    if (i < E) {
        atomicAdd(&degU[src[i]], 1.0f);
        atomicAdd(&cnt[dst[i]], 1);
    }
}

__global__ void rsqrt_arr(float* p, int n) {
    int i = blockIdx.x*blockDim.x + threadIdx.x;
    if (i < n) p[i] = rsqrtf(p[i]);
}

// ---------------- CSR build ----------------
__global__ void scan_block(const int* __restrict__ cnt, int* incl, int* bsum, int n) {
    __shared__ int sm[1024];
    int i = blockIdx.x*1024 + threadIdx.x;
    sm[threadIdx.x] = (i < n) ? cnt[i] : 0;
    __syncthreads();
    for (int off = 1; off < 1024; off <<= 1) {
        int t = (threadIdx.x >= off) ? sm[threadIdx.x - off] : 0;
        __syncthreads();
        sm[threadIdx.x] += t;
        __syncthreads();
    }
    if (i < n) incl[i] = sm[threadIdx.x];
    if (threadIdx.x == 1023) bsum[blockIdx.x] = sm[1023];
}

__global__ void scan_tops(int* bsum, int nb) {
    int lane = threadIdx.x;
    int v0 = (lane < nb) ? bsum[lane] : 0;
    int v1 = (32 + lane < nb) ? bsum[32 + lane] : 0;
    #pragma unroll
    for (int o = 1; o < 32; o <<= 1) {
        int t = __shfl_up_sync(0xffffffffu, v0, o);
        if (lane >= o) v0 += t;
    }
    int tot0 = __shfl_sync(0xffffffffu, v0, 31);
    #pragma unroll
    for (int o = 1; o < 32; o <<= 1) {
        int t = __shfl_up_sync(0xffffffffu, v1, o);
        if (lane >= o) v1 += t;
    }
    v1 += tot0;
    if (lane < nb) bsum[lane] = v0;
    if (32 + lane < nb) bsum[32 + lane] = v1;
}

__global__ void make_rowptr(const int* __restrict__ cnt, const int* __restrict__ incl,
                            const int* __restrict__ bsum,
                            int* rowptr, int* cursor, float* disU, int n, int E) {
    int i = blockIdx.x*blockDim.x + threadIdx.x;
    if (i < n) {
        int b = i >> 10;
        int ex = incl[i] - cnt[i] + ((b > 0) ? bsum[b-1] : 0);
        rowptr[i] = ex;
        cursor[i] = ex;
        disU[i] = rsqrtf(disU[i]);
    }
    if (i == 0) rowptr[n] = E;
}

__global__ void fill_csr(const int* __restrict__ src, const int* __restrict__ dst,
                         int* cursor, int* csrc, int* pos, int E) {
    int e = blockIdx.x*blockDim.x + threadIdx.x;
    if (e < E) {
        int p = atomicAdd(&cursor[dst[e]], 1);
        csrc[p] = src[e];
        pos[e] = p;
    }
}

// ---------------- BatchNorm stats (accumulate only; consumers finalize) ----------------
__global__ void colstats(const float* __restrict__ A, int n, float* sums) {
    GDC_WAIT();
    long total  = (long)n * 128;
    long stride = (long)gridDim.x * blockDim.x;
    long i0     = (long)blockIdx.x*blockDim.x + threadIdx.x;
    if (i0 < total) {
        int c = (int)(i0 % 128);
        float s0 = 0.f, s1 = 0.f;
        for (long i = i0; i < total; i += stride) {
            int r = (int)(i / 128);
            float v = A[(long)r*128 + c];
            s0 += v; s1 += v*v;
        }
        atomicAdd(&sums[c], s0);
        atomicAdd(&sums[128+c], s1);
    }
    GDC_LAUNCH();
}

__global__ void colstats2(const float* __restrict__ A, const float* __restrict__ natt,
                          int n, float* sums) {
    GDC_WAIT();
    long total  = (long)n * 128;
    long stride = (long)gridDim.x * blockDim.x;
    long i0     = (long)blockIdx.x*blockDim.x + threadIdx.x;
    if (i0 < total) {
        int c = (int)(i0 % 128);
        float s00=0.f, s01=0.f, s10=0.f, s11=0.f;
        for (long i = i0; i < total; i += stride) {
            int r = (int)(i / 128);
            float v = A[(long)r*128 + c];
            float v0 = v * natt[r*2+0];
            float v1 = v * natt[r*2+1];
            s00 += v0; s01 += v0*v0;
            s10 += v1; s11 += v1*v1;
        }
        atomicAdd(&sums[c], s00);
        atomicAdd(&sums[128+c], s01);
        atomicAdd(&sums[256+c], s10);
        atomicAdd(&sums[384+c], s11);
    }
    GDC_LAUNCH();
}

// merged finalize (both natt channels) + BN-folded bias rows
__global__ void finalize2bias(const float* __restrict__ sums, float inv_n,
                              float* __restrict__ mean, float* __restrict__ rstd,
                              const float* __restrict__ xcW, const float* __restrict__ xoW,
                              float* __restrict__ bias2) {
    __shared__ float coef[128];
    GDC_WAIT();
    int ch = blockIdx.x;
    int t = threadIdx.x;
    float s0 = sums[ch*256 + t], s1 = sums[ch*256 + 128 + t];
    float m = s0*inv_n;
    float var = s1*inv_n - m*m;
    float rs = rsqrtf(var + EPSBN);
    mean[ch*128 + t] = m;
    rstd[ch*128 + t] = rs;
    coef[t] = BNB - m*rs;
    __syncthreads();
    const float* W = ch ? xoW : xcW;
    float acc = 0.f;
    for (int k = 0; k < 128; k++) acc += coef[k]*W[k*128+t];
    bias2[ch*128 + t] = acc;
    GDC_LAUNCH();
}

__global__ void head_stats(const float* __restrict__ A, int lda, int n,
                           float* mean, float* rstd) {
    __shared__ float s0s[4], s1s[4];
    GDC_WAIT();
    int c = blockIdx.x;
    int lane = threadIdx.x & 31, warp = threadIdx.x >> 5;
    float s0 = 0.f, s1 = 0.f;
    for (int r = threadIdx.x; r < n; r += blockDim.x) {
        float v = A[r*lda + c];
        s0 += v; s1 += v*v;
    }
    #pragma unroll
    for (int o = 16; o; o >>= 1) {
        s0 += __shfl_xor_sync(0xffffffffu, s0, o);
        s1 += __shfl_xor_sync(0xffffffffu, s1, o);
    }
    if (lane == 0) { s0s[warp] = s0; s1s[warp] = s1; }
    __syncthreads();
    if (threadIdx.x == 0) {
        float t0 = 0.f, t1 = 0.f;
        for (int w = 0; w < 4; w++) { t0 += s0s[w]; t1 += s1s[w]; }
        float m = t0 / n;
        float var = t1 / n - m*m;
        mean[c] = m;
        rstd[c] = rsqrtf(var + EPSBN);
    }
    GDC_LAUNCH();
}

__global__ void head_stats3(const float* __restrict__ hd, int n,
                            float* mean, float* rstd) {
    __shared__ float s0s[4], s1s[4];
    GDC_WAIT();
    int cg = blockIdx.x;
    int head = cg >> 7, c = cg & 127;
    const float* A = hd + head*Gg*128;
    int lane = threadIdx.x & 31, warp = threadIdx.x >> 5;
    float s0 = 0.f, s1 = 0.f;
    for (int r = threadIdx.x; r < n; r += blockDim.x) {
        float v = A[r*128 + c];
        s0 += v; s1 += v*v;
    }
    #pragma unroll
    for (int o = 16; o; o >>= 1) {
        s0 += __shfl_xor_sync(0xffffffffu, s0, o);
        s1 += __shfl_xor_sync(0xffffffffu, s1, o);
    }
    if (lane == 0) { s0s[warp] = s0; s1s[warp] = s1; }
    __syncthreads();
    if (threadIdx.x == 0) {
        float t0 = 0.f, t1 = 0.f;
        for (int w = 0; w < 4; w++) { t0 += s0s[w]; t1 += s1s[w]; }
        float m = t0 / n;
        float var = t1 / n - m*m;
        mean[cg] = m;
        rstd[cg] = rsqrtf(var + EPSBN);
    }
    GDC_LAUNCH();
}

// ---------------- big GEMM (f32x2 FMA, BM=64, K-chunked, 3 CTAs/SM, PDL) ----------------
static constexpr int GEMM_SMEM = (64*128 + 64*128 + 256) * 4;

__global__ __launch_bounds__(256, 3) void gemm128(
    const float* __restrict__ A,
    const float* __restrict__ sums_in, float inv_n,
    const float* __restrict__ W,
    float* __restrict__ out,
    float* __restrict__ sums_out,
    const float* __restrict__ rowscale,
    int n, int act)
{
    extern __shared__ float sm[];
    float* As = sm;                    // [64][128]
    float* Ws = sm + 64*128;           // [64][128] W chunk
    float* smean = sm + 2*64*128;      // [128]
    float* srstd = smean + 128;        // [128]
    int tid  = threadIdx.x;
    int row0 = blockIdx.x * 64;

    const float4* Wg = (const float4*)W;
    float4* Ws4 = (float4*)Ws;

    // prologue: W chunk 0 (input-constant, runs before grid dependency resolves)
    #pragma unroll 2
    for (int i = tid; i < 64*32; i += 256)
        Ws4[i] = Wg[(i >> 5)*32 + (i & 31)];

    GDC_WAIT();

    if (tid < 128) {
        float s0 = sums_in[tid], s1 = sums_in[128+tid];
        float m = s0*inv_n;
        float var = s1*inv_n - m*m;
        smean[tid] = m;
        srstd[tid] = rsqrtf(var + EPSBN);
    }
    __syncthreads();

    #pragma unroll 2
    for (int i = tid; i < 64*32; i += 256) {
        int r = i >> 5, cq = i & 31;
        int gr = row0 + r;
        float4 v = make_float4(0.f,0.f,0.f,0.f);
        if (gr < n) {
            v = ((const float4*)A)[gr*32 + cq];
            int c = cq*4;
            v.x = (v.x - smean[c+0])*srstd[c+0] + BNB;
            v.y = (v.y - smean[c+1])*srstd[c+1] + BNB;
            v.z = (v.z - smean[c+2])*srstd[c+2] + BNB;
            v.w = (v.w - smean[c+3])*srstd[c+3] + BNB;
        }
        ((float4*)As)[i] = v;
    }

    int tc = tid & 15, tr = tid >> 4;
    int r0 = tr*4;
    int c0 = tc*4, c1 = 64 + tc*4;

    u64 accp[4][4];
    #pragma unroll
    for (int i = 0; i < 4; i++)
        #pragma unroll
        for (int j = 0; j < 4; j++) accp[i][j] = 0ull;

    #pragma unroll
    for (int kc = 0; kc < 128; kc += 64) {
        if (kc > 0) {
            __syncthreads();
            #pragma unroll 2
            for (int i = tid; i < 64*32; i += 256)
                Ws4[i] = Wg[(kc + (i >> 5))*32 + (i & 31)];
        }
        __syncthreads();

        for (int k = 0; k < 64; k += 4) {
            float4 a4[4];
            #pragma unroll
            for (int i = 0; i < 4; i++)
                a4[i] = *(const float4*)&As[(r0+i)*128 + kc + k];
            #pragma unroll
            for (int kk = 0; kk < 4; kk++) {
                ulonglong2 w01 = *(const ulonglong2*)&Ws[(k+kk)*128 + c0];
                ulonglong2 w23 = *(const ulonglong2*)&Ws[(k+kk)*128 + c1];
                u64 wp0 = w01.x, wp1 = w01.y, wp2 = w23.x, wp3 = w23.y;
                #pragma unroll
                for (int i = 0; i < 4; i++) {
                    float a = ((const float*)&a4[i])[kk];
                    unsigned int ai = __float_as_uint(a);
                    u64 ap;
                    asm("mov.b64 %0, {%1, %1};" : "=l"(ap) : "r"(ai));
                    asm("fma.rn.f32x2 %0, %1, %2, %0;" : "+l"(accp[i][0]) : "l"(ap), "l"(wp0));
                    asm("fma.rn.f32x2 %0, %1, %2, %0;" : "+l"(accp[i][1]) : "l"(ap), "l"(wp1));
                    asm("fma.rn.f32x2 %0, %1, %2, %0;" : "+l"(accp[i][2]) : "l"(ap), "l"(wp2));
                    asm("fma.rn.f32x2 %0, %1, %2, %0;" : "+l"(accp[i][3]) : "l"(ap), "l"(wp3));
                }
            }
        }
    }

    float t0[8], t1[8];
    #pragma unroll
    for (int j = 0; j < 8; j++) { t0[j] = 0.f; t1[j] = 0.f; }

    float4* O4 = (float4*)out;
    #pragma unroll
    for (int i = 0; i < 4; i++) {
        int gr = row0 + r0 + i;
        if (gr < n) {
            float o[8];
            #pragma unroll
            for (int j = 0; j < 4; j++) {
                unsigned int lo, hi;
                asm("mov.b64 {%0, %1}, %2;" : "=r"(lo), "=r"(hi) : "l"(accp[i][j]));
                o[2*j]   = __uint_as_float(lo);
                o[2*j+1] = __uint_as_float(hi);
            }
            if (act == 1) {
                #pragma unroll
                for (int j = 0; j < 8; j++) o[j] = fmaxf(o[j], 0.f);
            }
            if (rowscale) {
                float rs = rowscale[gr];
                #pragma unroll
                for (int j = 0; j < 8; j++) o[j] *= rs;
            }
            if (sums_out) {
                #pragma unroll
                for (int j = 0; j < 8; j++) { t0[j] += o[j]; t1[j] += o[j]*o[j]; }
            }
            O4[gr*32 + tc]      = make_float4(o[0], o[1], o[2], o[3]);
            O4[gr*32 + 16 + tc] = make_float4(o[4], o[5], o[6], o[7]);
        }
    }

    if (sums_out) {
        __syncthreads();
        float* ss = sm;
        ss[tid] = 0.f;
        __syncthreads();
        #pragma unroll
        for (int j = 0; j < 4; j++) {
            atomicAdd(&ss[c0+j],     t0[j]);   atomicAdd(&ss[128+c0+j], t1[j]);
            atomicAdd(&ss[c1+j],     t0[4+j]); atomicAdd(&ss[128+c1+j], t1[4+j]);
        }
        __syncthreads();
        atomicAdd(&sums_out[tid], ss[tid]);
    }
    GDC_LAUNCH();
}

// ---------------- merged XC/XO GEMM (K-chunked, rows pre-scaled by deg01) ----------------
__global__ __launch_bounds__(256, 3) void gemm256(
    const float* __restrict__ h,
    const float* __restrict__ natt,
    const float* __restrict__ rstd2,
    const float* __restrict__ xcW, const float* __restrict__ xoW,
    const float* __restrict__ bias2,
    const float2* __restrict__ deg01,
    float* __restrict__ outc, float* __restrict__ outo, int n)
{
    extern __shared__ float sm[];
    float* As = sm;               // [64][128]
    float* Ws = sm + 64*128;      // [64][128] chunk
    int tid  = threadIdx.x;
    int row0 = blockIdx.x * 64;

    GDC_WAIT();

    #pragma unroll 2
    for (int i = tid; i < 64*32; i += 256) {
        int r = i >> 5, cq = i & 31;
        int gr = row0 + r;
        float4 v = (gr < n) ? ((const float4*)h)[gr*32 + cq]
                            : make_float4(0.f,0.f,0.f,0.f);
        ((float4*)As)[i] = v;
    }

    int tc = tid & 15, tr = tid >> 4;
    int r0 = tr*4;
    int c0 = tc*4, c1 = 64 + tc*4;

    #pragma unroll
    for (int half = 0; half < 2; half++) {
        const float* W  = half ? xoW : xcW;
        const float* rs = rstd2 + half*128;
        const float* bs = bias2 + half*128;
        float* out = half ? outo : outc;

        float nv[4], dsc[4];
        #pragma unroll
        for (int i = 0; i < 4; i++) {
            int gr = row0 + r0 + i;
            nv[i] = (gr < n) ? natt[gr*2 + half] : 0.f;
            float2 d = (gr < n) ? deg01[gr] : make_float2(0.f, 0.f);
            dsc[i] = half ? d.y : d.x;
        }

        u64 accp[4][4];
        #pragma unroll
        for (int i = 0; i < 4; i++)
            #pragma unroll
            for (int j = 0; j < 4; j++) accp[i][j] = 0ull;

        #pragma unroll
        for (int kc = 0; kc < 128; kc += 64) {
            __syncthreads();
            #pragma unroll 2
            for (int i = tid; i < 64*32; i += 256) {
                int r = kc + (i >> 5);
                float4 w = ((const float4*)W)[r*32 + (i & 31)];
                float sc = rs[r];
                w.x *= sc; w.y *= sc; w.z *= sc; w.w *= sc;
                ((float4*)Ws)[i] = w;
            }
            __syncthreads();

            for (int k = 0; k < 64; k += 4) {
                float4 a4[4];
                #pragma unroll
                for (int i = 0; i < 4; i++)
                    a4[i] = *(const float4*)&As[(r0+i)*128 + kc + k];
                #pragma unroll
                for (int kk = 0; kk < 4; kk++) {
                    ulonglong2 w01 = *(const ulonglong2*)&Ws[(k+kk)*128 + c0];
                    ulonglong2 w23 = *(const ulonglong2*)&Ws[(k+kk)*128 + c1];
                    u64 wp0 = w01.x, wp1 = w01.y, wp2 = w23.x, wp3 = w23.y;
                    #pragma unroll
                    for (int i = 0; i < 4; i++) {
                        float a = ((const float*)&a4[i])[kk] * nv[i];
                        unsigned int ai = __float_as_uint(a);
                        u64 ap;
                        asm("mov.b64 %0, {%1, %1};" : "=l"(ap) : "r"(ai));
                        asm("fma.rn.f32x2 %0, %1, %2, %0;" : "+l"(accp[i][0]) : "l"(ap), "l"(wp0));
                        asm("fma.rn.f32x2 %0, %1, %2, %0;" : "+l"(accp[i][1]) : "l"(ap), "l"(wp1));
                        asm("fma.rn.f32x2 %0, %1, %2, %0;" : "+l"(accp[i][2]) : "l"(ap), "l"(wp2));
                        asm("fma.rn.f32x2 %0, %1, %2, %0;" : "+l"(accp[i][3]) : "l"(ap), "l"(wp3));
                    }
                }
            }
        }

        float4 b0 = *(const float4*)&bs[c0];
        float4 b1 = *(const float4*)&bs[c1];
        float4* O4 = (float4*)out;
        #pragma unroll
        for (int i = 0; i < 4; i++) {
            int gr = row0 + r0 + i;
            if (gr < n) {
                float o[8];
                #pragma unroll
                for (int j = 0; j < 4; j++) {
                    unsigned int lo, hi;
                    asm("mov.b64 {%0, %1}, %2;" : "=r"(lo), "=r"(hi) : "l"(accp[i][j]));
                    o[2*j]   = __uint_as_float(lo);
                    o[2*j+1] = __uint_as_float(hi);
                }
                float d = dsc[i];
                O4[gr*32 + tc]      = make_float4((o[0]+b0.x)*d, (o[1]+b0.y)*d,
                                                  (o[2]+b0.z)*d, (o[3]+b0.w)*d);
                O4[gr*32 + 16 + tc] = make_float4((o[4]+b1.x)*d, (o[5]+b1.y)*d,
                                                  (o[6]+b1.z)*d, (o[7]+b1.w)*d);
            }
        }
    }
    GDC_LAUNCH();
}

// ---------------- CSR gather conv (rows pre-scaled: pure row-add loop) ----------------
__global__ __launch_bounds__(256) void gather128(
    const float* __restrict__ t,
    const int* __restrict__ rowptr, const int* __restrict__ csrc,
    const float* __restrict__ dis,
    const float* __restrict__ bias,
    float* __restrict__ out, float* __restrict__ sums,
    const float* __restrict__ eWg, const float* __restrict__ naWg,
    float* __restrict__ epro, float* __restrict__ t2,
    int n, int act)
{
    __shared__ float sEW[512];
    __shared__ float sNA[256];
    int lane = threadIdx.x & 31;
    // prologue: weight tables + bias (input constants)
    if (eWg) {
        for (int i = threadIdx.x; i < 512; i += 256) sEW[i] = eWg[i];
        for (int i = threadIdx.x; i < 256; i += 256) sNA[i] = naWg[i];
    }
    float4 bb = bias ? ((const float4*)bias)[lane] : make_float4(0.f,0.f,0.f,0.f);

    GDC_WAIT();
    if (eWg) __syncthreads();

    int w0 = (blockIdx.x*blockDim.x + threadIdx.x) >> 5;
    int nw = (gridDim.x*blockDim.x) >> 5;
    float ls0[4] = {0.f,0.f,0.f,0.f}, ls1[4] = {0.f,0.f,0.f,0.f};
    const float4* t4 = (const float4*)t;

    for (int v = w0; v < n; v += nw) {
        float dv = dis[v];
        float4 acc = t4[v*32 + lane];
        int p = rowptr[v], en = rowptr[v+1];
        for (; p + 4 <= en; p += 4) {
            int s0 = __ldg(&csrc[p+0]);
            int s1 = __ldg(&csrc[p+1]);
            int s2 = __ldg(&csrc[p+2]);
            int s3 = __ldg(&csrc[p+3]);
            float4 x0 = t4[s0*32 + lane];
            float4 x1 = t4[s1*32 + lane];
            float4 x2 = t4[s2*32 + lane];
            float4 x3 = t4[s3*32 + lane];
            acc.x += x0.x + x1.x + x2.x + x3.x;
            acc.y += x0.y + x1.y + x2.y + x3.y;
            acc.z += x0.z + x1.z + x2.z + x3.z;
            acc.w += x0.w + x1.w + x2.w + x3.w;
        }
        for (; p < en; p++) {
            int s = __ldg(&csrc[p]);
            float4 x = t4[s*32 + lane];
            acc.x += x.x; acc.y += x.y; acc.z += x.z; acc.w += x.w;
        }
        acc.x = acc.x*dv + bb.x; acc.y = acc.y*dv + bb.y;
        acc.z = acc.z*dv + bb.z; acc.w = acc.w*dv + bb.w;
        if (act == 1) {
            acc.x = fmaxf(acc.x, 0.f); acc.y = fmaxf(acc.y, 0.f);
            acc.z = fmaxf(acc.z, 0.f); acc.w = fmaxf(acc.w, 0.f);
        }
        if (sums) {
            ls0[0]+=acc.x; ls1[0]+=acc.x*acc.x;
            ls0[1]+=acc.y; ls1[1]+=acc.y*acc.y;
            ls0[2]+=acc.z; ls1[2]+=acc.z*acc.z;
            ls0[3]+=acc.w; ls1[3]+=acc.w*acc.w;
        }
        ((float4*)out)[v*32 + lane] = acc;

        if (eWg) {
            float hx[4] = {acc.x, acc.y, acc.z, acc.w};
            float p0=0,p1=0,q0=0,q1=0,u0=0,u1=0;
            #pragma unroll
            for (int i = 0; i < 4; i++) {
                int k = lane*4 + i; float xv = hx[i];
                p0 += xv*sEW[k*2+0];        p1 += xv*sEW[k*2+1];
                q0 += xv*sEW[(128+k)*2+0];  q1 += xv*sEW[(128+k)*2+1];
                u0 += xv*sNA[k*2+0];        u1 += xv*sNA[k*2+1];
            }
            #pragma unroll
            for (int o = 16; o; o >>= 1) {
                p0 += __shfl_xor_sync(0xffffffffu, p0, o);
                p1 += __shfl_xor_sync(0xffffffffu, p1, o);
                q0 += __shfl_xor_sync(0xffffffffu, q0, o);
                q1 += __shfl_xor_sync(0xffffffffu, q1, o);
                u0 += __shfl_xor_sync(0xffffffffu, u0, o);
                u1 += __shfl_xor_sync(0xffffffffu, u1, o);
            }
            if (lane == 0) {
                epro[v*4+0]=p0; epro[v*4+1]=p1; epro[v*4+2]=q0; epro[v*4+3]=q1;
                t2[v*2+0]=u0*dv; t2[v*2+1]=u1*dv;
            }
        }
    }

    if (sums) {
        __shared__ float ss[256];
        ss[threadIdx.x] = 0.f;
        __syncthreads();
        #pragma unroll
        for (int j = 0; j < 4; j++) {
            atomicAdd(&ss[lane*4+j],     ls0[j]);
            atomicAdd(&ss[128+lane*4+j], ls1[j]);
        }
        __syncthreads();
        atomicAdd(&sums[threadIdx.x], ss[threadIdx.x]);
    }
    GDC_LAUNCH();
}

// fused XC+XO gather + conv-bias + ELU + pool (rows pre-scaled by deg01)
__global__ __launch_bounds__(256) void gather2(
    const float* __restrict__ tc_, const float* __restrict__ to_,
    const int* __restrict__ rowptr, const int* __restrict__ csrc,
    const float2* __restrict__ dis01,
    const float* __restrict__ eperm,
    const float* __restrict__ xcb, const float* __restrict__ xob,
    const int* __restrict__ batch,
    float* __restrict__ cat, int n)
{
    int lane = threadIdx.x & 31;
    float4 bc = ((const float4*)xcb)[lane];
    float4 bo = ((const float4*)xob)[lane];
    GDC_WAIT();

    int w0 = (blockIdx.x*blockDim.x + threadIdx.x) >> 5;
    int nw = (gridDim.x*blockDim.x) >> 5;
    const float4* tc4 = (const float4*)tc_;
    const float4* to4 = (const float4*)to_;

    for (int v = w0; v < n; v += nw) {
        float2 dv = dis01[v];
        float4 ac = tc4[v*32 + lane];
        float4 ao = to4[v*32 + lane];
        int p = rowptr[v], en = rowptr[v+1];
        for (; p + 2 <= en; p += 2) {
            int s0 = __ldg(&csrc[p+0]);
            int s1 = __ldg(&csrc[p+1]);
            float2 ea0 = __ldg((const float2*)&eperm[(p+0)*2]);
            float2 ea1 = __ldg((const float2*)&eperm[(p+1)*2]);
            float4 xc0 = tc4[s0*32 + lane];
            float4 xo0 = to4[s0*32 + lane];
            float4 xc1 = tc4[s1*32 + lane];
            float4 xo1 = to4[s1*32 + lane];
            ac.x += ea0.x*xc0.x + ea1.x*xc1.x; ac.y += ea0.x*xc0.y + ea1.x*xc1.y;
            ac.z += ea0.x*xc0.z + ea1.x*xc1.z; ac.w += ea0.x*xc0.w + ea1.x*xc1.w;
            ao.x += ea0.y*xo0.x + ea1.y*xo1.x; ao.y += ea0.y*xo0.y + ea1.y*xo1.y;
            ao.z += ea0.y*xo0.z + ea1.y*xo1.z; ao.w += ea0.y*xo0.w + ea1.y*xo1.w;
        }
        for (; p < en; p++) {
            int s = __ldg(&csrc[p]);
            float2 ea = __ldg((const float2*)&eperm[p*2]);
            float4 xc = tc4[s*32 + lane];
            float4 xo = to4[s*32 + lane];
            ac.x += ea.x*xc.x; ac.y += ea.x*xc.y; ac.z += ea.x*xc.z; ac.w += ea.x*xc.w;
            ao.x += ea.y*xo.x; ao.y += ea.y*xo.y; ao.z += ea.y*xo.z; ao.w += ea.y*xo.w;
        }
        float zc[4] = {ac.x*dv.x+bc.x, ac.y*dv.x+bc.y, ac.z*dv.x+bc.z, ac.w*dv.x+bc.w};
        float zo[4] = {ao.x*dv.y+bo.x, ao.y*dv.y+bo.y, ao.z*dv.y+bo.z, ao.w*dv.y+bo.w};
        #pragma unroll
        for (int j = 0; j < 4; j++) {
            zc[j] = (zc[j] > 0.f) ? zc[j] : expm1f(zc[j]);
            zo[j] = (zo[j] > 0.f) ? zo[j] : expm1f(zo[j]);
        }
        int g = __ldg(&batch[v]);
        float* pc = cat + g*256 + lane*4;
        float* po = pc + 128;
        asm volatile("red.global.add.v4.f32 [%0], {%1, %2, %3, %4};"
                     :: "l"(pc), "f"(zc[0]), "f"(zc[1]), "f"(zc[2]), "f"(zc[3]) : "memory");
        asm volatile("red.global.add.v4.f32 [%0], {%1, %2, %3, %4};"
                     :: "l"(po), "f"(zo[0]), "f"(zo[1]), "f"(zo[2]), "f"(zo[3]) : "memory");
    }
    GDC_LAUNCH();
}

// ---------------- attention ----------------
__global__ void edge_att_kernel(const int* __restrict__ src, const int* __restrict__ dst,
                                const int* __restrict__ pos,
                                const float* __restrict__ epro, const float* __restrict__ eb,
                                float* __restrict__ eperm, float2* __restrict__ deg01, int E) {
    int e = blockIdx.x*blockDim.x + threadIdx.x;
    if (e >= E) return;
    int s = src[e], d = dst[e];
    float2 ps = *(const float2*)&epro[s*4];
    float2 qd = *(const float2*)&epro[d*4+2];
    float l0 = ps.x + qd.x + eb[0];
    float l1 = ps.y + qd.y + eb[1];
    float m = fmaxf(l0, l1);
    float e0 = expf(l0 - m), e1 = expf(l1 - m);
    float inv = 1.f/(e0+e1);
    float a0 = e0*inv, a1 = e1*inv;
    int p = pos[e];
    *(float2*)&eperm[p*2] = make_float2(a0, a1);
    asm volatile("red.global.add.v2.f32 [%0], {%1, %2};"
                 :: "l"(&deg01[s]), "f"(a0), "f"(a1) : "memory");
}

// t2 rows pre-scaled by disU; logits = dv*(t2'[v] + sum t2'[s]) + nab
__global__ void natt_gather(const float* __restrict__ t2,
                            const int* __restrict__ rowptr, const int* __restrict__ csrc,
                            const float* __restrict__ disU,
                            const float* __restrict__ nab,
                            float* __restrict__ natt, int n) {
    GDC_WAIT();
    int v = blockIdx.x*blockDim.x + threadIdx.x;
    if (v < n) {
        float dv = disU[v];
        float2 selfv = __ldg((const float2*)&t2[v*2]);
        float a0 = selfv.x, a1 = selfv.y;
        int p = rowptr[v], en = rowptr[v+1];
        for (; p + 4 <= en; p += 4) {
            int s0 = __ldg(&csrc[p+0]);
            int s1 = __ldg(&csrc[p+1]);
            int s2 = __ldg(&csrc[p+2]);
            int s3 = __ldg(&csrc[p+3]);
            float2 x0 = __ldg((const float2*)&t2[s0*2]);
            float2 x1 = __ldg((const float2*)&t2[s1*2]);
            float2 x2 = __ldg((const float2*)&t2[s2*2]);
            float2 x3 = __ldg((const float2*)&t2[s3*2]);
            a0 += x0.x + x1.x + x2.x + x3.x;
            a1 += x0.y + x1.y + x2.y + x3.y;
        }
        for (; p < en; p++) {
            int s = __ldg(&csrc[p]);
            float2 ts = __ldg((const float2*)&t2[s*2]);
            a0 += ts.x;
            a1 += ts.y;
        }
        a0 = a0*dv + nab[0];
        a1 = a1*dv + nab[1];
        float m = fmaxf(a0, a1);
        float e0 = expf(a0 - m), e1 = expf(a1 - m);
        float inv = 1.f/(e0+e1);
        natt[v*2+0] = e0*inv; natt[v*2+1] = e1*inv;
    }
    GDC_LAUNCH();
}

// ---------------- fused heads ----------------
__global__ void head_gemm1(const float* __restrict__ cat,
                           const float* __restrict__ mean, const float* __restrict__ rstd,
                           const float* __restrict__ cW1, const float* __restrict__ cb1,
                           const float* __restrict__ oW1, const float* __restrict__ ob1,
                           const float* __restrict__ coW1, const float* __restrict__ cob1,
                           float* __restrict__ hd) {
    __shared__ float a[256];
    GDC_WAIT();
    int r = blockIdx.x, head = blockIdx.y;
    for (int k = threadIdx.x; k < 256; k += 128)
        a[k] = (cat[r*256 + k] - mean[k]) * rstd[k] + BNB;
    __syncthreads();
    const float* W; const float* b; int K, koff, act;
    if (head == 0)      { W = cW1;  b = cb1;  K = 128; koff = 0;   act = 1; }
    else if (head == 1) { W = oW1;  b = ob1;  K = 128; koff = 128; act = 1; }
    else                { W = coW1; b = cob1; K = 256; koff = 0;   act = 2; }
    int c = threadIdx.x;
    float acc = b[c];
    for (int k = 0; k < K; k++) acc += a[koff + k] * W[k*128 + c];
    if (act == 1) acc = fmaxf(acc, 0.f);
    else {
        acc = (acc > 0.f) ? acc : expm1f(acc);
        acc = (acc > 0.f) ? acc : expm1f(acc);
    }
    hd[(head*Gg + r)*128 + c] = acc;
    GDC_LAUNCH();
}

__global__ void head_gemm2_lsm(const float* __restrict__ hd,
                               const float* __restrict__ mean, const float* __restrict__ rstd,
                               const float* __restrict__ cW2, const float* __restrict__ cb2,
                               const float* __restrict__ oW2, const float* __restrict__ ob2,
                               const float* __restrict__ coW2, const float* __restrict__ cob2,
                               float* __restrict__ out) {
    __shared__ float a[128];
    __shared__ float lg[COUT];
    GDC_WAIT();
    int r = blockIdx.x, head = blockIdx.y;
    int k = threadIdx.x;
    a[k] = (hd[(head*Gg + r)*128 + k] - mean[head*128 + k]) * rstd[head*128 + k] + BNB;
    __syncthreads();
    const float* W = (head == 0) ? cW2 : (head == 1) ? oW2 : coW2;
    const float* b = (head == 0) ? cb2 : (head == 1) ? ob2 : cob2;
    if (k < COUT) {
        float acc = b[k];
        for (int kk = 0; kk < 128; kk++) acc += a[kk] * W[kk*COUT + k];
        lg[k] = acc;
    }
    __syncthreads();
    if (k < COUT) {
        float m = -1e30f;
        #pragma unroll
        for (int i = 0; i < COUT; i++) m = fmaxf(m, lg[i]);
        float s = 0.f;
        #pragma unroll
        for (int i = 0; i < COUT; i++) s += expf(lg[i] - m);
        out[head*Gg*COUT + r*COUT + k] = lg[k] - m - logf(s);
    }
}

// ---------------- PDL launch helper ----------------
template <typename F, typename... Args>
static inline void launch_pdl(F kern, dim3 grid, dim3 block, size_t shm, Args... args) {
    cudaLaunchConfig_t cfg = {};
    cfg.gridDim = grid; cfg.blockDim = block;
    cfg.dynamicSmemBytes = shm; cfg.stream = 0;
    cudaLaunchAttribute at[1];
    at[0].id = cudaLaunchAttributeProgrammaticStreamSerialization;
    at[0].val.programmaticStreamSerializationAllowed = 1;
    cfg.attrs = at; cfg.numAttrs = 1;
    cudaLaunchKernelEx(&cfg, kern, args...);
}

// ---------------- host orchestration ----------------
extern "C" void kernel_launch(void* const* d_in, const int* in_sizes, int n_in,
                              void* d_out, int out_size) {
    const float* x      = (const float*)d_in[0];
    const float* W_feat = (const float*)d_in[1];
    const float* conv_Ws= (const float*)d_in[2];
    const float* conv_bs= (const float*)d_in[3];
    const float* eW     = (const float*)d_in[4];
    const float* eb     = (const float*)d_in[5];
    const float* naW    = (const float*)d_in[6];
    const float* nab    = (const float*)d_in[7];
    const float* xcW    = (const float*)d_in[8];
    const float* xcb    = (const float*)d_in[9];
    const float* xoW    = (const float*)d_in[10];
    const float* xob    = (const float*)d_in[11];
    const float* cW1    = (const float*)d_in[12];
    const float* cb1    = (const float*)d_in[13];
    const float* cW2    = (const float*)d_in[14];
    const float* cb2    = (const float*)d_in[15];
    const float* oW1    = (const float*)d_in[16];
    const float* ob1    = (const float*)d_in[17];
    const float* oW2    = (const float*)d_in[18];
    const float* ob2    = (const float*)d_in[19];
    const float* coW1   = (const float*)d_in[20];
    const float* cob1   = (const float*)d_in[21];
    const float* coW2   = (const float*)d_in[22];
    const float* cob2   = (const float*)d_in[23];
    const int* esrc     = (const int*)d_in[24];
    const int* edst     = (const int*)d_in[25];
    const int* batch    = (const int*)d_in[26];
    float* out = (float*)d_out;

    float *p_h,*p_t,*p_t2b,*p_stats,*p_mean,*p_rstd,*p_disU;
    float *p_epro,*p_t2,*p_natt,*p_eperm,*p_bias2,*p_cat,*p_hd;
    float2* p_deg01;
    int *p_cnt,*p_incl,*p_bsum,*p_rowptr,*p_cursor,*p_csrc,*p_pos;
    cudaGetSymbolAddress((void**)&p_h, g_h);
    cudaGetSymbolAddress((void**)&p_t, g_t);
    cudaGetSymbolAddress((void**)&p_t2b, g_t2b);
    cudaGetSymbolAddress((void**)&p_stats, g_stats);
    cudaGetSymbolAddress((void**)&p_mean, g_mean);
    cudaGetSymbolAddress((void**)&p_rstd, g_rstd);
    cudaGetSymbolAddress((void**)&p_disU, g_disU);
    cudaGetSymbolAddress((void**)&p_deg01, g_deg01);
    cudaGetSymbolAddress((void**)&p_epro, g_epro);
    cudaGetSymbolAddress((void**)&p_t2, g_t2);
    cudaGetSymbolAddress((void**)&p_natt, g_natt);
    cudaGetSymbolAddress((void**)&p_eperm, g_eperm);
    cudaGetSymbolAddress((void**)&p_bias2, g_bias2);
    cudaGetSymbolAddress((void**)&p_cat, g_cat);
    cudaGetSymbolAddress((void**)&p_hd, g_hd);
    cudaGetSymbolAddress((void**)&p_cnt, g_cnt);
    cudaGetSymbolAddress((void**)&p_incl, g_incl);
    cudaGetSymbolAddress((void**)&p_bsum, g_bsum);
    cudaGetSymbolAddress((void**)&p_rowptr, g_rowptr);
    cudaGetSymbolAddress((void**)&p_cursor, g_cursor);
    cudaGetSymbolAddress((void**)&p_csrc, g_csrc);
    cudaGetSymbolAddress((void**)&p_pos, g_pos);

    cudaFuncSetAttribute(gemm128, cudaFuncAttributeMaxDynamicSharedMemorySize, GEMM_SMEM);
    cudaFuncSetAttribute(gemm256, cudaFuncAttributeMaxDynamicSharedMemorySize, GEMM_SMEM);

    const int N = Nn, E = Ee, G = Gg;
    const int NB = (N + 63) / 64;
    const int NT = (N + 255) / 256;
    const int ET = (E + 255) / 256;
    const int GB = 1024;
    const int NSCAN = (N + 1023) / 1024;
    const float invN = 1.f/N;

    float* stX  = p_stats + 0*512;
    float* stH0 = p_stats + 1*512;
    float* stH1 = p_stats + 2*512;
    float* stH2 = p_stats + 3*512;
    float* stNA = p_stats + 4*512;

    cudaStream_t sA;
    cudaStreamCreateWithFlags(&sA, cudaStreamNonBlocking);
    cudaEvent_t evF1, evJ1, evF2, evJ2;
    cudaEventCreateWithFlags(&evF1, cudaEventDisableTiming);
    cudaEventCreateWithFlags(&evJ1, cudaEventDisableTiming);
    cudaEventCreateWithFlags(&evF2, cudaEventDisableTiming);
    cudaEventCreateWithFlags(&evJ2, cudaEventDisableTiming);

    cudaMemsetAsync(p_stats, 0, 5*512*sizeof(float));

    // ==== FORK 1: CSR build on sA ====
    cudaEventRecord(evF1, 0);
    cudaStreamWaitEvent(sA, evF1, 0);
    init_kernel<<<NT,256,0,sA>>>(p_disU, p_deg01, p_cnt, N);
    deg_hist<<<ET,256,0,sA>>>(esrc, edst, p_disU, p_cnt, E);
    scan_block<<<NSCAN,1024,0,sA>>>(p_cnt, p_incl, p_bsum, N);
    scan_tops<<<1,32,0,sA>>>(p_bsum, NSCAN);
    make_rowptr<<<NT,256,0,sA>>>(p_cnt, p_incl, p_bsum, p_rowptr, p_cursor, p_disU, N, E);
    fill_csr<<<ET,256,0,sA>>>(esrc, edst, p_cursor, p_csrc, p_pos, E);
    cudaEventRecord(evJ1, sA);

    // main chain: stats(x) -> gemm0 (PDL pair)
    colstats<<<512,256>>>(x, N, stX);
    launch_pdl(gemm128, dim3(NB), dim3(256), (size_t)GEMM_SMEM,
               x, (const float*)stX, invN, W_feat, p_h, stH0,
               (const float*)nullptr, N, 1);

    // JOIN 1 (needs disU + CSR) — plain launch after event wait
    cudaStreamWaitEvent(0, evJ1, 0);
    gemm128<<<NB,256,GEMM_SMEM>>>(p_h, stH0, invN, conv_Ws, p_t,
                                  (float*)nullptr, p_disU, N, 0);

    // ---- GCN layers (PDL chain) ----
    launch_pdl(gather128, dim3(GB), dim3(256), (size_t)0,
               (const float*)p_t, (const int*)p_rowptr, (const int*)p_csrc,
               (const float*)p_disU, conv_bs, p_h, stH1,
               (const float*)nullptr, (const float*)nullptr,
               (float*)nullptr, (float*)nullptr, N, 1);
    launch_pdl(gemm128, dim3(NB), dim3(256), (size_t)GEMM_SMEM,
               (const float*)p_h, (const float*)stH1, invN, conv_Ws + 128*128,
               p_t, (float*)nullptr, (const float*)p_disU, N, 0);
    launch_pdl(gather128, dim3(GB), dim3(256), (size_t)0,
               (const float*)p_t, (const int*)p_rowptr, (const int*)p_csrc,
               (const float*)p_disU, conv_bs + 128, p_h, stH2,
               (const float*)nullptr, (const float*)nullptr,
               (float*)nullptr, (float*)nullptr, N, 1);
    launch_pdl(gemm128, dim3(NB), dim3(256), (size_t)GEMM_SMEM,
               (const float*)p_h, (const float*)stH2, invN, conv_Ws + 2*128*128,
               p_t, (float*)nullptr, (const float*)p_disU, N, 0);
    launch_pdl(gather128, dim3(GB), dim3(256), (size_t)0,
               (const float*)p_t, (const int*)p_rowptr, (const int*)p_csrc,
               (const float*)p_disU, conv_bs + 2*128, p_h, (float*)nullptr,
               eW, naW, p_epro, p_t2, N, 1);

    // ==== FORK 2: edge attention on sA ====
    cudaEventRecord(evF2, 0);
    cudaStreamWaitEvent(sA, evF2, 0);
    edge_att_kernel<<<ET,256,0,sA>>>(esrc, edst, p_pos, p_epro, eb, p_eperm, p_deg01, E);
    rsqrt_arr<<<(2*N+255)/256,256,0,sA>>>((float*)p_deg01, 2*N);
    cudaMemsetAsync(p_cat, 0, Gg*256*sizeof(float), sA);
    cudaEventRecord(evJ2, sA);

    // main: node attention + XC/XO stats (natt after event record: plain launch)
    natt_gather<<<NT,256>>>(p_t2, p_rowptr, p_csrc, p_disU, nab, p_natt, N);
    launch_pdl(colstats2, dim3(512), dim3(256), (size_t)0,
               (const float*)p_h, (const float*)p_natt, N, stNA);
    launch_pdl(finalize2bias, dim3(2), dim3(128), (size_t)0,
               (const float*)stNA, invN, p_mean, p_rstd, xcW, xoW, p_bias2);

    // JOIN 2 — plain launch after event wait
    cudaStreamWaitEvent(0, evJ2, 0);
    gemm256<<<NB,256,GEMM_SMEM>>>(p_h, p_natt, p_rstd, xcW, xoW, p_bias2,
                                  p_deg01, p_t, p_t2b, N);
    launch_pdl(gather2, dim3(GB), dim3(256), (size_t)0,
               (const float*)p_t, (const float*)p_t2b, (const int*)p_rowptr,
               (const int*)p_csrc, (const float2*)p_deg01, (const float*)p_eperm,
               xcb, xob, batch, p_cat, N);

    // ---- heads (PDL chain) ----
    launch_pdl(head_stats, dim3(256), dim3(128), (size_t)0,
               (const float*)p_cat, 256, G, p_mean, p_rstd);
    launch_pdl(head_gemm1, dim3(G, 3), dim3(128), (size_t)0,
               (const float*)p_cat, (const float*)p_mean, (const float*)p_rstd,
               cW1, cb1, oW1, ob1, coW1, cob1, p_hd);
    launch_pdl(head_stats3, dim3(384), dim3(128), (size_t)0,
               (const float*)p_hd, G, p_mean, p_rstd);
    launch_pdl(head_gemm2_lsm, dim3(G, 3), dim3(128), (size_t)0,
               (const float*)p_hd, (const float*)p_mean, (const float*)p_rstd,
               cW2, cb2, oW2, ob2, coW2, cob2, out);

    cudaEventDestroy(evF1);
    cudaEventDestroy(evJ1);
    cudaEventDestroy(evF2);
    cudaEventDestroy(evJ2);
    cudaStreamDestroy(sA);
}

// round 17
// speedup vs baseline: 1.2258x; 1.0530x over previous
#include <cuda_runtime.h>
#include <math.h>

#define Nn 50000
#define Ee 400000
#define Hh 128
#define Gg 512
#define COUT 10

typedef unsigned long long u64;

static constexpr float EPSBN = 1e-5f;
static constexpr float BNB   = 1e-4f;

#define GDC_WAIT()   asm volatile("griddepcontrol.wait;" ::: "memory")
#define GDC_LAUNCH() asm volatile("griddepcontrol.launch_dependents;" ::: "memory")

// ---------------- scratch (static device allocations) ----------------
__device__ float g_h[Nn*Hh];
__device__ float g_t[Nn*Hh];
__device__ float g_t2b[Nn*Hh];
__device__ float g_stats[5*512];
__device__ float g_mean[512];
__device__ float g_rstd[512];
__device__ float g_disU[Nn];
__device__ float2 g_deg01[Nn];
__device__ float g_epro[Nn*4];
__device__ float g_t2[Nn*2];
__device__ float g_natt[Nn*2];
__device__ float g_eperm[Ee*2];
__device__ float g_bias2[256];
__device__ float g_cat[Gg*256];
__device__ float g_hd[3*Gg*128];
// CSR by destination
__device__ int g_cnt[Nn];
__device__ int g_incl[Nn];
__device__ int g_bsum[64];
__device__ int g_rowptr[Nn+1];
__device__ int g_cursor[Nn];
__device__ int g_csrc[Ee];
__device__ int g_pos[Ee];

// ---------------- small utility kernels ----------------
__global__ void init_kernel(float* disU, float2* deg01, int* cnt, int n) {
    int i = blockIdx.x*blockDim.x + threadIdx.x;
    if (i < n) { disU[i] = 1.f; deg01[i] = make_float2(1.f, 1.f); cnt[i] = 0; }
}

__global__ void deg_hist(const int* __restrict__ src, const int* __restrict__ dst,
                         float* degU, int* cnt, int E) {
    int i = blockIdx.x*blockDim.x + threadIdx.x;
    if (i < E) {
        atomicAdd(&degU[src[i]], 1.0f);
        atomicAdd(&cnt[dst[i]], 1);
    }
}

__global__ void rsqrt_arr(float* p, int n) {
    int i = blockIdx.x*blockDim.x + threadIdx.x;
    if (i < n) p[i] = rsqrtf(p[i]);
}

// ---------------- CSR build ----------------
__global__ void scan_block(const int* __restrict__ cnt, int* incl, int* bsum, int n) {
    __shared__ int sm[1024];
    int i = blockIdx.x*1024 + threadIdx.x;
    sm[threadIdx.x] = (i < n) ? cnt[i] : 0;
    __syncthreads();
    for (int off = 1; off < 1024; off <<= 1) {
        int t = (threadIdx.x >= off) ? sm[threadIdx.x - off] : 0;
        __syncthreads();
        sm[threadIdx.x] += t;
        __syncthreads();
    }
    if (i < n) incl[i] = sm[threadIdx.x];
    if (threadIdx.x == 1023) bsum[blockIdx.x] = sm[1023];
}

__global__ void scan_tops(int* bsum, int nb) {
    int lane = threadIdx.x;
    int v0 = (lane < nb) ? bsum[lane] : 0;
    int v1 = (32 + lane < nb) ? bsum[32 + lane] : 0;
    #pragma unroll
    for (int o = 1; o < 32; o <<= 1) {
        int t = __shfl_up_sync(0xffffffffu, v0, o);
        if (lane >= o) v0 += t;
    }
    int tot0 = __shfl_sync(0xffffffffu, v0, 31);
    #pragma unroll
    for (int o = 1; o < 32; o <<= 1) {
        int t = __shfl_up_sync(0xffffffffu, v1, o);
        if (lane >= o) v1 += t;
    }
    v1 += tot0;
    if (lane < nb) bsum[lane] = v0;
    if (32 + lane < nb) bsum[32 + lane] = v1;
}

__global__ void make_rowptr(const int* __restrict__ cnt, const int* __restrict__ incl,
                            const int* __restrict__ bsum,
                            int* rowptr, int* cursor, float* disU, int n, int E) {
    int i = blockIdx.x*blockDim.x + threadIdx.x;
    if (i < n) {
        int b = i >> 10;
        int ex = incl[i] - cnt[i] + ((b > 0) ? bsum[b-1] : 0);
        rowptr[i] = ex;
        cursor[i] = ex;
        disU[i] = rsqrtf(disU[i]);
    }
    if (i == 0) rowptr[n] = E;
}

__global__ void fill_csr(const int* __restrict__ src, const int* __restrict__ dst,
                         int* cursor, int* csrc, int* pos, int E) {
    int e = blockIdx.x*blockDim.x + threadIdx.x;
    if (e < E) {
        int p = atomicAdd(&cursor[dst[e]], 1);
        csrc[p] = src[e];
        pos[e] = p;
    }
}

// ---------------- BatchNorm stats (accumulate only; consumers finalize) ----------------
__global__ void colstats(const float* __restrict__ A, int n, float* sums) {
    GDC_WAIT();
    long total  = (long)n * 128;
    long stride = (long)gridDim.x * blockDim.x;
    long i0     = (long)blockIdx.x*blockDim.x + threadIdx.x;
    if (i0 < total) {
        int c = (int)(i0 % 128);
        float s0 = 0.f, s1 = 0.f;
        for (long i = i0; i < total; i += stride) {
            int r = (int)(i / 128);
            float v = A[(long)r*128 + c];
            s0 += v; s1 += v*v;
        }
        atomicAdd(&sums[c], s0);
        atomicAdd(&sums[128+c], s1);
    }
    GDC_LAUNCH();
}

__global__ void colstats2(const float* __restrict__ A, const float* __restrict__ natt,
                          int n, float* sums) {
    GDC_WAIT();
    long total  = (long)n * 128;
    long stride = (long)gridDim.x * blockDim.x;
    long i0     = (long)blockIdx.x*blockDim.x + threadIdx.x;
    if (i0 < total) {
        int c = (int)(i0 % 128);
        float s00=0.f, s01=0.f, s10=0.f, s11=0.f;
        for (long i = i0; i < total; i += stride) {
            int r = (int)(i / 128);
            float v = A[(long)r*128 + c];
            float v0 = v * natt[r*2+0];
            float v1 = v * natt[r*2+1];
            s00 += v0; s01 += v0*v0;
            s10 += v1; s11 += v1*v1;
        }
        atomicAdd(&sums[c], s00);
        atomicAdd(&sums[128+c], s01);
        atomicAdd(&sums[256+c], s10);
        atomicAdd(&sums[384+c], s11);
    }
    GDC_LAUNCH();
}

// merged finalize (both natt channels) + BN-folded bias rows
__global__ void finalize2bias(const float* __restrict__ sums, float inv_n,
                              float* __restrict__ mean, float* __restrict__ rstd,
                              const float* __restrict__ xcW, const float* __restrict__ xoW,
                              float* __restrict__ bias2) {
    __shared__ float coef[128];
    GDC_WAIT();
    int ch = blockIdx.x;
    int t = threadIdx.x;
    float s0 = sums[ch*256 + t], s1 = sums[ch*256 + 128 + t];
    float m = s0*inv_n;
    float var = s1*inv_n - m*m;
    float rs = rsqrtf(var + EPSBN);
    mean[ch*128 + t] = m;
    rstd[ch*128 + t] = rs;
    coef[t] = BNB - m*rs;
    __syncthreads();
    const float* W = ch ? xoW : xcW;
    float acc = 0.f;
    for (int k = 0; k < 128; k++) acc += coef[k]*W[k*128+t];
    bias2[ch*128 + t] = acc;
    GDC_LAUNCH();
}

__global__ void head_stats(const float* __restrict__ A, int lda, int n,
                           float* mean, float* rstd) {
    __shared__ float s0s[4], s1s[4];
    GDC_WAIT();
    int c = blockIdx.x;
    int lane = threadIdx.x & 31, warp = threadIdx.x >> 5;
    float s0 = 0.f, s1 = 0.f;
    for (int r = threadIdx.x; r < n; r += blockDim.x) {
        float v = A[r*lda + c];
        s0 += v; s1 += v*v;
    }
    #pragma unroll
    for (int o = 16; o; o >>= 1) {
        s0 += __shfl_xor_sync(0xffffffffu, s0, o);
        s1 += __shfl_xor_sync(0xffffffffu, s1, o);
    }
    if (lane == 0) { s0s[warp] = s0; s1s[warp] = s1; }
    __syncthreads();
    if (threadIdx.x == 0) {
        float t0 = 0.f, t1 = 0.f;
        for (int w = 0; w < 4; w++) { t0 += s0s[w]; t1 += s1s[w]; }
        float m = t0 / n;
        float var = t1 / n - m*m;
        mean[c] = m;
        rstd[c] = rsqrtf(var + EPSBN);
    }
    GDC_LAUNCH();
}

__global__ void head_stats3(const float* __restrict__ hd, int n,
                            float* mean, float* rstd) {
    __shared__ float s0s[4], s1s[4];
    GDC_WAIT();
    int cg = blockIdx.x;
    int head = cg >> 7, c = cg & 127;
    const float* A = hd + head*Gg*128;
    int lane = threadIdx.x & 31, warp = threadIdx.x >> 5;
    float s0 = 0.f, s1 = 0.f;
    for (int r = threadIdx.x; r < n; r += blockDim.x) {
        float v = A[r*128 + c];
        s0 += v; s1 += v*v;
    }
    #pragma unroll
    for (int o = 16; o; o >>= 1) {
        s0 += __shfl_xor_sync(0xffffffffu, s0, o);
        s1 += __shfl_xor_sync(0xffffffffu, s1, o);
    }
    if (lane == 0) { s0s[warp] = s0; s1s[warp] = s1; }
    __syncthreads();
    if (threadIdx.x == 0) {
        float t0 = 0.f, t1 = 0.f;
        for (int w = 0; w < 4; w++) { t0 += s0s[w]; t1 += s1s[w]; }
        float m = t0 / n;
        float var = t1 / n - m*m;
        mean[cg] = m;
        rstd[cg] = rsqrtf(var + EPSBN);
    }
    GDC_LAUNCH();
}

// ---------------- big GEMM (f32x2 FMA, BM=64, K-chunked, 3 CTAs/SM, PDL) ----------------
static constexpr int GEMM_SMEM = (64*128 + 64*128 + 256) * 4;

__global__ __launch_bounds__(256, 3) void gemm128(
    const float* __restrict__ A,
    const float* __restrict__ sums_in, float inv_n,
    const float* __restrict__ W,
    float* __restrict__ out,
    float* __restrict__ sums_out,
    const float* __restrict__ rowscale,
    int n, int act)
{
    extern __shared__ float sm[];
    float* As = sm;
    float* Ws = sm + 64*128;
    float* smean = sm + 2*64*128;
    float* srstd = smean + 128;
    int tid  = threadIdx.x;
    int row0 = blockIdx.x * 64;

    const float4* Wg = (const float4*)W;
    float4* Ws4 = (float4*)Ws;

    #pragma unroll 2
    for (int i = tid; i < 64*32; i += 256)
        Ws4[i] = Wg[(i >> 5)*32 + (i & 31)];

    GDC_WAIT();

    if (tid < 128) {
        float s0 = sums_in[tid], s1 = sums_in[128+tid];
        float m = s0*inv_n;
        float var = s1*inv_n - m*m;
        smean[tid] = m;
        srstd[tid] = rsqrtf(var + EPSBN);
    }
    __syncthreads();

    #pragma unroll 2
    for (int i = tid; i < 64*32; i += 256) {
        int r = i >> 5, cq = i & 31;
        int gr = row0 + r;
        float4 v = make_float4(0.f,0.f,0.f,0.f);
        if (gr < n) {
            v = ((const float4*)A)[gr*32 + cq];
            int c = cq*4;
            v.x = (v.x - smean[c+0])*srstd[c+0] + BNB;
            v.y = (v.y - smean[c+1])*srstd[c+1] + BNB;
            v.z = (v.z - smean[c+2])*srstd[c+2] + BNB;
            v.w = (v.w - smean[c+3])*srstd[c+3] + BNB;
        }
        ((float4*)As)[i] = v;
    }

    int tc = tid & 15, tr = tid >> 4;
    int r0 = tr*4;
    int c0 = tc*4, c1 = 64 + tc*4;

    u64 accp[4][4];
    #pragma unroll
    for (int i = 0; i < 4; i++)
        #pragma unroll
        for (int j = 0; j < 4; j++) accp[i][j] = 0ull;

    #pragma unroll
    for (int kc = 0; kc < 128; kc += 64) {
        if (kc > 0) {
            __syncthreads();
            #pragma unroll 2
            for (int i = tid; i < 64*32; i += 256)
                Ws4[i] = Wg[(kc + (i >> 5))*32 + (i & 31)];
        }
        __syncthreads();

        for (int k = 0; k < 64; k += 4) {
            float4 a4[4];
            #pragma unroll
            for (int i = 0; i < 4; i++)
                a4[i] = *(const float4*)&As[(r0+i)*128 + kc + k];
            #pragma unroll
            for (int kk = 0; kk < 4; kk++) {
                ulonglong2 w01 = *(const ulonglong2*)&Ws[(k+kk)*128 + c0];
                ulonglong2 w23 = *(const ulonglong2*)&Ws[(k+kk)*128 + c1];
                u64 wp0 = w01.x, wp1 = w01.y, wp2 = w23.x, wp3 = w23.y;
                #pragma unroll
                for (int i = 0; i < 4; i++) {
                    float a = ((const float*)&a4[i])[kk];
                    unsigned int ai = __float_as_uint(a);
                    u64 ap;
                    asm("mov.b64 %0, {%1, %1};" : "=l"(ap) : "r"(ai));
                    asm("fma.rn.f32x2 %0, %1, %2, %0;" : "+l"(accp[i][0]) : "l"(ap), "l"(wp0));
                    asm("fma.rn.f32x2 %0, %1, %2, %0;" : "+l"(accp[i][1]) : "l"(ap), "l"(wp1));
                    asm("fma.rn.f32x2 %0, %1, %2, %0;" : "+l"(accp[i][2]) : "l"(ap), "l"(wp2));
                    asm("fma.rn.f32x2 %0, %1, %2, %0;" : "+l"(accp[i][3]) : "l"(ap), "l"(wp3));
                }
            }
        }
    }

    float t0[8], t1[8];
    #pragma unroll
    for (int j = 0; j < 8; j++) { t0[j] = 0.f; t1[j] = 0.f; }

    float4* O4 = (float4*)out;
    #pragma unroll
    for (int i = 0; i < 4; i++) {
        int gr = row0 + r0 + i;
        if (gr < n) {
            float o[8];
            #pragma unroll
            for (int j = 0; j < 4; j++) {
                unsigned int lo, hi;
                asm("mov.b64 {%0, %1}, %2;" : "=r"(lo), "=r"(hi) : "l"(accp[i][j]));
                o[2*j]   = __uint_as_float(lo);
                o[2*j+1] = __uint_as_float(hi);
            }
            if (act == 1) {
                #pragma unroll
                for (int j = 0; j < 8; j++) o[j] = fmaxf(o[j], 0.f);
            }
            if (rowscale) {
                float rs = rowscale[gr];
                #pragma unroll
                for (int j = 0; j < 8; j++) o[j] *= rs;
            }
            if (sums_out) {
                #pragma unroll
                for (int j = 0; j < 8; j++) { t0[j] += o[j]; t1[j] += o[j]*o[j]; }
            }
            O4[gr*32 + tc]      = make_float4(o[0], o[1], o[2], o[3]);
            O4[gr*32 + 16 + tc] = make_float4(o[4], o[5], o[6], o[7]);
        }
    }

    if (sums_out) {
        __syncthreads();
        float* ss = sm;
        ss[tid] = 0.f;
        __syncthreads();
        #pragma unroll
        for (int j = 0; j < 4; j++) {
            atomicAdd(&ss[c0+j],     t0[j]);   atomicAdd(&ss[128+c0+j], t1[j]);
            atomicAdd(&ss[c1+j],     t0[4+j]); atomicAdd(&ss[128+c1+j], t1[4+j]);
        }
        __syncthreads();
        atomicAdd(&sums_out[tid], ss[tid]);
    }
    GDC_LAUNCH();
}

// ---------------- merged XC/XO GEMM (K-chunked, rows pre-scaled by deg01) ----------------
__global__ __launch_bounds__(256, 3) void gemm256(
    const float* __restrict__ h,
    const float* __restrict__ natt,
    const float* __restrict__ rstd2,
    const float* __restrict__ xcW, const float* __restrict__ xoW,
    const float* __restrict__ bias2,
    const float2* __restrict__ deg01,
    float* __restrict__ outc, float* __restrict__ outo, int n)
{
    extern __shared__ float sm[];
    float* As = sm;
    float* Ws = sm + 64*128;
    int tid  = threadIdx.x;
    int row0 = blockIdx.x * 64;

    GDC_WAIT();

    #pragma unroll 2
    for (int i = tid; i < 64*32; i += 256) {
        int r = i >> 5, cq = i & 31;
        int gr = row0 + r;
        float4 v = (gr < n) ? ((const float4*)h)[gr*32 + cq]
                            : make_float4(0.f,0.f,0.f,0.f);
        ((float4*)As)[i] = v;
    }

    int tc = tid & 15, tr = tid >> 4;
    int r0 = tr*4;
    int c0 = tc*4, c1 = 64 + tc*4;

    #pragma unroll
    for (int half = 0; half < 2; half++) {
        const float* W  = half ? xoW : xcW;
        const float* rs = rstd2 + half*128;
        const float* bs = bias2 + half*128;
        float* out = half ? outo : outc;

        float nv[4], dsc[4];
        #pragma unroll
        for (int i = 0; i < 4; i++) {
            int gr = row0 + r0 + i;
            nv[i] = (gr < n) ? natt[gr*2 + half] : 0.f;
            float2 d = (gr < n) ? deg01[gr] : make_float2(0.f, 0.f);
            dsc[i] = half ? d.y : d.x;
        }

        u64 accp[4][4];
        #pragma unroll
        for (int i = 0; i < 4; i++)
            #pragma unroll
            for (int j = 0; j < 4; j++) accp[i][j] = 0ull;

        #pragma unroll
        for (int kc = 0; kc < 128; kc += 64) {
            __syncthreads();
            #pragma unroll 2
            for (int i = tid; i < 64*32; i += 256) {
                int r = kc + (i >> 5);
                float4 w = ((const float4*)W)[r*32 + (i & 31)];
                float sc = rs[r];
                w.x *= sc; w.y *= sc; w.z *= sc; w.w *= sc;
                ((float4*)Ws)[i] = w;
            }
            __syncthreads();

            for (int k = 0; k < 64; k += 4) {
                float4 a4[4];
                #pragma unroll
                for (int i = 0; i < 4; i++)
                    a4[i] = *(const float4*)&As[(r0+i)*128 + kc + k];
                #pragma unroll
                for (int kk = 0; kk < 4; kk++) {
                    ulonglong2 w01 = *(const ulonglong2*)&Ws[(k+kk)*128 + c0];
                    ulonglong2 w23 = *(const ulonglong2*)&Ws[(k+kk)*128 + c1];
                    u64 wp0 = w01.x, wp1 = w01.y, wp2 = w23.x, wp3 = w23.y;
                    #pragma unroll
                    for (int i = 0; i < 4; i++) {
                        float a = ((const float*)&a4[i])[kk] * nv[i];
                        unsigned int ai = __float_as_uint(a);
                        u64 ap;
                        asm("mov.b64 %0, {%1, %1};" : "=l"(ap) : "r"(ai));
                        asm("fma.rn.f32x2 %0, %1, %2, %0;" : "+l"(accp[i][0]) : "l"(ap), "l"(wp0));
                        asm("fma.rn.f32x2 %0, %1, %2, %0;" : "+l"(accp[i][1]) : "l"(ap), "l"(wp1));
                        asm("fma.rn.f32x2 %0, %1, %2, %0;" : "+l"(accp[i][2]) : "l"(ap), "l"(wp2));
                        asm("fma.rn.f32x2 %0, %1, %2, %0;" : "+l"(accp[i][3]) : "l"(ap), "l"(wp3));
                    }
                }
            }
        }

        float4 b0 = *(const float4*)&bs[c0];
        float4 b1 = *(const float4*)&bs[c1];
        float4* O4 = (float4*)out;
        #pragma unroll
        for (int i = 0; i < 4; i++) {
            int gr = row0 + r0 + i;
            if (gr < n) {
                float o[8];
                #pragma unroll
                for (int j = 0; j < 4; j++) {
                    unsigned int lo, hi;
                    asm("mov.b64 {%0, %1}, %2;" : "=r"(lo), "=r"(hi) : "l"(accp[i][j]));
                    o[2*j]   = __uint_as_float(lo);
                    o[2*j+1] = __uint_as_float(hi);
                }
                float d = dsc[i];
                O4[gr*32 + tc]      = make_float4((o[0]+b0.x)*d, (o[1]+b0.y)*d,
                                                  (o[2]+b0.z)*d, (o[3]+b0.w)*d);
                O4[gr*32 + 16 + tc] = make_float4((o[4]+b1.x)*d, (o[5]+b1.y)*d,
                                                  (o[6]+b1.z)*d, (o[7]+b1.w)*d);
            }
        }
    }
    GDC_LAUNCH();
}

// ---------------- CSR gather conv (rows pre-scaled: pure row-add loop) ----------------
__global__ __launch_bounds__(256) void gather128(
    const float* __restrict__ t,
    const int* __restrict__ rowptr, const int* __restrict__ csrc,
    const float* __restrict__ dis,
    const float* __restrict__ bias,
    float* __restrict__ out, float* __restrict__ sums,
    const float* __restrict__ eWg, const float* __restrict__ naWg,
    float* __restrict__ epro, float* __restrict__ t2,
    int n, int act)
{
    __shared__ float sEW[512];
    __shared__ float sNA[256];
    int lane = threadIdx.x & 31;
    if (eWg) {
        for (int i = threadIdx.x; i < 512; i += 256) sEW[i] = eWg[i];
        for (int i = threadIdx.x; i < 256; i += 256) sNA[i] = naWg[i];
    }
    float4 bb = bias ? ((const float4*)bias)[lane] : make_float4(0.f,0.f,0.f,0.f);

    GDC_WAIT();
    if (eWg) __syncthreads();

    int w0 = (blockIdx.x*blockDim.x + threadIdx.x) >> 5;
    int nw = (gridDim.x*blockDim.x) >> 5;
    float ls0[4] = {0.f,0.f,0.f,0.f}, ls1[4] = {0.f,0.f,0.f,0.f};
    const float4* t4 = (const float4*)t;

    for (int v = w0; v < n; v += nw) {
        float dv = dis[v];
        float4 acc = t4[v*32 + lane];
        int p = rowptr[v], en = rowptr[v+1];
        for (; p + 4 <= en; p += 4) {
            int s0 = __ldg(&csrc[p+0]);
            int s1 = __ldg(&csrc[p+1]);
            int s2 = __ldg(&csrc[p+2]);
            int s3 = __ldg(&csrc[p+3]);
            float4 x0 = t4[s0*32 + lane];
            float4 x1 = t4[s1*32 + lane];
            float4 x2 = t4[s2*32 + lane];
            float4 x3 = t4[s3*32 + lane];
            acc.x += x0.x + x1.x + x2.x + x3.x;
            acc.y += x0.y + x1.y + x2.y + x3.y;
            acc.z += x0.z + x1.z + x2.z + x3.z;
            acc.w += x0.w + x1.w + x2.w + x3.w;
        }
        for (; p < en; p++) {
            int s = __ldg(&csrc[p]);
            float4 x = t4[s*32 + lane];
            acc.x += x.x; acc.y += x.y; acc.z += x.z; acc.w += x.w;
        }
        acc.x = acc.x*dv + bb.x; acc.y = acc.y*dv + bb.y;
        acc.z = acc.z*dv + bb.z; acc.w = acc.w*dv + bb.w;
        if (act == 1) {
            acc.x = fmaxf(acc.x, 0.f); acc.y = fmaxf(acc.y, 0.f);
            acc.z = fmaxf(acc.z, 0.f); acc.w = fmaxf(acc.w, 0.f);
        }
        if (sums) {
            ls0[0]+=acc.x; ls1[0]+=acc.x*acc.x;
            ls0[1]+=acc.y; ls1[1]+=acc.y*acc.y;
            ls0[2]+=acc.z; ls1[2]+=acc.z*acc.z;
            ls0[3]+=acc.w; ls1[3]+=acc.w*acc.w;
        }
        ((float4*)out)[v*32 + lane] = acc;

        if (eWg) {
            float hx[4] = {acc.x, acc.y, acc.z, acc.w};
            float p0=0,p1=0,q0=0,q1=0,u0=0,u1=0;
            #pragma unroll
            for (int i = 0; i < 4; i++) {
                int k = lane*4 + i; float xv = hx[i];
                p0 += xv*sEW[k*2+0];        p1 += xv*sEW[k*2+1];
                q0 += xv*sEW[(128+k)*2+0];  q1 += xv*sEW[(128+k)*2+1];
                u0 += xv*sNA[k*2+0];        u1 += xv*sNA[k*2+1];
            }
            #pragma unroll
            for (int o = 16; o; o >>= 1) {
                p0 += __shfl_xor_sync(0xffffffffu, p0, o);
                p1 += __shfl_xor_sync(0xffffffffu, p1, o);
                q0 += __shfl_xor_sync(0xffffffffu, q0, o);
                q1 += __shfl_xor_sync(0xffffffffu, q1, o);
                u0 += __shfl_xor_sync(0xffffffffu, u0, o);
                u1 += __shfl_xor_sync(0xffffffffu, u1, o);
            }
            if (lane == 0) {
                epro[v*4+0]=p0; epro[v*4+1]=p1; epro[v*4+2]=q0; epro[v*4+3]=q1;
                t2[v*2+0]=u0*dv; t2[v*2+1]=u1*dv;
            }
        }
    }

    if (sums) {
        __shared__ float ss[256];
        ss[threadIdx.x] = 0.f;
        __syncthreads();
        #pragma unroll
        for (int j = 0; j < 4; j++) {
            atomicAdd(&ss[lane*4+j],     ls0[j]);
            atomicAdd(&ss[128+lane*4+j], ls1[j]);
        }
        __syncthreads();
        atomicAdd(&sums[threadIdx.x], ss[threadIdx.x]);
    }
    GDC_LAUNCH();
}

// fused XC+XO gather + conv-bias + ELU + pool (rows pre-scaled by deg01)
__global__ __launch_bounds__(256) void gather2(
    const float* __restrict__ tc_, const float* __restrict__ to_,
    const int* __restrict__ rowptr, const int* __restrict__ csrc,
    const float2* __restrict__ dis01,
    const float* __restrict__ eperm,
    const float* __restrict__ xcb, const float* __restrict__ xob,
    const int* __restrict__ batch,
    float* __restrict__ cat, int n)
{
    int lane = threadIdx.x & 31;
    float4 bc = ((const float4*)xcb)[lane];
    float4 bo = ((const float4*)xob)[lane];
    GDC_WAIT();

    int w0 = (blockIdx.x*blockDim.x + threadIdx.x) >> 5;
    int nw = (gridDim.x*blockDim.x) >> 5;
    const float4* tc4 = (const float4*)tc_;
    const float4* to4 = (const float4*)to_;

    for (int v = w0; v < n; v += nw) {
        float2 dv = dis01[v];
        float4 ac = tc4[v*32 + lane];
        float4 ao = to4[v*32 + lane];
        int p = rowptr[v], en = rowptr[v+1];
        for (; p + 2 <= en; p += 2) {
            int s0 = __ldg(&csrc[p+0]);
            int s1 = __ldg(&csrc[p+1]);
            float2 ea0 = __ldg((const float2*)&eperm[(p+0)*2]);
            float2 ea1 = __ldg((const float2*)&eperm[(p+1)*2]);
            float4 xc0 = tc4[s0*32 + lane];
            float4 xo0 = to4[s0*32 + lane];
            float4 xc1 = tc4[s1*32 + lane];
            float4 xo1 = to4[s1*32 + lane];
            ac.x += ea0.x*xc0.x + ea1.x*xc1.x; ac.y += ea0.x*xc0.y + ea1.x*xc1.y;
            ac.z += ea0.x*xc0.z + ea1.x*xc1.z; ac.w += ea0.x*xc0.w + ea1.x*xc1.w;
            ao.x += ea0.y*xo0.x + ea1.y*xo1.x; ao.y += ea0.y*xo0.y + ea1.y*xo1.y;
            ao.z += ea0.y*xo0.z + ea1.y*xo1.z; ao.w += ea0.y*xo0.w + ea1.y*xo1.w;
        }
        for (; p < en; p++) {
            int s = __ldg(&csrc[p]);
            float2 ea = __ldg((const float2*)&eperm[p*2]);
            float4 xc = tc4[s*32 + lane];
            float4 xo = to4[s*32 + lane];
            ac.x += ea.x*xc.x; ac.y += ea.x*xc.y; ac.z += ea.x*xc.z; ac.w += ea.x*xc.w;
            ao.x += ea.y*xo.x; ao.y += ea.y*xo.y; ao.z += ea.y*xo.z; ao.w += ea.y*xo.w;
        }
        float zc[4] = {ac.x*dv.x+bc.x, ac.y*dv.x+bc.y, ac.z*dv.x+bc.z, ac.w*dv.x+bc.w};
        float zo[4] = {ao.x*dv.y+bo.x, ao.y*dv.y+bo.y, ao.z*dv.y+bo.z, ao.w*dv.y+bo.w};
        #pragma unroll
        for (int j = 0; j < 4; j++) {
            zc[j] = (zc[j] > 0.f) ? zc[j] : expm1f(zc[j]);
            zo[j] = (zo[j] > 0.f) ? zo[j] : expm1f(zo[j]);
        }
        int g = __ldg(&batch[v]);
        float* pc = cat + g*256 + lane*4;
        float* po = pc + 128;
        asm volatile("red.global.add.v4.f32 [%0], {%1, %2, %3, %4};"
                     :: "l"(pc), "f"(zc[0]), "f"(zc[1]), "f"(zc[2]), "f"(zc[3]) : "memory");
        asm volatile("red.global.add.v4.f32 [%0], {%1, %2, %3, %4};"
                     :: "l"(po), "f"(zo[0]), "f"(zo[1]), "f"(zo[2]), "f"(zo[3]) : "memory");
    }
    GDC_LAUNCH();
}

// ---------------- attention ----------------
__global__ void edge_att_kernel(const int* __restrict__ src, const int* __restrict__ dst,
                                const int* __restrict__ pos,
                                const float* __restrict__ epro, const float* __restrict__ eb,
                                float* __restrict__ eperm, float2* __restrict__ deg01, int E) {
    int e = blockIdx.x*blockDim.x + threadIdx.x;
    if (e >= E) return;
    int s = src[e], d = dst[e];
    float2 ps = *(const float2*)&epro[s*4];
    float2 qd = *(const float2*)&epro[d*4+2];
    float l0 = ps.x + qd.x + eb[0];
    float l1 = ps.y + qd.y + eb[1];
    float m = fmaxf(l0, l1);
    float e0 = expf(l0 - m), e1 = expf(l1 - m);
    float inv = 1.f/(e0+e1);
    float a0 = e0*inv, a1 = e1*inv;
    int p = pos[e];
    *(float2*)&eperm[p*2] = make_float2(a0, a1);
    asm volatile("red.global.add.v2.f32 [%0], {%1, %2};"
                 :: "l"(&deg01[s]), "f"(a0), "f"(a1) : "memory");
}

// t2 rows pre-scaled by disU; logits = dv*(t2'[v] + sum t2'[s]) + nab
__global__ void natt_gather(const float* __restrict__ t2,
                            const int* __restrict__ rowptr, const int* __restrict__ csrc,
                            const float* __restrict__ disU,
                            const float* __restrict__ nab,
                            float* __restrict__ natt, int n) {
    GDC_WAIT();
    int v = blockIdx.x*blockDim.x + threadIdx.x;
    if (v < n) {
        float dv = disU[v];
        float2 selfv = __ldg((const float2*)&t2[v*2]);
        float a0 = selfv.x, a1 = selfv.y;
        int p = rowptr[v], en = rowptr[v+1];
        for (; p + 4 <= en; p += 4) {
            int s0 = __ldg(&csrc[p+0]);
            int s1 = __ldg(&csrc[p+1]);
            int s2 = __ldg(&csrc[p+2]);
            int s3 = __ldg(&csrc[p+3]);
            float2 x0 = __ldg((const float2*)&t2[s0*2]);
            float2 x1 = __ldg((const float2*)&t2[s1*2]);
            float2 x2 = __ldg((const float2*)&t2[s2*2]);
            float2 x3 = __ldg((const float2*)&t2[s3*2]);
            a0 += x0.x + x1.x + x2.x + x3.x;
            a1 += x0.y + x1.y + x2.y + x3.y;
        }
        for (; p < en; p++) {
            int s = __ldg(&csrc[p]);
            float2 ts = __ldg((const float2*)&t2[s*2]);
            a0 += ts.x;
            a1 += ts.y;
        }
        a0 = a0*dv + nab[0];
        a1 = a1*dv + nab[1];
        float m = fmaxf(a0, a1);
        float e0 = expf(a0 - m), e1 = expf(a1 - m);
        float inv = 1.f/(e0+e1);
        natt[v*2+0] = e0*inv; natt[v*2+1] = e1*inv;
    }
    GDC_LAUNCH();
}

// ---------------- fused heads ----------------
__global__ void head_gemm1(const float* __restrict__ cat,
                           const float* __restrict__ mean, const float* __restrict__ rstd,
                           const float* __restrict__ cW1, const float* __restrict__ cb1,
                           const float* __restrict__ oW1, const float* __restrict__ ob1,
                           const float* __restrict__ coW1, const float* __restrict__ cob1,
                           float* __restrict__ hd) {
    __shared__ float a[256];
    GDC_WAIT();
    int r = blockIdx.x, head = blockIdx.y;
    for (int k = threadIdx.x; k < 256; k += 128)
        a[k] = (cat[r*256 + k] - mean[k]) * rstd[k] + BNB;
    __syncthreads();
    const float* W; const float* b; int K, koff, act;
    if (head == 0)      { W = cW1;  b = cb1;  K = 128; koff = 0;   act = 1; }
    else if (head == 1) { W = oW1;  b = ob1;  K = 128; koff = 128; act = 1; }
    else                { W = coW1; b = cob1; K = 256; koff = 0;   act = 2; }
    int c = threadIdx.x;
    float acc = b[c];
    for (int k = 0; k < K; k++) acc += a[koff + k] * W[k*128 + c];
    if (act == 1) acc = fmaxf(acc, 0.f);
    else {
        acc = (acc > 0.f) ? acc : expm1f(acc);
        acc = (acc > 0.f) ? acc : expm1f(acc);
    }
    hd[(head*Gg + r)*128 + c] = acc;
    GDC_LAUNCH();
}

__global__ void head_gemm2_lsm(const float* __restrict__ hd,
                               const float* __restrict__ mean, const float* __restrict__ rstd,
                               const float* __restrict__ cW2, const float* __restrict__ cb2,
                               const float* __restrict__ oW2, const float* __restrict__ ob2,
                               const float* __restrict__ coW2, const float* __restrict__ cob2,
                               float* __restrict__ out) {
    __shared__ float a[128];
    __shared__ float lg[COUT];
    GDC_WAIT();
    int r = blockIdx.x, head = blockIdx.y;
    int k = threadIdx.x;
    a[k] = (hd[(head*Gg + r)*128 + k] - mean[head*128 + k]) * rstd[head*128 + k] + BNB;
    __syncthreads();
    const float* W = (head == 0) ? cW2 : (head == 1) ? oW2 : coW2;
    const float* b = (head == 0) ? cb2 : (head == 1) ? ob2 : cob2;
    if (k < COUT) {
        float acc = b[k];
        for (int kk = 0; kk < 128; kk++) acc += a[kk] * W[kk*COUT + k];
        lg[k] = acc;
    }
    __syncthreads();
    if (k < COUT) {
        float m = -1e30f;
        #pragma unroll
        for (int i = 0; i < COUT; i++) m = fmaxf(m, lg[i]);
        float s = 0.f;
        #pragma unroll
        for (int i = 0; i < COUT; i++) s += expf(lg[i] - m);
        out[head*Gg*COUT + r*COUT + k] = lg[k] - m - logf(s);
    }
}

// ---------------- PDL launch helper ----------------
template <typename F, typename... Args>
static inline void launch_pdl(F kern, dim3 grid, dim3 block, size_t shm, Args... args) {
    cudaLaunchConfig_t cfg = {};
    cfg.gridDim = grid; cfg.blockDim = block;
    cfg.dynamicSmemBytes = shm; cfg.stream = 0;
    cudaLaunchAttribute at[1];
    at[0].id = cudaLaunchAttributeProgrammaticStreamSerialization;
    at[0].val.programmaticStreamSerializationAllowed = 1;
    cfg.attrs = at; cfg.numAttrs = 1;
    cudaLaunchKernelEx(&cfg, kern, args...);
}

// ---------------- host orchestration ----------------
extern "C" void kernel_launch(void* const* d_in, const int* in_sizes, int n_in,
                              void* d_out, int out_size) {
    const float* x      = (const float*)d_in[0];
    const float* W_feat = (const float*)d_in[1];
    const float* conv_Ws= (const float*)d_in[2];
    const float* conv_bs= (const float*)d_in[3];
    const float* eW     = (const float*)d_in[4];
    const float* eb     = (const float*)d_in[5];
    const float* naW    = (const float*)d_in[6];
    const float* nab    = (const float*)d_in[7];
    const float* xcW    = (const float*)d_in[8];
    const float* xcb    = (const float*)d_in[9];
    const float* xoW    = (const float*)d_in[10];
    const float* xob    = (const float*)d_in[11];
    const float* cW1    = (const float*)d_in[12];
    const float* cb1    = (const float*)d_in[13];
    const float* cW2    = (const float*)d_in[14];
    const float* cb2    = (const float*)d_in[15];
    const float* oW1    = (const float*)d_in[16];
    const float* ob1    = (const float*)d_in[17];
    const float* oW2    = (const float*)d_in[18];
    const float* ob2    = (const float*)d_in[19];
    const float* coW1   = (const float*)d_in[20];
    const float* cob1   = (const float*)d_in[21];
    const float* coW2   = (const float*)d_in[22];
    const float* cob2   = (const float*)d_in[23];
    const int* esrc     = (const int*)d_in[24];
    const int* edst     = (const int*)d_in[25];
    const int* batch    = (const int*)d_in[26];
    float* out = (float*)d_out;

    float *p_h,*p_t,*p_t2b,*p_stats,*p_mean,*p_rstd,*p_disU;
    float *p_epro,*p_t2,*p_natt,*p_eperm,*p_bias2,*p_cat,*p_hd;
    float2* p_deg01;
    int *p_cnt,*p_incl,*p_bsum,*p_rowptr,*p_cursor,*p_csrc,*p_pos;
    cudaGetSymbolAddress((void**)&p_h, g_h);
    cudaGetSymbolAddress((void**)&p_t, g_t);
    cudaGetSymbolAddress((void**)&p_t2b, g_t2b);
    cudaGetSymbolAddress((void**)&p_stats, g_stats);
    cudaGetSymbolAddress((void**)&p_mean, g_mean);
    cudaGetSymbolAddress((void**)&p_rstd, g_rstd);
    cudaGetSymbolAddress((void**)&p_disU, g_disU);
    cudaGetSymbolAddress((void**)&p_deg01, g_deg01);
    cudaGetSymbolAddress((void**)&p_epro, g_epro);
    cudaGetSymbolAddress((void**)&p_t2, g_t2);
    cudaGetSymbolAddress((void**)&p_natt, g_natt);
    cudaGetSymbolAddress((void**)&p_eperm, g_eperm);
    cudaGetSymbolAddress((void**)&p_bias2, g_bias2);
    cudaGetSymbolAddress((void**)&p_cat, g_cat);
    cudaGetSymbolAddress((void**)&p_hd, g_hd);
    cudaGetSymbolAddress((void**)&p_cnt, g_cnt);
    cudaGetSymbolAddress((void**)&p_incl, g_incl);
    cudaGetSymbolAddress((void**)&p_bsum, g_bsum);
    cudaGetSymbolAddress((void**)&p_rowptr, g_rowptr);
    cudaGetSymbolAddress((void**)&p_cursor, g_cursor);
    cudaGetSymbolAddress((void**)&p_csrc, g_csrc);
    cudaGetSymbolAddress((void**)&p_pos, g_pos);

    cudaFuncSetAttribute(gemm128, cudaFuncAttributeMaxDynamicSharedMemorySize, GEMM_SMEM);
    cudaFuncSetAttribute(gemm256, cudaFuncAttributeMaxDynamicSharedMemorySize, GEMM_SMEM);

    const int N = Nn, E = Ee, G = Gg;
    const int NB = (N + 63) / 64;
    const int NT = (N + 255) / 256;
    const int ET = (E + 255) / 256;
    const int GB = 592;                 // 4 blocks/SM x 148: single resident wave
    const int NSCAN = (N + 1023) / 1024;
    const float invN = 1.f/N;

    float* stX  = p_stats + 0*512;
    float* stH0 = p_stats + 1*512;
    float* stH1 = p_stats + 2*512;
    float* stH2 = p_stats + 3*512;
    float* stNA = p_stats + 4*512;

    cudaStream_t sA;
    cudaStreamCreateWithFlags(&sA, cudaStreamNonBlocking);
    cudaEvent_t evF1, evJ1, evF2, evJ2;
    cudaEventCreateWithFlags(&evF1, cudaEventDisableTiming);
    cudaEventCreateWithFlags(&evJ1, cudaEventDisableTiming);
    cudaEventCreateWithFlags(&evF2, cudaEventDisableTiming);
    cudaEventCreateWithFlags(&evJ2, cudaEventDisableTiming);

    cudaMemsetAsync(p_stats, 0, 5*512*sizeof(float));

    // ==== FORK 1: CSR build on sA ====
    cudaEventRecord(evF1, 0);
    cudaStreamWaitEvent(sA, evF1, 0);
    init_kernel<<<NT,256,0,sA>>>(p_disU, p_deg01, p_cnt, N);
    deg_hist<<<ET,256,0,sA>>>(esrc, edst, p_disU, p_cnt, E);
    scan_block<<<NSCAN,1024,0,sA>>>(p_cnt, p_incl, p_bsum, N);
    scan_tops<<<1,32,0,sA>>>(p_bsum, NSCAN);
    make_rowptr<<<NT,256,0,sA>>>(p_cnt, p_incl, p_bsum, p_rowptr, p_cursor, p_disU, N, E);
    fill_csr<<<ET,256,0,sA>>>(esrc, edst, p_cursor, p_csrc, p_pos, E);
    cudaEventRecord(evJ1, sA);

    // main chain: stats(x) -> gemm0 (PDL pair)
    colstats<<<512,256>>>(x, N, stX);
    launch_pdl(gemm128, dim3(NB), dim3(256), (size_t)GEMM_SMEM,
               x, (const float*)stX, invN, W_feat, p_h, stH0,
               (const float*)nullptr, N, 1);

    // JOIN 1 — PDL launch (event edge preserved; same-stream edge relaxed)
    cudaStreamWaitEvent(0, evJ1, 0);
    launch_pdl(gemm128, dim3(NB), dim3(256), (size_t)GEMM_SMEM,
               (const float*)p_h, (const float*)stH0, invN, conv_Ws, p_t,
               (float*)nullptr, (const float*)p_disU, N, 0);

    // ---- GCN layers (PDL chain) ----
    launch_pdl(gather128, dim3(GB), dim3(256), (size_t)0,
               (const float*)p_t, (const int*)p_rowptr, (const int*)p_csrc,
               (const float*)p_disU, conv_bs, p_h, stH1,
               (const float*)nullptr, (const float*)nullptr,
               (float*)nullptr, (float*)nullptr, N, 1);
    launch_pdl(gemm128, dim3(NB), dim3(256), (size_t)GEMM_SMEM,
               (const float*)p_h, (const float*)stH1, invN, conv_Ws + 128*128,
               p_t, (float*)nullptr, (const float*)p_disU, N, 0);
    launch_pdl(gather128, dim3(GB), dim3(256), (size_t)0,
               (const float*)p_t, (const int*)p_rowptr, (const int*)p_csrc,
               (const float*)p_disU, conv_bs + 128, p_h, stH2,
               (const float*)nullptr, (const float*)nullptr,
               (float*)nullptr, (float*)nullptr, N, 1);
    launch_pdl(gemm128, dim3(NB), dim3(256), (size_t)GEMM_SMEM,
               (const float*)p_h, (const float*)stH2, invN, conv_Ws + 2*128*128,
               p_t, (float*)nullptr, (const float*)p_disU, N, 0);
    launch_pdl(gather128, dim3(GB), dim3(256), (size_t)0,
               (const float*)p_t, (const int*)p_rowptr, (const int*)p_csrc,
               (const float*)p_disU, conv_bs + 2*128, p_h, (float*)nullptr,
               eW, naW, p_epro, p_t2, N, 1);

    // ==== FORK 2: edge attention on sA ====
    cudaEventRecord(evF2, 0);
    cudaStreamWaitEvent(sA, evF2, 0);
    edge_att_kernel<<<ET,256,0,sA>>>(esrc, edst, p_pos, p_epro, eb, p_eperm, p_deg01, E);
    rsqrt_arr<<<(2*N+255)/256,256,0,sA>>>((float*)p_deg01, 2*N);
    cudaMemsetAsync(p_cat, 0, Gg*256*sizeof(float), sA);
    cudaEventRecord(evJ2, sA);

    // main: node attention + XC/XO stats
    natt_gather<<<NT,256>>>(p_t2, p_rowptr, p_csrc, p_disU, nab, p_natt, N);
    launch_pdl(colstats2, dim3(512), dim3(256), (size_t)0,
               (const float*)p_h, (const float*)p_natt, N, stNA);
    launch_pdl(finalize2bias, dim3(2), dim3(128), (size_t)0,
               (const float*)stNA, invN, p_mean, p_rstd, xcW, xoW, p_bias2);

    // JOIN 2 — PDL launch (event edge preserved)
    cudaStreamWaitEvent(0, evJ2, 0);
    launch_pdl(gemm256, dim3(NB), dim3(256), (size_t)GEMM_SMEM,
               (const float*)p_h, (const float*)p_natt, (const float*)p_rstd,
               xcW, xoW, (const float*)p_bias2, (const float2*)p_deg01,
               p_t, p_t2b, N);
    launch_pdl(gather2, dim3(GB), dim3(256), (size_t)0,
               (const float*)p_t, (const float*)p_t2b, (const int*)p_rowptr,
               (const int*)p_csrc, (const float2*)p_deg01, (const float*)p_eperm,
               xcb, xob, batch, p_cat, N);

    // ---- heads (PDL chain) ----
    launch_pdl(head_stats, dim3(256), dim3(128), (size_t)0,
               (const float*)p_cat, 256, G, p_mean, p_rstd);
    launch_pdl(head_gemm1, dim3(G, 3), dim3(128), (size_t)0,
               (const float*)p_cat, (const float*)p_mean, (const float*)p_rstd,
               cW1, cb1, oW1, ob1, coW1, cob1, p_hd);
    launch_pdl(head_stats3, dim3(384), dim3(128), (size_t)0,
               (const float*)p_hd, G, p_mean, p_rstd);
    launch_pdl(head_gemm2_lsm, dim3(G, 3), dim3(128), (size_t)0,
               (const float*)p_hd, (const float*)p_mean, (const float*)p_rstd,
               cW2, cb2, oW2, ob2, coW2, cob2, out);

    cudaEventDestroy(evF1);
    cudaEventDestroy(evJ1);
    cudaEventDestroy(evF2);
    cudaEventDestroy(evJ2);
    cudaStreamDestroy(sA);
}